// round 1
// baseline (speedup 1.0000x reference)
#include <cuda_runtime.h>
#include <cuda_bf16.h>
#include <cstddef>

// Problem constants
#define DM      512          // d_model
#define DFF     2048         // d_ff
#define NB      8            // batch
#define SEQ     1024         // seq len
#define NHEAD   8
#define EHEAD   64
#define ROWS    (NB*SEQ)     // 8192
#define NLAYERS 4
#define LN_EPS  1e-5f

// ---------------- scratch (device globals; no allocations allowed) --------
__device__ float g_q [ROWS*DM];
__device__ float g_k [ROWS*DM];
__device__ float g_v [ROWS*DM];
__device__ float g_o [ROWS*DM];
__device__ float g_h [ROWS*DM];
__device__ float g_h1[ROWS*DM];
__device__ float g_h2[ROWS*DM];
__device__ float g_x [ROWS*DM];
__device__ float g_ff[ROWS*DFF];

// ---------------------------------------------------------------------------
// Tiled SGEMM:  C[M,N] = A[M,K] @ B[K,N] + bias  (+ReLU | +residual)
// BM=BN=128, BK=8, 256 threads, 8x8 micro-tile per thread.
// EPI: 0 = bias only, 1 = bias+relu, 2 = bias+residual add
// All dims here are multiples of tile sizes (8192, 512, 2048) -> no bounds.
// ---------------------------------------------------------------------------
template<int EPI>
__global__ __launch_bounds__(256, 2)
void gemm_kernel(const float* __restrict__ A, const float* __restrict__ B,
                 const float* __restrict__ bias, const float* __restrict__ res,
                 float* __restrict__ C, int M, int N, int K)
{
    constexpr int BM = 128, BN = 128, BK = 8;
    __shared__ float As[BK][BM];
    __shared__ float Bs[BK][BN];

    const int tid = threadIdx.x;
    const int bx = blockIdx.x;     // along N
    const int by = blockIdx.y;     // along M
    const int tx = tid & 15;       // 0..15
    const int ty = tid >> 4;       // 0..15

    // global->shared load mapping
    const int arow = tid >> 1;          // 0..127
    const int acol = (tid & 1) << 2;    // 0 or 4
    const int brow = tid >> 5;          // 0..7
    const int bcol = (tid & 31) << 2;   // 0..124

    const float* Ap = A + (size_t)(by*BM + arow)*K + acol;
    const float* Bp = B + (size_t)brow*N + (size_t)bx*BN + bcol;

    float acc[8][8];
#pragma unroll
    for (int i = 0; i < 8; i++)
#pragma unroll
        for (int j = 0; j < 8; j++) acc[i][j] = 0.f;

    for (int k0 = 0; k0 < K; k0 += BK) {
        float4 av = *(const float4*)(Ap + k0);
        float4 bv = *(const float4*)(Bp + (size_t)k0 * N);
        __syncthreads();
        As[acol+0][arow] = av.x;
        As[acol+1][arow] = av.y;
        As[acol+2][arow] = av.z;
        As[acol+3][arow] = av.w;
        *(float4*)&Bs[brow][bcol] = bv;
        __syncthreads();
#pragma unroll
        for (int kk = 0; kk < BK; kk++) {
            float ra[8], rb[8];
            *(float4*)&ra[0] = *(const float4*)&As[kk][ty*8];
            *(float4*)&ra[4] = *(const float4*)&As[kk][ty*8 + 4];
            *(float4*)&rb[0] = *(const float4*)&Bs[kk][tx*8];
            *(float4*)&rb[4] = *(const float4*)&Bs[kk][tx*8 + 4];
#pragma unroll
            for (int i = 0; i < 8; i++)
#pragma unroll
                for (int j = 0; j < 8; j++)
                    acc[i][j] += ra[i] * rb[j];
        }
    }

    const int crow = by*BM + ty*8;
    const int ccol = bx*BN + tx*8;
#pragma unroll
    for (int i = 0; i < 8; i++) {
        float* Cp = C + (size_t)(crow + i)*N + ccol;
        const float* Rp = (EPI == 2) ? (res + (size_t)(crow + i)*N + ccol) : nullptr;
#pragma unroll
        for (int j = 0; j < 8; j += 4) {
            float4 c = make_float4(acc[i][j], acc[i][j+1], acc[i][j+2], acc[i][j+3]);
            float4 b4 = *(const float4*)(bias + ccol + j);
            c.x += b4.x; c.y += b4.y; c.z += b4.z; c.w += b4.w;
            if (EPI == 1) {
                c.x = fmaxf(c.x, 0.f); c.y = fmaxf(c.y, 0.f);
                c.z = fmaxf(c.z, 0.f); c.w = fmaxf(c.w, 0.f);
            }
            if (EPI == 2) {
                float4 r4 = *(const float4*)(Rp + j);
                c.x += r4.x; c.y += r4.y; c.z += r4.z; c.w += r4.w;
            }
            *(float4*)(Cp + j) = c;
        }
    }
}

// ---------------------------------------------------------------------------
// Flash attention (fp32, online softmax). One thread per query row.
// Block = 128 query rows of one (batch, head). K/V tiles of 32 rows in smem.
// grid = (SEQ/128, NHEAD, NB), block = 128
// ---------------------------------------------------------------------------
__global__ __launch_bounds__(128)
void attn_kernel(const float* __restrict__ Q, const float* __restrict__ K,
                 const float* __restrict__ V, float* __restrict__ O)
{
    const int n = blockIdx.z, h = blockIdx.y;
    const int tid = threadIdx.x;
    const int row = blockIdx.x * 128 + tid;
    const float scale = 0.125f;   // 1/sqrt(64)

    __shared__ float Ks[32][64];
    __shared__ float Vs[32][64];

    float q[64];
    {
        const float4* qp = (const float4*)(Q + ((size_t)(n*SEQ + row))*DM + h*EHEAD);
#pragma unroll
        for (int i = 0; i < 16; i++) {
            float4 t = qp[i];
            q[4*i+0] = t.x; q[4*i+1] = t.y; q[4*i+2] = t.z; q[4*i+3] = t.w;
        }
    }

    float acc[64];
#pragma unroll
    for (int d = 0; d < 64; d++) acc[d] = 0.f;
    float m = -1e30f, lsum = 0.f;

    for (int kt = 0; kt < SEQ/32; kt++) {
        __syncthreads();
        // cooperative load of 32x64 K and V tiles (coalesced float4)
#pragma unroll
        for (int i = 0; i < 4; i++) {
            int idx = i*128 + tid;
            int r = idx >> 4;
            int c = (idx & 15) << 2;
            size_t gofs = ((size_t)(n*SEQ + kt*32 + r))*DM + h*EHEAD + c;
            *(float4*)&Ks[r][c] = *(const float4*)(K + gofs);
            *(float4*)&Vs[r][c] = *(const float4*)(V + gofs);
        }
        __syncthreads();

        float s[32];
#pragma unroll
        for (int j = 0; j < 32; j++) {
            const float4* kr = (const float4*)Ks[j];
            float sj = 0.f;
#pragma unroll
            for (int d4 = 0; d4 < 16; d4++) {
                float4 kv = kr[d4];
                sj += q[4*d4+0]*kv.x + q[4*d4+1]*kv.y
                    + q[4*d4+2]*kv.z + q[4*d4+3]*kv.w;
            }
            s[j] = sj * scale;
        }
        float tmax = m;
#pragma unroll
        for (int j = 0; j < 32; j++) tmax = fmaxf(tmax, s[j]);
        float corr = __expf(m - tmax);
        m = tmax;
        lsum *= corr;
#pragma unroll
        for (int d = 0; d < 64; d++) acc[d] *= corr;
#pragma unroll
        for (int j = 0; j < 32; j++) {
            float p = __expf(s[j] - m);
            lsum += p;
            const float4* vr = (const float4*)Vs[j];
#pragma unroll
            for (int d4 = 0; d4 < 16; d4++) {
                float4 vv = vr[d4];
                acc[4*d4+0] += p*vv.x; acc[4*d4+1] += p*vv.y;
                acc[4*d4+2] += p*vv.z; acc[4*d4+3] += p*vv.w;
            }
        }
    }

    const float inv = 1.f / lsum;
    float* op = O + ((size_t)(n*SEQ + row))*DM + h*EHEAD;
#pragma unroll
    for (int d = 0; d < 64; d += 4) {
        float4 o4 = make_float4(acc[d]*inv, acc[d+1]*inv, acc[d+2]*inv, acc[d+3]*inv);
        *(float4*)(op + d) = o4;
    }
}

// ---------------------------------------------------------------------------
// LayerNorm over last dim (512). One block (128 threads) per row.
// ---------------------------------------------------------------------------
__global__ __launch_bounds__(128)
void ln_kernel(const float* __restrict__ in, const float* __restrict__ gamma,
               const float* __restrict__ beta, float* __restrict__ out)
{
    const int row = blockIdx.x, tid = threadIdx.x;
    const float4 v = ((const float4*)(in + (size_t)row*DM))[tid];
    float s  = v.x + v.y + v.z + v.w;
    float sq = v.x*v.x + v.y*v.y + v.z*v.z + v.w*v.w;
#pragma unroll
    for (int o = 16; o; o >>= 1) {
        s  += __shfl_down_sync(0xffffffffu, s,  o);
        sq += __shfl_down_sync(0xffffffffu, sq, o);
    }
    __shared__ float ss[4], sqs[4];
    const int w = tid >> 5, lane = tid & 31;
    if (lane == 0) { ss[w] = s; sqs[w] = sq; }
    __syncthreads();
    s  = ss[0] + ss[1] + ss[2] + ss[3];
    sq = sqs[0] + sqs[1] + sqs[2] + sqs[3];

    const float mean = s * (1.f / DM);
    const float var  = sq * (1.f / DM) - mean * mean;
    const float inv  = rsqrtf(var + LN_EPS);

    const float4 g4 = ((const float4*)gamma)[tid];
    const float4 b4 = ((const float4*)beta)[tid];
    float4 o4;
    o4.x = (v.x - mean)*inv*g4.x + b4.x;
    o4.y = (v.y - mean)*inv*g4.y + b4.y;
    o4.z = (v.z - mean)*inv*g4.z + b4.z;
    o4.w = (v.w - mean)*inv*g4.w + b4.w;
    ((float4*)(out + (size_t)row*DM))[tid] = o4;
}

// ---------------------------------------------------------------------------
extern "C" void kernel_launch(void* const* d_in, const int* in_sizes, int n_in,
                              void* d_out, int out_size)
{
    const float* x   = (const float*)d_in[0];
    const float* Wq  = (const float*)d_in[1];
    const float* bq  = (const float*)d_in[2];
    const float* Wk  = (const float*)d_in[3];
    const float* bk  = (const float*)d_in[4];
    const float* Wv  = (const float*)d_in[5];
    const float* bv  = (const float*)d_in[6];
    const float* Wo  = (const float*)d_in[7];
    const float* bo  = (const float*)d_in[8];
    const float* W1  = (const float*)d_in[9];
    const float* b1  = (const float*)d_in[10];
    const float* W2  = (const float*)d_in[11];
    const float* b2  = (const float*)d_in[12];
    const float* g1  = (const float*)d_in[13];
    const float* be1 = (const float*)d_in[14];
    const float* g2  = (const float*)d_in[15];
    const float* be2 = (const float*)d_in[16];

    float *q, *k, *v, *o, *hb, *h1, *h2, *xb, *ff;
    cudaGetSymbolAddress((void**)&q,  g_q);
    cudaGetSymbolAddress((void**)&k,  g_k);
    cudaGetSymbolAddress((void**)&v,  g_v);
    cudaGetSymbolAddress((void**)&o,  g_o);
    cudaGetSymbolAddress((void**)&hb, g_h);
    cudaGetSymbolAddress((void**)&h1, g_h1);
    cudaGetSymbolAddress((void**)&h2, g_h2);
    cudaGetSymbolAddress((void**)&xb, g_x);
    cudaGetSymbolAddress((void**)&ff, g_ff);

    const dim3 gProj(DM / 128, ROWS / 128);    // (4, 64)
    const dim3 gFF1 (DFF / 128, ROWS / 128);   // (16, 64)
    const dim3 gAttn(SEQ / 128, NHEAD, NB);    // (8, 8, 8)

    const float* hin = x;
    for (int l = 0; l < NLAYERS; l++) {
        const float* wq = Wq + (size_t)l*DM*DM;
        const float* wk = Wk + (size_t)l*DM*DM;
        const float* wv = Wv + (size_t)l*DM*DM;
        const float* wo = Wo + (size_t)l*DM*DM;
        const float* w1 = W1 + (size_t)l*DM*DFF;
        const float* w2 = W2 + (size_t)l*DFF*DM;

        gemm_kernel<0><<<gProj, 256>>>(hin, wq, bq + l*DM, nullptr, q, ROWS, DM, DM);
        gemm_kernel<0><<<gProj, 256>>>(hin, wk, bk + l*DM, nullptr, k, ROWS, DM, DM);
        gemm_kernel<0><<<gProj, 256>>>(hin, wv, bv + l*DM, nullptr, v, ROWS, DM, DM);

        attn_kernel<<<gAttn, 128>>>(q, k, v, o);

        gemm_kernel<2><<<gProj, 256>>>(o, wo, bo + l*DM, hin, hb, ROWS, DM, DM);
        ln_kernel<<<ROWS, 128>>>(hb, g1 + l*DM, be1 + l*DM, h1);

        gemm_kernel<1><<<gFF1, 256>>>(h1, w1, b1 + l*DFF, nullptr, ff, ROWS, DFF, DM);
        gemm_kernel<2><<<gProj, 256>>>(ff, w2, b2 + l*DM, h1, h2, ROWS, DM, DFF);

        float* lnout = (l == NLAYERS - 1) ? (float*)d_out : xb;
        ln_kernel<<<ROWS, 128>>>(h2, g2 + l*DM, be2 + l*DM, lnout);
        hin = xb;
    }
}

// round 2
// speedup vs baseline: 1.6600x; 1.6600x over previous
#include <cuda_runtime.h>
#include <cuda_bf16.h>
#include <cstdint>
#include <cstddef>

// Problem constants
#define DM      512
#define DFF     2048
#define NB      8
#define SEQ     1024
#define NHEAD   8
#define EHEAD   64
#define ROWS    (NB*SEQ)     // 8192
#define NLAYERS 4
#define LN_EPS  1e-5f

// ---------------- scratch (device globals; no allocations allowed) --------
__device__ float g_q [ROWS*DM];
__device__ float g_k [ROWS*DM];
__device__ float g_v [ROWS*DM];
__device__ float g_o [ROWS*DM];
__device__ float g_h [ROWS*DM];
__device__ float g_h1[ROWS*DM];
__device__ float g_h2[ROWS*DM];
__device__ float g_x [ROWS*DM];
__device__ float g_ff[ROWS*DFF];

// ---------------------------------------------------------------------------
// TF32 tensor-core GEMM:  C[M,N] = A[M,K] @ B[K,N] + bias (+ReLU | +residual)
// BM=BN=128, BK=16, 256 threads = 8 warps in 4(m) x 2(n); warp tile 32x64.
// mma.sync.aligned.m16n8k8.row.col.f32.tf32.tf32.f32, operands via ldmatrix.
// Smem layout: As[m][k] pitch 20, Bs[n][k] pitch 20 (B transposed on store),
// so BOTH fragments load with plain (non-trans) ldmatrix.x4, conflict-free.
// ---------------------------------------------------------------------------
#define PA 20
#define BUFF (128*PA)

__device__ __forceinline__ float tf32r(float x) {
    uint32_t u;
    asm("cvt.rna.tf32.f32 %0, %1;" : "=r"(u) : "f"(x));
    return __uint_as_float(u);
}
__device__ __forceinline__ void ldsm4(uint32_t* r, uint32_t addr) {
    asm volatile("ldmatrix.sync.aligned.m8n8.x4.shared.b16 {%0,%1,%2,%3}, [%4];\n"
                 : "=r"(r[0]), "=r"(r[1]), "=r"(r[2]), "=r"(r[3]) : "r"(addr));
}
__device__ __forceinline__ void mma_tf32(float* d, const uint32_t* a,
                                         uint32_t b0, uint32_t b1) {
    asm volatile(
        "mma.sync.aligned.m16n8k8.row.col.f32.tf32.tf32.f32 "
        "{%0,%1,%2,%3},{%4,%5,%6,%7},{%8,%9},{%0,%1,%2,%3};\n"
        : "+f"(d[0]), "+f"(d[1]), "+f"(d[2]), "+f"(d[3])
        : "r"(a[0]), "r"(a[1]), "r"(a[2]), "r"(a[3]), "r"(b0), "r"(b1));
}

template<int EPI>   // 0: bias, 1: bias+relu, 2: bias+residual
__global__ __launch_bounds__(256, 2)
void gemm_tf32(const float* __restrict__ A, const float* __restrict__ B,
               const float* __restrict__ bias, const float* __restrict__ res,
               float* __restrict__ C, int M, int N, int K)
{
    __shared__ alignas(16) float As[2][BUFF];
    __shared__ alignas(16) float Bs[2][BUFF];

    const int tid = threadIdx.x;
    const int lane = tid & 31, wid = tid >> 5;
    const int wm = wid & 3, wn = wid >> 2;
    const int bx = blockIdx.x, by = blockIdx.y;

    // ---- global load mapping ----
    const int arow = tid >> 2, ac4 = (tid & 3) << 2;    // A: 64 rows/pass
    const int bk   = tid & 15, bn4 = (tid >> 4) << 2;   // B: 16 k-rows, 16 n4/pass
    const float* Ag0 = A + (size_t)(by*128 + arow)*K + ac4;
    const float* Ag1 = Ag0 + (size_t)64*K;
    const float* Bg0 = B + (size_t)bk*N + bx*128 + bn4;
    const float* Bg1 = Bg0 + 64;

    const int sa = arow*PA + ac4;

    // ---- ldmatrix per-lane addresses (buf 0, kh 0) ----
    const int lr = lane & 7, lq = (lane >> 3) & 1, lh = lane >> 4;
    uint32_t sAbase = (uint32_t)__cvta_generic_to_shared(&As[0][0]);
    uint32_t sBbase = (uint32_t)__cvta_generic_to_shared(&Bs[0][0]);
    uint32_t aAddr[2], bAddr[4];
#pragma unroll
    for (int mi = 0; mi < 2; mi++)
        aAddr[mi] = sAbase + (((wm*32 + mi*16 + lr + lq*8)*PA + lh*4) << 2);
#pragma unroll
    for (int p = 0; p < 4; p++)
        bAddr[p] = sBbase + (((wn*64 + p*16 + lr + lq*8)*PA + lh*4) << 2);

    float acc[2][8][4];
#pragma unroll
    for (int mi = 0; mi < 2; mi++)
#pragma unroll
        for (int ni = 0; ni < 8; ni++)
#pragma unroll
            for (int c = 0; c < 4; c++) acc[mi][ni][c] = 0.f;

    const int KT = K >> 4;

    // prologue: load tile 0 into buf 0
    {
        float4 a0 = *(const float4*)Ag0;
        float4 a1 = *(const float4*)Ag1;
        float4 b0 = *(const float4*)Bg0;
        float4 b1 = *(const float4*)Bg1;
        a0.x=tf32r(a0.x); a0.y=tf32r(a0.y); a0.z=tf32r(a0.z); a0.w=tf32r(a0.w);
        a1.x=tf32r(a1.x); a1.y=tf32r(a1.y); a1.z=tf32r(a1.z); a1.w=tf32r(a1.w);
        b0.x=tf32r(b0.x); b0.y=tf32r(b0.y); b0.z=tf32r(b0.z); b0.w=tf32r(b0.w);
        b1.x=tf32r(b1.x); b1.y=tf32r(b1.y); b1.z=tf32r(b1.z); b1.w=tf32r(b1.w);
        *(float4*)&As[0][sa]         = a0;
        *(float4*)&As[0][sa + 64*PA] = a1;
        Bs[0][(bn4+0)*PA + bk] = b0.x; Bs[0][(bn4+1)*PA + bk] = b0.y;
        Bs[0][(bn4+2)*PA + bk] = b0.z; Bs[0][(bn4+3)*PA + bk] = b0.w;
        Bs[0][(bn4+64)*PA + bk] = b1.x; Bs[0][(bn4+65)*PA + bk] = b1.y;
        Bs[0][(bn4+66)*PA + bk] = b1.z; Bs[0][(bn4+67)*PA + bk] = b1.w;
    }
    __syncthreads();

    int buf = 0;
    for (int kt = 0; kt < KT; kt++) {
        const bool next = (kt + 1 < KT);
        float4 a0, a1, b0, b1;
        if (next) {
            a0 = *(const float4*)(Ag0 + (kt+1)*16);
            a1 = *(const float4*)(Ag1 + (kt+1)*16);
            b0 = *(const float4*)(Bg0 + (size_t)(kt+1)*16*N);
            b1 = *(const float4*)(Bg1 + (size_t)(kt+1)*16*N);
        }

        // compute current buffer
        const uint32_t bo = buf ? (uint32_t)(BUFF*4) : 0u;
#pragma unroll
        for (int kh = 0; kh < 2; kh++) {
            uint32_t af[2][4], bf[4][4];
            ldsm4(af[0], aAddr[0] + bo + kh*32);
            ldsm4(af[1], aAddr[1] + bo + kh*32);
#pragma unroll
            for (int p = 0; p < 4; p++) ldsm4(bf[p], bAddr[p] + bo + kh*32);
#pragma unroll
            for (int ni = 0; ni < 8; ni++) {
                const uint32_t bb0 = bf[ni>>1][ni&1];
                const uint32_t bb1 = bf[ni>>1][2 + (ni&1)];
                mma_tf32(acc[0][ni], af[0], bb0, bb1);
                mma_tf32(acc[1][ni], af[1], bb0, bb1);
            }
        }

        if (next) {
            const int nb = buf ^ 1;
            a0.x=tf32r(a0.x); a0.y=tf32r(a0.y); a0.z=tf32r(a0.z); a0.w=tf32r(a0.w);
            a1.x=tf32r(a1.x); a1.y=tf32r(a1.y); a1.z=tf32r(a1.z); a1.w=tf32r(a1.w);
            b0.x=tf32r(b0.x); b0.y=tf32r(b0.y); b0.z=tf32r(b0.z); b0.w=tf32r(b0.w);
            b1.x=tf32r(b1.x); b1.y=tf32r(b1.y); b1.z=tf32r(b1.z); b1.w=tf32r(b1.w);
            *(float4*)&As[nb][sa]         = a0;
            *(float4*)&As[nb][sa + 64*PA] = a1;
            Bs[nb][(bn4+0)*PA + bk] = b0.x; Bs[nb][(bn4+1)*PA + bk] = b0.y;
            Bs[nb][(bn4+2)*PA + bk] = b0.z; Bs[nb][(bn4+3)*PA + bk] = b0.w;
            Bs[nb][(bn4+64)*PA + bk] = b1.x; Bs[nb][(bn4+65)*PA + bk] = b1.y;
            Bs[nb][(bn4+66)*PA + bk] = b1.z; Bs[nb][(bn4+67)*PA + bk] = b1.w;
            __syncthreads();
            buf = nb;
        }
    }

    // ---- epilogue ----
    const int r0 = (by*128) + wm*32 + (lane >> 2);
    const int c0 = (bx*128) + wn*64 + ((lane & 3) << 1);
#pragma unroll
    for (int mi = 0; mi < 2; mi++) {
        const int gr = r0 + mi*16;
#pragma unroll
        for (int ni = 0; ni < 8; ni++) {
            const int gc = c0 + ni*8;
            const float2 bia = *(const float2*)(bias + gc);
            float2 v0 = make_float2(acc[mi][ni][0] + bia.x, acc[mi][ni][1] + bia.y);
            float2 v1 = make_float2(acc[mi][ni][2] + bia.x, acc[mi][ni][3] + bia.y);
            if (EPI == 1) {
                v0.x = fmaxf(v0.x, 0.f); v0.y = fmaxf(v0.y, 0.f);
                v1.x = fmaxf(v1.x, 0.f); v1.y = fmaxf(v1.y, 0.f);
            }
            if (EPI == 2) {
                const float2 r_0 = *(const float2*)(res + (size_t)gr*N + gc);
                const float2 r_1 = *(const float2*)(res + (size_t)(gr+8)*N + gc);
                v0.x += r_0.x; v0.y += r_0.y;
                v1.x += r_1.x; v1.y += r_1.y;
            }
            *(float2*)(C + (size_t)gr*N + gc)     = v0;
            *(float2*)(C + (size_t)(gr+8)*N + gc) = v1;
        }
    }
}

// ---------------------------------------------------------------------------
// Flash attention (fp32, online softmax). One thread per query row.
// ---------------------------------------------------------------------------
__global__ __launch_bounds__(128)
void attn_kernel(const float* __restrict__ Q, const float* __restrict__ K,
                 const float* __restrict__ V, float* __restrict__ O)
{
    const int n = blockIdx.z, h = blockIdx.y;
    const int tid = threadIdx.x;
    const int row = blockIdx.x * 128 + tid;
    const float scale = 0.125f;

    __shared__ float Ks[32][64];
    __shared__ float Vs[32][64];

    float q[64];
    {
        const float4* qp = (const float4*)(Q + ((size_t)(n*SEQ + row))*DM + h*EHEAD);
#pragma unroll
        for (int i = 0; i < 16; i++) {
            float4 t = qp[i];
            q[4*i+0] = t.x; q[4*i+1] = t.y; q[4*i+2] = t.z; q[4*i+3] = t.w;
        }
    }

    float acc[64];
#pragma unroll
    for (int d = 0; d < 64; d++) acc[d] = 0.f;
    float m = -1e30f, lsum = 0.f;

    for (int kt = 0; kt < SEQ/32; kt++) {
        __syncthreads();
#pragma unroll
        for (int i = 0; i < 4; i++) {
            int idx = i*128 + tid;
            int r = idx >> 4;
            int c = (idx & 15) << 2;
            size_t gofs = ((size_t)(n*SEQ + kt*32 + r))*DM + h*EHEAD + c;
            *(float4*)&Ks[r][c] = *(const float4*)(K + gofs);
            *(float4*)&Vs[r][c] = *(const float4*)(V + gofs);
        }
        __syncthreads();

        float s[32];
#pragma unroll
        for (int j = 0; j < 32; j++) {
            const float4* kr = (const float4*)Ks[j];
            float sj = 0.f;
#pragma unroll
            for (int d4 = 0; d4 < 16; d4++) {
                float4 kv = kr[d4];
                sj += q[4*d4+0]*kv.x + q[4*d4+1]*kv.y
                    + q[4*d4+2]*kv.z + q[4*d4+3]*kv.w;
            }
            s[j] = sj * scale;
        }
        float tmax = m;
#pragma unroll
        for (int j = 0; j < 32; j++) tmax = fmaxf(tmax, s[j]);
        float corr = __expf(m - tmax);
        m = tmax;
        lsum *= corr;
#pragma unroll
        for (int d = 0; d < 64; d++) acc[d] *= corr;
#pragma unroll
        for (int j = 0; j < 32; j++) {
            float p = __expf(s[j] - m);
            lsum += p;
            const float4* vr = (const float4*)Vs[j];
#pragma unroll
            for (int d4 = 0; d4 < 16; d4++) {
                float4 vv = vr[d4];
                acc[4*d4+0] += p*vv.x; acc[4*d4+1] += p*vv.y;
                acc[4*d4+2] += p*vv.z; acc[4*d4+3] += p*vv.w;
            }
        }
    }

    const float inv = 1.f / lsum;
    float* op = O + ((size_t)(n*SEQ + row))*DM + h*EHEAD;
#pragma unroll
    for (int d = 0; d < 64; d += 4) {
        float4 o4 = make_float4(acc[d]*inv, acc[d+1]*inv, acc[d+2]*inv, acc[d+3]*inv);
        *(float4*)(op + d) = o4;
    }
}

// ---------------------------------------------------------------------------
// LayerNorm over last dim (512). One block (128 threads) per row.
// ---------------------------------------------------------------------------
__global__ __launch_bounds__(128)
void ln_kernel(const float* __restrict__ in, const float* __restrict__ gamma,
               const float* __restrict__ beta, float* __restrict__ out)
{
    const int row = blockIdx.x, tid = threadIdx.x;
    const float4 v = ((const float4*)(in + (size_t)row*DM))[tid];
    float s  = v.x + v.y + v.z + v.w;
    float sq = v.x*v.x + v.y*v.y + v.z*v.z + v.w*v.w;
#pragma unroll
    for (int o = 16; o; o >>= 1) {
        s  += __shfl_down_sync(0xffffffffu, s,  o);
        sq += __shfl_down_sync(0xffffffffu, sq, o);
    }
    __shared__ float ss[4], sqs[4];
    const int w = tid >> 5, lane = tid & 31;
    if (lane == 0) { ss[w] = s; sqs[w] = sq; }
    __syncthreads();
    s  = ss[0] + ss[1] + ss[2] + ss[3];
    sq = sqs[0] + sqs[1] + sqs[2] + sqs[3];

    const float mean = s * (1.f / DM);
    const float var  = sq * (1.f / DM) - mean * mean;
    const float inv  = rsqrtf(var + LN_EPS);

    const float4 g4 = ((const float4*)gamma)[tid];
    const float4 b4 = ((const float4*)beta)[tid];
    float4 o4;
    o4.x = (v.x - mean)*inv*g4.x + b4.x;
    o4.y = (v.y - mean)*inv*g4.y + b4.y;
    o4.z = (v.z - mean)*inv*g4.z + b4.z;
    o4.w = (v.w - mean)*inv*g4.w + b4.w;
    ((float4*)(out + (size_t)row*DM))[tid] = o4;
}

// ---------------------------------------------------------------------------
extern "C" void kernel_launch(void* const* d_in, const int* in_sizes, int n_in,
                              void* d_out, int out_size)
{
    const float* x   = (const float*)d_in[0];
    const float* Wq  = (const float*)d_in[1];
    const float* bq  = (const float*)d_in[2];
    const float* Wk  = (const float*)d_in[3];
    const float* bk  = (const float*)d_in[4];
    const float* Wv  = (const float*)d_in[5];
    const float* bv  = (const float*)d_in[6];
    const float* Wo  = (const float*)d_in[7];
    const float* bo  = (const float*)d_in[8];
    const float* W1  = (const float*)d_in[9];
    const float* b1  = (const float*)d_in[10];
    const float* W2  = (const float*)d_in[11];
    const float* b2  = (const float*)d_in[12];
    const float* g1  = (const float*)d_in[13];
    const float* be1 = (const float*)d_in[14];
    const float* g2  = (const float*)d_in[15];
    const float* be2 = (const float*)d_in[16];

    float *q, *k, *v, *o, *hb, *h1, *h2, *xb, *ff;
    cudaGetSymbolAddress((void**)&q,  g_q);
    cudaGetSymbolAddress((void**)&k,  g_k);
    cudaGetSymbolAddress((void**)&v,  g_v);
    cudaGetSymbolAddress((void**)&o,  g_o);
    cudaGetSymbolAddress((void**)&hb, g_h);
    cudaGetSymbolAddress((void**)&h1, g_h1);
    cudaGetSymbolAddress((void**)&h2, g_h2);
    cudaGetSymbolAddress((void**)&xb, g_x);
    cudaGetSymbolAddress((void**)&ff, g_ff);

    const dim3 gProj(DM / 128, ROWS / 128);    // (4, 64)
    const dim3 gFF1 (DFF / 128, ROWS / 128);   // (16, 64)
    const dim3 gAttn(SEQ / 128, NHEAD, NB);    // (8, 8, 8)

    const float* hin = x;
    for (int l = 0; l < NLAYERS; l++) {
        const float* wq = Wq + (size_t)l*DM*DM;
        const float* wk = Wk + (size_t)l*DM*DM;
        const float* wv = Wv + (size_t)l*DM*DM;
        const float* wo = Wo + (size_t)l*DM*DM;
        const float* w1 = W1 + (size_t)l*DM*DFF;
        const float* w2 = W2 + (size_t)l*DFF*DM;

        gemm_tf32<0><<<gProj, 256>>>(hin, wq, bq + l*DM, nullptr, q, ROWS, DM, DM);
        gemm_tf32<0><<<gProj, 256>>>(hin, wk, bk + l*DM, nullptr, k, ROWS, DM, DM);
        gemm_tf32<0><<<gProj, 256>>>(hin, wv, bv + l*DM, nullptr, v, ROWS, DM, DM);

        attn_kernel<<<gAttn, 128>>>(q, k, v, o);

        gemm_tf32<2><<<gProj, 256>>>(o, wo, bo + l*DM, hin, hb, ROWS, DM, DM);
        ln_kernel<<<ROWS, 128>>>(hb, g1 + l*DM, be1 + l*DM, h1);

        gemm_tf32<1><<<gFF1, 256>>>(h1, w1, b1 + l*DFF, nullptr, ff, ROWS, DFF, DM);
        gemm_tf32<2><<<gProj, 256>>>(ff, w2, b2 + l*DM, h1, h2, ROWS, DM, DFF);

        float* lnout = (l == NLAYERS - 1) ? (float*)d_out : xb;
        ln_kernel<<<ROWS, 128>>>(h2, g2 + l*DM, be2 + l*DM, lnout);
        hin = xb;
    }
}

// round 3
// speedup vs baseline: 2.6386x; 1.5895x over previous
#include <cuda_runtime.h>
#include <cuda_bf16.h>
#include <cstdint>
#include <cstddef>

// Problem constants
#define DM      512
#define DFF     2048
#define NB      8
#define SEQ     1024
#define NHEAD   8
#define EHEAD   64
#define ROWS    (NB*SEQ)     // 8192
#define NLAYERS 4
#define LN_EPS  1e-5f

// ---------------- scratch (device globals; no allocations allowed) --------
__device__ float g_q [ROWS*DM];
__device__ float g_k [ROWS*DM];
__device__ float g_v [ROWS*DM];
__device__ float g_o [ROWS*DM];
__device__ float g_h [ROWS*DM];
__device__ float g_h1[ROWS*DM];
__device__ float g_h2[ROWS*DM];
__device__ float g_x [ROWS*DM];
__device__ float g_ff[ROWS*DFF];

// ---------------- common tensor-core helpers ------------------------------
__device__ __forceinline__ float tf32r(float x) {
    uint32_t u;
    asm("cvt.rna.tf32.f32 %0, %1;" : "=r"(u) : "f"(x));
    return __uint_as_float(u);
}
__device__ __forceinline__ void ldsm4(uint32_t* r, uint32_t addr) {
    asm volatile("ldmatrix.sync.aligned.m8n8.x4.shared.b16 {%0,%1,%2,%3}, [%4];\n"
                 : "=r"(r[0]), "=r"(r[1]), "=r"(r[2]), "=r"(r[3]) : "r"(addr));
}
__device__ __forceinline__ void mma_tf32(float* d, const uint32_t* a,
                                         uint32_t b0, uint32_t b1) {
    asm volatile(
        "mma.sync.aligned.m16n8k8.row.col.f32.tf32.tf32.f32 "
        "{%0,%1,%2,%3},{%4,%5,%6,%7},{%8,%9},{%0,%1,%2,%3};\n"
        : "+f"(d[0]), "+f"(d[1]), "+f"(d[2]), "+f"(d[3])
        : "r"(a[0]), "r"(a[1]), "r"(a[2]), "r"(a[3]), "r"(b0), "r"(b1));
}

// ---------------------------------------------------------------------------
// TF32 tensor-core GEMM:  C[M,N] = A[M,K] @ B[K,N] + bias (+ReLU | +residual)
// ---------------------------------------------------------------------------
#define PA 20
#define BUFF (128*PA)

template<int EPI>   // 0: bias, 1: bias+relu, 2: bias+residual
__global__ __launch_bounds__(256, 2)
void gemm_tf32(const float* __restrict__ A, const float* __restrict__ B,
               const float* __restrict__ bias, const float* __restrict__ res,
               float* __restrict__ C, int M, int N, int K)
{
    __shared__ alignas(16) float As[2][BUFF];
    __shared__ alignas(16) float Bs[2][BUFF];

    const int tid = threadIdx.x;
    const int lane = tid & 31, wid = tid >> 5;
    const int wm = wid & 3, wn = wid >> 2;
    const int bx = blockIdx.x, by = blockIdx.y;

    const int arow = tid >> 2, ac4 = (tid & 3) << 2;
    const int bk   = tid & 15, bn4 = (tid >> 4) << 2;
    const float* Ag0 = A + (size_t)(by*128 + arow)*K + ac4;
    const float* Ag1 = Ag0 + (size_t)64*K;
    const float* Bg0 = B + (size_t)bk*N + bx*128 + bn4;
    const float* Bg1 = Bg0 + 64;

    const int sa = arow*PA + ac4;

    const int lr = lane & 7, lq = (lane >> 3) & 1, lh = lane >> 4;
    uint32_t sAbase = (uint32_t)__cvta_generic_to_shared(&As[0][0]);
    uint32_t sBbase = (uint32_t)__cvta_generic_to_shared(&Bs[0][0]);
    uint32_t aAddr[2], bAddr[4];
#pragma unroll
    for (int mi = 0; mi < 2; mi++)
        aAddr[mi] = sAbase + (((wm*32 + mi*16 + lr + lq*8)*PA + lh*4) << 2);
#pragma unroll
    for (int p = 0; p < 4; p++)
        bAddr[p] = sBbase + (((wn*64 + p*16 + lr + lq*8)*PA + lh*4) << 2);

    float acc[2][8][4];
#pragma unroll
    for (int mi = 0; mi < 2; mi++)
#pragma unroll
        for (int ni = 0; ni < 8; ni++)
#pragma unroll
            for (int c = 0; c < 4; c++) acc[mi][ni][c] = 0.f;

    const int KT = K >> 4;

    {
        float4 a0 = *(const float4*)Ag0;
        float4 a1 = *(const float4*)Ag1;
        float4 b0 = *(const float4*)Bg0;
        float4 b1 = *(const float4*)Bg1;
        a0.x=tf32r(a0.x); a0.y=tf32r(a0.y); a0.z=tf32r(a0.z); a0.w=tf32r(a0.w);
        a1.x=tf32r(a1.x); a1.y=tf32r(a1.y); a1.z=tf32r(a1.z); a1.w=tf32r(a1.w);
        b0.x=tf32r(b0.x); b0.y=tf32r(b0.y); b0.z=tf32r(b0.z); b0.w=tf32r(b0.w);
        b1.x=tf32r(b1.x); b1.y=tf32r(b1.y); b1.z=tf32r(b1.z); b1.w=tf32r(b1.w);
        *(float4*)&As[0][sa]         = a0;
        *(float4*)&As[0][sa + 64*PA] = a1;
        Bs[0][(bn4+0)*PA + bk] = b0.x; Bs[0][(bn4+1)*PA + bk] = b0.y;
        Bs[0][(bn4+2)*PA + bk] = b0.z; Bs[0][(bn4+3)*PA + bk] = b0.w;
        Bs[0][(bn4+64)*PA + bk] = b1.x; Bs[0][(bn4+65)*PA + bk] = b1.y;
        Bs[0][(bn4+66)*PA + bk] = b1.z; Bs[0][(bn4+67)*PA + bk] = b1.w;
    }
    __syncthreads();

    int buf = 0;
    for (int kt = 0; kt < KT; kt++) {
        const bool next = (kt + 1 < KT);
        float4 a0, a1, b0, b1;
        if (next) {
            a0 = *(const float4*)(Ag0 + (kt+1)*16);
            a1 = *(const float4*)(Ag1 + (kt+1)*16);
            b0 = *(const float4*)(Bg0 + (size_t)(kt+1)*16*N);
            b1 = *(const float4*)(Bg1 + (size_t)(kt+1)*16*N);
        }

        const uint32_t bo = buf ? (uint32_t)(BUFF*4) : 0u;
#pragma unroll
        for (int kh = 0; kh < 2; kh++) {
            uint32_t af[2][4], bf[4][4];
            ldsm4(af[0], aAddr[0] + bo + kh*32);
            ldsm4(af[1], aAddr[1] + bo + kh*32);
#pragma unroll
            for (int p = 0; p < 4; p++) ldsm4(bf[p], bAddr[p] + bo + kh*32);
#pragma unroll
            for (int ni = 0; ni < 8; ni++) {
                const uint32_t bb0 = bf[ni>>1][ni&1];
                const uint32_t bb1 = bf[ni>>1][2 + (ni&1)];
                mma_tf32(acc[0][ni], af[0], bb0, bb1);
                mma_tf32(acc[1][ni], af[1], bb0, bb1);
            }
        }

        if (next) {
            const int nb = buf ^ 1;
            a0.x=tf32r(a0.x); a0.y=tf32r(a0.y); a0.z=tf32r(a0.z); a0.w=tf32r(a0.w);
            a1.x=tf32r(a1.x); a1.y=tf32r(a1.y); a1.z=tf32r(a1.z); a1.w=tf32r(a1.w);
            b0.x=tf32r(b0.x); b0.y=tf32r(b0.y); b0.z=tf32r(b0.z); b0.w=tf32r(b0.w);
            b1.x=tf32r(b1.x); b1.y=tf32r(b1.y); b1.z=tf32r(b1.z); b1.w=tf32r(b1.w);
            *(float4*)&As[nb][sa]         = a0;
            *(float4*)&As[nb][sa + 64*PA] = a1;
            Bs[nb][(bn4+0)*PA + bk] = b0.x; Bs[nb][(bn4+1)*PA + bk] = b0.y;
            Bs[nb][(bn4+2)*PA + bk] = b0.z; Bs[nb][(bn4+3)*PA + bk] = b0.w;
            Bs[nb][(bn4+64)*PA + bk] = b1.x; Bs[nb][(bn4+65)*PA + bk] = b1.y;
            Bs[nb][(bn4+66)*PA + bk] = b1.z; Bs[nb][(bn4+67)*PA + bk] = b1.w;
            __syncthreads();
            buf = nb;
        }
    }

    const int r0 = (by*128) + wm*32 + (lane >> 2);
    const int c0 = (bx*128) + wn*64 + ((lane & 3) << 1);
#pragma unroll
    for (int mi = 0; mi < 2; mi++) {
        const int gr = r0 + mi*16;
#pragma unroll
        for (int ni = 0; ni < 8; ni++) {
            const int gc = c0 + ni*8;
            const float2 bia = *(const float2*)(bias + gc);
            float2 v0 = make_float2(acc[mi][ni][0] + bia.x, acc[mi][ni][1] + bia.y);
            float2 v1 = make_float2(acc[mi][ni][2] + bia.x, acc[mi][ni][3] + bia.y);
            if (EPI == 1) {
                v0.x = fmaxf(v0.x, 0.f); v0.y = fmaxf(v0.y, 0.f);
                v1.x = fmaxf(v1.x, 0.f); v1.y = fmaxf(v1.y, 0.f);
            }
            if (EPI == 2) {
                const float2 r_0 = *(const float2*)(res + (size_t)gr*N + gc);
                const float2 r_1 = *(const float2*)(res + (size_t)(gr+8)*N + gc);
                v0.x += r_0.x; v0.y += r_0.y;
                v1.x += r_1.x; v1.y += r_1.y;
            }
            *(float2*)(C + (size_t)gr*N + gc)     = v0;
            *(float2*)(C + (size_t)(gr+8)*N + gc) = v1;
        }
    }
}

// ---------------------------------------------------------------------------
// Tensor-core flash attention (tf32 mma, fp32 softmax).
// Block = 128 q rows of one (batch, head); 8 warps, warp = 16 q rows.
// K-tile = 128 keys. P round-trips through smem (warp-private rows).
// smem: sP (128 x 132, also holds Q initially), sK (128 x 68), sV (128 x 68).
// ---------------------------------------------------------------------------
#define ATT_PQ 132
#define ATT_PK 68
#define ATT_OFF_K (128*ATT_PQ)
#define ATT_OFF_V (ATT_OFF_K + 128*ATT_PK)
#define ATT_SMEM_BYTES ((128*ATT_PQ + 2*128*ATT_PK)*4)

__global__ __launch_bounds__(256, 1)
void attn_tc(const float* __restrict__ Q, const float* __restrict__ K,
             const float* __restrict__ V, float* __restrict__ O)
{
    extern __shared__ float sm[];
    float* sP = sm;
    float* sK = sm + ATT_OFF_K;
    float* sV = sm + ATT_OFF_V;

    const int n = blockIdx.z, h = blockIdx.y;
    const int tid = threadIdx.x, lane = tid & 31, w = tid >> 5;
    const size_t base = ((size_t)n*SEQ)*DM + h*EHEAD;
    const int q0 = blockIdx.x * 128;

    // ---- load Q tile (scaled by 1/8, tf32) into sP ----
#pragma unroll
    for (int i = 0; i < 8; i++) {
        int idx = i*256 + tid;              // 0..2047
        int r = idx >> 4, c4 = (idx & 15) << 2;
        float4 t = *(const float4*)(Q + base + (size_t)(q0 + r)*DM + c4);
        t.x = tf32r(t.x*0.125f); t.y = tf32r(t.y*0.125f);
        t.z = tf32r(t.z*0.125f); t.w = tf32r(t.w*0.125f);
        *(float4*)&sP[r*ATT_PQ + c4] = t;
    }
    __syncthreads();

    // ---- hoist Q fragments (warp-private rows) ----
    const int lr = lane & 7, lq = (lane >> 3) & 1, lh = lane >> 4;
    const uint32_t sPu = (uint32_t)__cvta_generic_to_shared(sP);
    const uint32_t sKu = (uint32_t)__cvta_generic_to_shared(sK);
    const uint32_t aBase = sPu + (((w*16 + lr + lq*8)*ATT_PQ + lh*4) << 2);
    uint32_t aQ[8][4];
#pragma unroll
    for (int ks = 0; ks < 8; ks++) ldsm4(aQ[ks], aBase + ks*32);

    uint32_t bK[8];
#pragma unroll
    for (int p = 0; p < 8; p++)
        bK[p] = sKu + (((p*16 + lr + lq*8)*ATT_PK + lh*4) << 2);

    float accO[8][4];
#pragma unroll
    for (int ni = 0; ni < 8; ni++)
#pragma unroll
        for (int c = 0; c < 4; c++) accO[ni][c] = 0.f;
    float m0 = -1e30f, m1 = -1e30f, l0 = 0.f, l1 = 0.f;

    const int rA = w*16 + (lane >> 2);
    float* pr0 = &sP[rA*ATT_PQ + 2*(lane & 3)];
    float* pr1 = pr0 + 8*ATT_PQ;

    for (int kt = 0; kt < SEQ/128; kt++) {
        __syncthreads();
#pragma unroll
        for (int i = 0; i < 8; i++) {
            int idx = i*256 + tid;
            int r = idx >> 4, c4 = (idx & 15) << 2;
            size_t g = base + (size_t)(kt*128 + r)*DM + c4;
            float4 a = *(const float4*)(K + g);
            a.x=tf32r(a.x); a.y=tf32r(a.y); a.z=tf32r(a.z); a.w=tf32r(a.w);
            *(float4*)&sK[r*ATT_PK + c4] = a;
            float4 b = *(const float4*)(V + g);
            b.x=tf32r(b.x); b.y=tf32r(b.y); b.z=tf32r(b.z); b.w=tf32r(b.w);
            *(float4*)&sV[r*ATT_PK + c4] = b;
        }
        __syncthreads();

        // ---- S = Q K^T ----
        float accS[16][4];
#pragma unroll
        for (int t = 0; t < 16; t++)
#pragma unroll
            for (int c = 0; c < 4; c++) accS[t][c] = 0.f;
#pragma unroll
        for (int ks = 0; ks < 8; ks++) {
#pragma unroll
            for (int p = 0; p < 8; p++) {
                uint32_t bf[4];
                ldsm4(bf, bK[p] + ks*32);
                mma_tf32(accS[2*p],   aQ[ks], bf[0], bf[2]);
                mma_tf32(accS[2*p+1], aQ[ks], bf[1], bf[3]);
            }
        }

        // ---- online softmax ----
        float rmax0 = -1e30f, rmax1 = -1e30f;
#pragma unroll
        for (int t = 0; t < 16; t++) {
            rmax0 = fmaxf(rmax0, fmaxf(accS[t][0], accS[t][1]));
            rmax1 = fmaxf(rmax1, fmaxf(accS[t][2], accS[t][3]));
        }
        rmax0 = fmaxf(rmax0, __shfl_xor_sync(0xffffffffu, rmax0, 1));
        rmax0 = fmaxf(rmax0, __shfl_xor_sync(0xffffffffu, rmax0, 2));
        rmax1 = fmaxf(rmax1, __shfl_xor_sync(0xffffffffu, rmax1, 1));
        rmax1 = fmaxf(rmax1, __shfl_xor_sync(0xffffffffu, rmax1, 2));
        const float mn0 = fmaxf(m0, rmax0), mn1 = fmaxf(m1, rmax1);
        const float cr0 = __expf(m0 - mn0), cr1 = __expf(m1 - mn1);
        m0 = mn0; m1 = mn1;
        l0 *= cr0; l1 *= cr1;
#pragma unroll
        for (int ni = 0; ni < 8; ni++) {
            accO[ni][0] *= cr0; accO[ni][1] *= cr0;
            accO[ni][2] *= cr1; accO[ni][3] *= cr1;
        }
#pragma unroll
        for (int t = 0; t < 16; t++) {
            float p0 = __expf(accS[t][0] - m0), p1 = __expf(accS[t][1] - m0);
            float p2 = __expf(accS[t][2] - m1), p3 = __expf(accS[t][3] - m1);
            l0 += p0 + p1; l1 += p2 + p3;
            *(float2*)(pr0 + t*8) = make_float2(tf32r(p0), tf32r(p1));
            *(float2*)(pr1 + t*8) = make_float2(tf32r(p2), tf32r(p3));
        }
        __syncwarp();

        // ---- O += P V ----
        const int kk0 = (lane & 3)*ATT_PK + (lane >> 2);
#pragma unroll
        for (int ks = 0; ks < 16; ks++) {
            uint32_t aP[4];
            ldsm4(aP, aBase + ks*32);
            const float* vb = &sV[ks*8*ATT_PK + kk0];
#pragma unroll
            for (int ni = 0; ni < 8; ni++) {
                uint32_t b0 = __float_as_uint(vb[ni*8]);
                uint32_t b1 = __float_as_uint(vb[4*ATT_PK + ni*8]);
                mma_tf32(accO[ni], aP, b0, b1);
            }
        }
    }

    // ---- epilogue: divide by full row-sum, write ----
    l0 += __shfl_xor_sync(0xffffffffu, l0, 1);
    l0 += __shfl_xor_sync(0xffffffffu, l0, 2);
    l1 += __shfl_xor_sync(0xffffffffu, l1, 1);
    l1 += __shfl_xor_sync(0xffffffffu, l1, 2);
    const float inv0 = 1.f / l0, inv1 = 1.f / l1;
    const int gr0 = q0 + w*16 + (lane >> 2);
    const int cc = 2*(lane & 3);
#pragma unroll
    for (int ni = 0; ni < 8; ni++) {
        float2 v0 = make_float2(accO[ni][0]*inv0, accO[ni][1]*inv0);
        float2 v1 = make_float2(accO[ni][2]*inv1, accO[ni][3]*inv1);
        *(float2*)(O + base + (size_t)gr0*DM + ni*8 + cc)     = v0;
        *(float2*)(O + base + (size_t)(gr0+8)*DM + ni*8 + cc) = v1;
    }
}

// ---------------------------------------------------------------------------
// LayerNorm over last dim (512). One block (128 threads) per row.
// ---------------------------------------------------------------------------
__global__ __launch_bounds__(128)
void ln_kernel(const float* __restrict__ in, const float* __restrict__ gamma,
               const float* __restrict__ beta, float* __restrict__ out)
{
    const int row = blockIdx.x, tid = threadIdx.x;
    const float4 v = ((const float4*)(in + (size_t)row*DM))[tid];
    float s  = v.x + v.y + v.z + v.w;
    float sq = v.x*v.x + v.y*v.y + v.z*v.z + v.w*v.w;
#pragma unroll
    for (int o = 16; o; o >>= 1) {
        s  += __shfl_down_sync(0xffffffffu, s,  o);
        sq += __shfl_down_sync(0xffffffffu, sq, o);
    }
    __shared__ float ss[4], sqs[4];
    const int w = tid >> 5, lane = tid & 31;
    if (lane == 0) { ss[w] = s; sqs[w] = sq; }
    __syncthreads();
    s  = ss[0] + ss[1] + ss[2] + ss[3];
    sq = sqs[0] + sqs[1] + sqs[2] + sqs[3];

    const float mean = s * (1.f / DM);
    const float var  = sq * (1.f / DM) - mean * mean;
    const float inv  = rsqrtf(var + LN_EPS);

    const float4 g4 = ((const float4*)gamma)[tid];
    const float4 b4 = ((const float4*)beta)[tid];
    float4 o4;
    o4.x = (v.x - mean)*inv*g4.x + b4.x;
    o4.y = (v.y - mean)*inv*g4.y + b4.y;
    o4.z = (v.z - mean)*inv*g4.z + b4.z;
    o4.w = (v.w - mean)*inv*g4.w + b4.w;
    ((float4*)(out + (size_t)row*DM))[tid] = o4;
}

// ---------------------------------------------------------------------------
extern "C" void kernel_launch(void* const* d_in, const int* in_sizes, int n_in,
                              void* d_out, int out_size)
{
    const float* x   = (const float*)d_in[0];
    const float* Wq  = (const float*)d_in[1];
    const float* bq  = (const float*)d_in[2];
    const float* Wk  = (const float*)d_in[3];
    const float* bk  = (const float*)d_in[4];
    const float* Wv  = (const float*)d_in[5];
    const float* bv  = (const float*)d_in[6];
    const float* Wo  = (const float*)d_in[7];
    const float* bo  = (const float*)d_in[8];
    const float* W1  = (const float*)d_in[9];
    const float* b1  = (const float*)d_in[10];
    const float* W2  = (const float*)d_in[11];
    const float* b2  = (const float*)d_in[12];
    const float* g1  = (const float*)d_in[13];
    const float* be1 = (const float*)d_in[14];
    const float* g2  = (const float*)d_in[15];
    const float* be2 = (const float*)d_in[16];

    float *q, *k, *v, *o, *hb, *h1, *h2, *xb, *ff;
    cudaGetSymbolAddress((void**)&q,  g_q);
    cudaGetSymbolAddress((void**)&k,  g_k);
    cudaGetSymbolAddress((void**)&v,  g_v);
    cudaGetSymbolAddress((void**)&o,  g_o);
    cudaGetSymbolAddress((void**)&hb, g_h);
    cudaGetSymbolAddress((void**)&h1, g_h1);
    cudaGetSymbolAddress((void**)&h2, g_h2);
    cudaGetSymbolAddress((void**)&xb, g_x);
    cudaGetSymbolAddress((void**)&ff, g_ff);

    cudaFuncSetAttribute(attn_tc, cudaFuncAttributeMaxDynamicSharedMemorySize,
                         ATT_SMEM_BYTES);

    const dim3 gProj(DM / 128, ROWS / 128);    // (4, 64)
    const dim3 gFF1 (DFF / 128, ROWS / 128);   // (16, 64)
    const dim3 gAttn(SEQ / 128, NHEAD, NB);    // (8, 8, 8)

    const float* hin = x;
    for (int l = 0; l < NLAYERS; l++) {
        const float* wq = Wq + (size_t)l*DM*DM;
        const float* wk = Wk + (size_t)l*DM*DM;
        const float* wv = Wv + (size_t)l*DM*DM;
        const float* wo = Wo + (size_t)l*DM*DM;
        const float* w1 = W1 + (size_t)l*DM*DFF;
        const float* w2 = W2 + (size_t)l*DFF*DM;

        gemm_tf32<0><<<gProj, 256>>>(hin, wq, bq + l*DM, nullptr, q, ROWS, DM, DM);
        gemm_tf32<0><<<gProj, 256>>>(hin, wk, bk + l*DM, nullptr, k, ROWS, DM, DM);
        gemm_tf32<0><<<gProj, 256>>>(hin, wv, bv + l*DM, nullptr, v, ROWS, DM, DM);

        attn_tc<<<gAttn, 256, ATT_SMEM_BYTES>>>(q, k, v, o);

        gemm_tf32<2><<<gProj, 256>>>(o, wo, bo + l*DM, hin, hb, ROWS, DM, DM);
        ln_kernel<<<ROWS, 128>>>(hb, g1 + l*DM, be1 + l*DM, h1);

        gemm_tf32<1><<<gFF1, 256>>>(h1, w1, b1 + l*DFF, nullptr, ff, ROWS, DFF, DM);
        gemm_tf32<2><<<gProj, 256>>>(ff, w2, b2 + l*DM, h1, h2, ROWS, DM, DFF);

        float* lnout = (l == NLAYERS - 1) ? (float*)d_out : xb;
        ln_kernel<<<ROWS, 128>>>(h2, g2 + l*DM, be2 + l*DM, lnout);
        hin = xb;
    }
}

// round 5
// speedup vs baseline: 2.7671x; 1.0487x over previous
#include <cuda_runtime.h>
#include <cuda_bf16.h>
#include <cstdint>
#include <cstddef>

// Problem constants
#define DM      512
#define DFF     2048
#define NB      8
#define SEQ     1024
#define NHEAD   8
#define EHEAD   64
#define ROWS    (NB*SEQ)     // 8192
#define NLAYERS 4
#define LN_EPS  1e-5f

// ---------------- scratch (device globals; no allocations allowed) --------
__device__ float g_q [ROWS*DM];
__device__ float g_k [ROWS*DM];
__device__ float g_v [ROWS*DM];    // holds V^T: [col(=h*64+d)][token]
__device__ float g_o [ROWS*DM];
__device__ float g_h [ROWS*DM];
__device__ float g_h1[ROWS*DM];
__device__ float g_h2[ROWS*DM];
__device__ float g_x [ROWS*DM];
__device__ float g_ff[ROWS*DFF];

// ---------------- common tensor-core helpers ------------------------------
__device__ __forceinline__ float tf32r(float x) {
    uint32_t u;
    asm("cvt.rna.tf32.f32 %0, %1;" : "=r"(u) : "f"(x));
    return __uint_as_float(u);
}
__device__ __forceinline__ void ldsm4(uint32_t* r, uint32_t addr) {
    asm volatile("ldmatrix.sync.aligned.m8n8.x4.shared.b16 {%0,%1,%2,%3}, [%4];\n"
                 : "=r"(r[0]), "=r"(r[1]), "=r"(r[2]), "=r"(r[3]) : "r"(addr));
}
__device__ __forceinline__ void mma_tf32(float* d, const uint32_t* a,
                                         uint32_t b0, uint32_t b1) {
    asm volatile(
        "mma.sync.aligned.m16n8k8.row.col.f32.tf32.tf32.f32 "
        "{%0,%1,%2,%3},{%4,%5,%6,%7},{%8,%9},{%0,%1,%2,%3};\n"
        : "+f"(d[0]), "+f"(d[1]), "+f"(d[2]), "+f"(d[3])
        : "r"(a[0]), "r"(a[1]), "r"(a[2]), "r"(a[3]), "r"(b0), "r"(b1));
}
__device__ __forceinline__ uint32_t smem_u32(const void* p) {
    return (uint32_t)__cvta_generic_to_shared(p);
}
__device__ __forceinline__ void cpa16(uint32_t dst, const void* src) {
    asm volatile("cp.async.ca.shared.global [%0], [%1], 16;\n"
                 :: "r"(dst), "l"(src) : "memory");
}
__device__ __forceinline__ void cpa_commit() {
    asm volatile("cp.async.commit_group;\n" ::: "memory");
}
template<int N>
__device__ __forceinline__ void cpa_wait() {
    asm volatile("cp.async.wait_group %0;\n" :: "n"(N) : "memory");
}

// ---------------------------------------------------------------------------
// TF32 tensor-core GEMM:  C[M,N] = A[M,K] @ B[K,N] + bias
//   EPI 0: bias   1: bias+relu   2: bias+residual   3: bias, store C^T
//   (EPI 3 stores C^T with layout Ct[col][row], row-count = ROWS)
// ---------------------------------------------------------------------------
#define PA 20
#define BUFF (128*PA)

template<int EPI>
__global__ __launch_bounds__(256, 2)
void gemm_tf32(const float* __restrict__ A, const float* __restrict__ B,
               const float* __restrict__ bias, const float* __restrict__ res,
               float* __restrict__ C, int M, int N, int K)
{
    __shared__ alignas(16) float As[2][BUFF];
    __shared__ alignas(16) float Bs[2][BUFF];

    const int tid = threadIdx.x;
    const int lane = tid & 31, wid = tid >> 5;
    const int wm = wid & 3, wn = wid >> 2;
    const int bx = blockIdx.x, by = blockIdx.y;

    const int arow = tid >> 2, ac4 = (tid & 3) << 2;
    const int bk   = tid & 15, bn4 = (tid >> 4) << 2;
    const float* Ag0 = A + (size_t)(by*128 + arow)*K + ac4;
    const float* Ag1 = Ag0 + (size_t)64*K;
    const float* Bg0 = B + (size_t)bk*N + bx*128 + bn4;
    const float* Bg1 = Bg0 + 64;

    const int sa = arow*PA + ac4;

    const int lr = lane & 7, lq = (lane >> 3) & 1, lh = lane >> 4;
    uint32_t sAbase = (uint32_t)__cvta_generic_to_shared(&As[0][0]);
    uint32_t sBbase = (uint32_t)__cvta_generic_to_shared(&Bs[0][0]);
    uint32_t aAddr[2], bAddr[4];
#pragma unroll
    for (int mi = 0; mi < 2; mi++)
        aAddr[mi] = sAbase + (((wm*32 + mi*16 + lr + lq*8)*PA + lh*4) << 2);
#pragma unroll
    for (int p = 0; p < 4; p++)
        bAddr[p] = sBbase + (((wn*64 + p*16 + lr + lq*8)*PA + lh*4) << 2);

    float acc[2][8][4];
#pragma unroll
    for (int mi = 0; mi < 2; mi++)
#pragma unroll
        for (int ni = 0; ni < 8; ni++)
#pragma unroll
            for (int c = 0; c < 4; c++) acc[mi][ni][c] = 0.f;

    const int KT = K >> 4;

    {
        float4 a0 = *(const float4*)Ag0;
        float4 a1 = *(const float4*)Ag1;
        float4 b0 = *(const float4*)Bg0;
        float4 b1 = *(const float4*)Bg1;
        a0.x=tf32r(a0.x); a0.y=tf32r(a0.y); a0.z=tf32r(a0.z); a0.w=tf32r(a0.w);
        a1.x=tf32r(a1.x); a1.y=tf32r(a1.y); a1.z=tf32r(a1.z); a1.w=tf32r(a1.w);
        b0.x=tf32r(b0.x); b0.y=tf32r(b0.y); b0.z=tf32r(b0.z); b0.w=tf32r(b0.w);
        b1.x=tf32r(b1.x); b1.y=tf32r(b1.y); b1.z=tf32r(b1.z); b1.w=tf32r(b1.w);
        *(float4*)&As[0][sa]         = a0;
        *(float4*)&As[0][sa + 64*PA] = a1;
        Bs[0][(bn4+0)*PA + bk] = b0.x; Bs[0][(bn4+1)*PA + bk] = b0.y;
        Bs[0][(bn4+2)*PA + bk] = b0.z; Bs[0][(bn4+3)*PA + bk] = b0.w;
        Bs[0][(bn4+64)*PA + bk] = b1.x; Bs[0][(bn4+65)*PA + bk] = b1.y;
        Bs[0][(bn4+66)*PA + bk] = b1.z; Bs[0][(bn4+67)*PA + bk] = b1.w;
    }
    __syncthreads();

    int buf = 0;
    for (int kt = 0; kt < KT; kt++) {
        const bool next = (kt + 1 < KT);
        float4 a0, a1, b0, b1;
        if (next) {
            a0 = *(const float4*)(Ag0 + (kt+1)*16);
            a1 = *(const float4*)(Ag1 + (kt+1)*16);
            b0 = *(const float4*)(Bg0 + (size_t)(kt+1)*16*N);
            b1 = *(const float4*)(Bg1 + (size_t)(kt+1)*16*N);
        }

        const uint32_t bo = buf ? (uint32_t)(BUFF*4) : 0u;
#pragma unroll
        for (int kh = 0; kh < 2; kh++) {
            uint32_t af[2][4], bf[4][4];
            ldsm4(af[0], aAddr[0] + bo + kh*32);
            ldsm4(af[1], aAddr[1] + bo + kh*32);
#pragma unroll
            for (int p = 0; p < 4; p++) ldsm4(bf[p], bAddr[p] + bo + kh*32);
#pragma unroll
            for (int ni = 0; ni < 8; ni++) {
                const uint32_t bb0 = bf[ni>>1][ni&1];
                const uint32_t bb1 = bf[ni>>1][2 + (ni&1)];
                mma_tf32(acc[0][ni], af[0], bb0, bb1);
                mma_tf32(acc[1][ni], af[1], bb0, bb1);
            }
        }

        if (next) {
            const int nb = buf ^ 1;
            a0.x=tf32r(a0.x); a0.y=tf32r(a0.y); a0.z=tf32r(a0.z); a0.w=tf32r(a0.w);
            a1.x=tf32r(a1.x); a1.y=tf32r(a1.y); a1.z=tf32r(a1.z); a1.w=tf32r(a1.w);
            b0.x=tf32r(b0.x); b0.y=tf32r(b0.y); b0.z=tf32r(b0.z); b0.w=tf32r(b0.w);
            b1.x=tf32r(b1.x); b1.y=tf32r(b1.y); b1.z=tf32r(b1.z); b1.w=tf32r(b1.w);
            *(float4*)&As[nb][sa]         = a0;
            *(float4*)&As[nb][sa + 64*PA] = a1;
            Bs[nb][(bn4+0)*PA + bk] = b0.x; Bs[nb][(bn4+1)*PA + bk] = b0.y;
            Bs[nb][(bn4+2)*PA + bk] = b0.z; Bs[nb][(bn4+3)*PA + bk] = b0.w;
            Bs[nb][(bn4+64)*PA + bk] = b1.x; Bs[nb][(bn4+65)*PA + bk] = b1.y;
            Bs[nb][(bn4+66)*PA + bk] = b1.z; Bs[nb][(bn4+67)*PA + bk] = b1.w;
            __syncthreads();
            buf = nb;
        }
    }

    const int r0 = (by*128) + wm*32 + (lane >> 2);
    const int c0 = (bx*128) + wn*64 + ((lane & 3) << 1);
#pragma unroll
    for (int mi = 0; mi < 2; mi++) {
        const int gr = r0 + mi*16;
#pragma unroll
        for (int ni = 0; ni < 8; ni++) {
            const int gc = c0 + ni*8;
            const float2 bia = *(const float2*)(bias + gc);
            float2 v0 = make_float2(acc[mi][ni][0] + bia.x, acc[mi][ni][1] + bia.y);
            float2 v1 = make_float2(acc[mi][ni][2] + bia.x, acc[mi][ni][3] + bia.y);
            if (EPI == 1) {
                v0.x = fmaxf(v0.x, 0.f); v0.y = fmaxf(v0.y, 0.f);
                v1.x = fmaxf(v1.x, 0.f); v1.y = fmaxf(v1.y, 0.f);
            }
            if (EPI == 2) {
                const float2 r_0 = *(const float2*)(res + (size_t)gr*N + gc);
                const float2 r_1 = *(const float2*)(res + (size_t)(gr+8)*N + gc);
                v0.x += r_0.x; v0.y += r_0.y;
                v1.x += r_1.x; v1.y += r_1.y;
            }
            if (EPI == 3) {
                // transposed store: Ct[col][row], row stride = ROWS
                C[(size_t)gc*ROWS + gr]           = v0.x;
                C[(size_t)(gc+1)*ROWS + gr]       = v0.y;
                C[(size_t)gc*ROWS + gr + 8]       = v1.x;
                C[(size_t)(gc+1)*ROWS + gr + 8]   = v1.y;
            } else {
                *(float2*)(C + (size_t)gr*N + gc)     = v0;
                *(float2*)(C + (size_t)(gr+8)*N + gc) = v1;
            }
        }
    }
}

// ---------------------------------------------------------------------------
// Tensor-core flash attention v2 (tf32 mma, fp32 softmax).
// Block = 128 q rows of one (batch, head); 8 warps, warp = 16 q rows.
// K-tile = 128 keys, double-buffered via cp.async. V consumed from V^T
// (g_v holds Vt[col][token]) so PV's B operand comes via ldmatrix.
// smem (floats): sP 128x132 | sK[2] 128x68 | sVt[2] 64x132
// ---------------------------------------------------------------------------
#define AT_PP 132
#define AT_PK 68
#define AT_KTILE_F (128*AT_PK)     // 8704 floats per K buffer
#define AT_VTILE_F (64*AT_PP)      // 8448 floats per V buffer
#define AT_OFF_K   (128*AT_PP)     // 16896
#define AT_OFF_V   (AT_OFF_K + 2*AT_KTILE_F)
#define AT_SMEM_BYTES ((AT_OFF_V + 2*AT_VTILE_F)*4)   // 204800 B

__global__ __launch_bounds__(256, 1)
void attn_tc2(const float* __restrict__ Q, const float* __restrict__ K,
              const float* __restrict__ Vt, float* __restrict__ O)
{
    extern __shared__ float sm[];
    float* sP = sm;

    const int n = blockIdx.z, h = blockIdx.y;
    const int tid = threadIdx.x, lane = tid & 31, w = tid >> 5;
    const size_t base  = ((size_t)n*SEQ)*DM + h*EHEAD;
    const size_t vbase = ((size_t)h*EHEAD)*ROWS + (size_t)n*SEQ;
    const int q0 = blockIdx.x * 128;

    const uint32_t sKu = smem_u32(sm + AT_OFF_K);
    const uint32_t sVu = smem_u32(sm + AT_OFF_V);

    // ---- load Q tile (scaled by 1/8, tf32-rna) into sP ----
#pragma unroll
    for (int i = 0; i < 8; i++) {
        int idx = i*256 + tid;
        int r = idx >> 4, c4 = (idx & 15) << 2;
        float4 t = *(const float4*)(Q + base + (size_t)(q0 + r)*DM + c4);
        t.x = tf32r(t.x*0.125f); t.y = tf32r(t.y*0.125f);
        t.z = tf32r(t.z*0.125f); t.w = tf32r(t.w*0.125f);
        *(float4*)&sP[r*AT_PP + c4] = t;
    }

    // ---- prologue: async-load tile 0 (K + V^T) into buffer 0 ----
#pragma unroll
    for (int j = 0; j < 8; j++) {
        int idx = j*256 + tid;
        int r = idx >> 4, c4 = (idx & 15) << 2;
        cpa16(sKu + (uint32_t)((r*AT_PK + c4) << 2),
              K + base + (size_t)r*DM + c4);
    }
#pragma unroll
    for (int j = 0; j < 8; j++) {
        int idx = j*256 + tid;
        int r = idx >> 5, c4 = (idx & 31) << 2;
        cpa16(sVu + (uint32_t)((r*AT_PP + c4) << 2),
              Vt + vbase + (size_t)r*ROWS + c4);
    }
    cpa_commit();

    __syncthreads();   // Q tile visible to all warps

    // ---- hoist Q fragments (warp-private rows) ----
    const int lr = lane & 7, lq = (lane >> 3) & 1, lh = lane >> 4;
    const uint32_t aBase = smem_u32(sP) + (((w*16 + lr + lq*8)*AT_PP + lh*4) << 2);
    uint32_t aQ[8][4];
#pragma unroll
    for (int ks = 0; ks < 8; ks++) ldsm4(aQ[ks], aBase + ks*32);

    uint32_t bK[8], bV[4];
#pragma unroll
    for (int p = 0; p < 8; p++)
        bK[p] = sKu + (((p*16 + lr + lq*8)*AT_PK + lh*4) << 2);
#pragma unroll
    for (int p = 0; p < 4; p++)
        bV[p] = sVu + (((p*16 + lr + lq*8)*AT_PP + lh*4) << 2);

    float accO[8][4];
#pragma unroll
    for (int ni = 0; ni < 8; ni++)
#pragma unroll
        for (int c = 0; c < 4; c++) accO[ni][c] = 0.f;
    float m0 = -1e30f, m1 = -1e30f, l0 = 0.f, l1 = 0.f;

    const int rA = w*16 + (lane >> 2);
    float* pr0 = &sP[rA*AT_PP + 2*(lane & 3)];
    float* pr1 = pr0 + 8*AT_PP;

    for (int kt = 0; kt < SEQ/128; kt++) {
        const int buf = kt & 1;
        // issue next tile into buf^1 (previous compute on buf^1 finished at
        // the __syncthreads() that ended iteration kt-1)
        if (kt + 1 < SEQ/128) {
            const int nb = buf ^ 1;
            const uint32_t ko = (uint32_t)(nb * AT_KTILE_F) << 2;
            const uint32_t vo = (uint32_t)(nb * AT_VTILE_F) << 2;
#pragma unroll
            for (int j = 0; j < 8; j++) {
                int idx = j*256 + tid;
                int r = idx >> 4, c4 = (idx & 15) << 2;
                cpa16(sKu + ko + (uint32_t)((r*AT_PK + c4) << 2),
                      K + base + (size_t)((kt+1)*128 + r)*DM + c4);
            }
#pragma unroll
            for (int j = 0; j < 8; j++) {
                int idx = j*256 + tid;
                int r = idx >> 5, c4 = (idx & 31) << 2;
                cpa16(sVu + vo + (uint32_t)((r*AT_PP + c4) << 2),
                      Vt + vbase + (size_t)r*ROWS + (kt+1)*128 + c4);
            }
            cpa_commit();
            cpa_wait<1>();
        } else {
            cpa_wait<0>();
        }
        __syncthreads();

        const uint32_t ko = (uint32_t)(buf * AT_KTILE_F) << 2;
        const uint32_t vo = (uint32_t)(buf * AT_VTILE_F) << 2;

        // ---- S = Q K^T ----
        float accS[16][4];
#pragma unroll
        for (int t = 0; t < 16; t++)
#pragma unroll
            for (int c = 0; c < 4; c++) accS[t][c] = 0.f;
#pragma unroll
        for (int ks = 0; ks < 8; ks++) {
#pragma unroll
            for (int p = 0; p < 8; p++) {
                uint32_t bf[4];
                ldsm4(bf, bK[p] + ko + ks*32);
                mma_tf32(accS[2*p],   aQ[ks], bf[0], bf[2]);
                mma_tf32(accS[2*p+1], aQ[ks], bf[1], bf[3]);
            }
        }

        // ---- online softmax ----
        float rmax0 = -1e30f, rmax1 = -1e30f;
#pragma unroll
        for (int t = 0; t < 16; t++) {
            rmax0 = fmaxf(rmax0, fmaxf(accS[t][0], accS[t][1]));
            rmax1 = fmaxf(rmax1, fmaxf(accS[t][2], accS[t][3]));
        }
        rmax0 = fmaxf(rmax0, __shfl_xor_sync(0xffffffffu, rmax0, 1));
        rmax0 = fmaxf(rmax0, __shfl_xor_sync(0xffffffffu, rmax0, 2));
        rmax1 = fmaxf(rmax1, __shfl_xor_sync(0xffffffffu, rmax1, 1));
        rmax1 = fmaxf(rmax1, __shfl_xor_sync(0xffffffffu, rmax1, 2));
        const float mn0 = fmaxf(m0, rmax0), mn1 = fmaxf(m1, rmax1);
        const float cr0 = __expf(m0 - mn0), cr1 = __expf(m1 - mn1);
        m0 = mn0; m1 = mn1;
        l0 *= cr0; l1 *= cr1;
#pragma unroll
        for (int ni = 0; ni < 8; ni++) {
            accO[ni][0] *= cr0; accO[ni][1] *= cr0;
            accO[ni][2] *= cr1; accO[ni][3] *= cr1;
        }
#pragma unroll
        for (int t = 0; t < 16; t++) {
            float p0 = __expf(accS[t][0] - m0), p1 = __expf(accS[t][1] - m0);
            float p2 = __expf(accS[t][2] - m1), p3 = __expf(accS[t][3] - m1);
            l0 += p0 + p1; l1 += p2 + p3;
            *(float2*)(pr0 + t*8) = make_float2(tf32r(p0), tf32r(p1));
            *(float2*)(pr1 + t*8) = make_float2(tf32r(p2), tf32r(p3));
        }
        __syncwarp();

        // ---- O += P V  (B operand = V^T rows via ldmatrix) ----
#pragma unroll
        for (int ks = 0; ks < 16; ks++) {
            uint32_t aP[4];
            ldsm4(aP, aBase + ks*32);
#pragma unroll
            for (int p = 0; p < 4; p++) {
                uint32_t bf[4];
                ldsm4(bf, bV[p] + vo + ks*32);
                mma_tf32(accO[2*p],   aP, bf[0], bf[2]);
                mma_tf32(accO[2*p+1], aP, bf[1], bf[3]);
            }
        }
        __syncthreads();   // all warps done with buf before it is refilled
    }

    // ---- epilogue ----
    l0 += __shfl_xor_sync(0xffffffffu, l0, 1);
    l0 += __shfl_xor_sync(0xffffffffu, l0, 2);
    l1 += __shfl_xor_sync(0xffffffffu, l1, 1);
    l1 += __shfl_xor_sync(0xffffffffu, l1, 2);
    const float inv0 = 1.f / l0, inv1 = 1.f / l1;
    const int gr0 = q0 + w*16 + (lane >> 2);
    const int cc = 2*(lane & 3);
#pragma unroll
    for (int ni = 0; ni < 8; ni++) {
        float2 v0 = make_float2(accO[ni][0]*inv0, accO[ni][1]*inv0);
        float2 v1 = make_float2(accO[ni][2]*inv1, accO[ni][3]*inv1);
        *(float2*)(O + base + (size_t)gr0*DM + ni*8 + cc)     = v0;
        *(float2*)(O + base + (size_t)(gr0+8)*DM + ni*8 + cc) = v1;
    }
}

// ---------------------------------------------------------------------------
// LayerNorm over last dim (512). One block (128 threads) per row.
// ---------------------------------------------------------------------------
__global__ __launch_bounds__(128)
void ln_kernel(const float* __restrict__ in, const float* __restrict__ gamma,
               const float* __restrict__ beta, float* __restrict__ out)
{
    const int row = blockIdx.x, tid = threadIdx.x;
    const float4 v = ((const float4*)(in + (size_t)row*DM))[tid];
    float s  = v.x + v.y + v.z + v.w;
    float sq = v.x*v.x + v.y*v.y + v.z*v.z + v.w*v.w;
#pragma unroll
    for (int o = 16; o; o >>= 1) {
        s  += __shfl_down_sync(0xffffffffu, s,  o);
        sq += __shfl_down_sync(0xffffffffu, sq, o);
    }
    __shared__ float ss[4], sqs[4];
    const int w = tid >> 5, lane = tid & 31;
    if (lane == 0) { ss[w] = s; sqs[w] = sq; }
    __syncthreads();
    s  = ss[0] + ss[1] + ss[2] + ss[3];
    sq = sqs[0] + sqs[1] + sqs[2] + sqs[3];

    const float mean = s * (1.f / DM);
    const float var  = sq * (1.f / DM) - mean * mean;
    const float inv  = rsqrtf(var + LN_EPS);

    const float4 g4 = ((const float4*)gamma)[tid];
    const float4 b4 = ((const float4*)beta)[tid];
    float4 o4;
    o4.x = (v.x - mean)*inv*g4.x + b4.x;
    o4.y = (v.y - mean)*inv*g4.y + b4.y;
    o4.z = (v.z - mean)*inv*g4.z + b4.z;
    o4.w = (v.w - mean)*inv*g4.w + b4.w;
    ((float4*)(out + (size_t)row*DM))[tid] = o4;
}

// ---------------------------------------------------------------------------
extern "C" void kernel_launch(void* const* d_in, const int* in_sizes, int n_in,
                              void* d_out, int out_size)
{
    const float* x   = (const float*)d_in[0];
    const float* Wq  = (const float*)d_in[1];
    const float* bq  = (const float*)d_in[2];
    const float* Wk  = (const float*)d_in[3];
    const float* bk  = (const float*)d_in[4];
    const float* Wv  = (const float*)d_in[5];
    const float* bv  = (const float*)d_in[6];
    const float* Wo  = (const float*)d_in[7];
    const float* bo  = (const float*)d_in[8];
    const float* W1  = (const float*)d_in[9];
    const float* b1  = (const float*)d_in[10];
    const float* W2  = (const float*)d_in[11];
    const float* b2  = (const float*)d_in[12];
    const float* g1  = (const float*)d_in[13];
    const float* be1 = (const float*)d_in[14];
    const float* g2  = (const float*)d_in[15];
    const float* be2 = (const float*)d_in[16];

    float *q, *k, *v, *o, *hb, *h1, *h2, *xb, *ff;
    cudaGetSymbolAddress((void**)&q,  g_q);
    cudaGetSymbolAddress((void**)&k,  g_k);
    cudaGetSymbolAddress((void**)&v,  g_v);
    cudaGetSymbolAddress((void**)&o,  g_o);
    cudaGetSymbolAddress((void**)&hb, g_h);
    cudaGetSymbolAddress((void**)&h1, g_h1);
    cudaGetSymbolAddress((void**)&h2, g_h2);
    cudaGetSymbolAddress((void**)&xb, g_x);
    cudaGetSymbolAddress((void**)&ff, g_ff);

    cudaFuncSetAttribute(attn_tc2, cudaFuncAttributeMaxDynamicSharedMemorySize,
                         AT_SMEM_BYTES);

    const dim3 gProj(DM / 128, ROWS / 128);    // (4, 64)
    const dim3 gFF1 (DFF / 128, ROWS / 128);   // (16, 64)
    const dim3 gAttn(SEQ / 128, NHEAD, NB);    // (8, 8, 8)

    const float* hin = x;
    for (int l = 0; l < NLAYERS; l++) {
        const float* wq = Wq + (size_t)l*DM*DM;
        const float* wk = Wk + (size_t)l*DM*DM;
        const float* wv = Wv + (size_t)l*DM*DM;
        const float* wo = Wo + (size_t)l*DM*DM;
        const float* w1 = W1 + (size_t)l*DM*DFF;
        const float* w2 = W2 + (size_t)l*DFF*DM;

        gemm_tf32<0><<<gProj, 256>>>(hin, wq, bq + l*DM, nullptr, q, ROWS, DM, DM);
        gemm_tf32<0><<<gProj, 256>>>(hin, wk, bk + l*DM, nullptr, k, ROWS, DM, DM);
        gemm_tf32<3><<<gProj, 256>>>(hin, wv, bv + l*DM, nullptr, v, ROWS, DM, DM);

        attn_tc2<<<gAttn, 256, AT_SMEM_BYTES>>>(q, k, v, o);

        gemm_tf32<2><<<gProj, 256>>>(o, wo, bo + l*DM, hin, hb, ROWS, DM, DM);
        ln_kernel<<<ROWS, 128>>>(hb, g1 + l*DM, be1 + l*DM, h1);

        gemm_tf32<1><<<gFF1, 256>>>(h1, w1, b1 + l*DFF, nullptr, ff, ROWS, DFF, DM);
        gemm_tf32<2><<<gProj, 256>>>(ff, w2, b2 + l*DM, h1, h2, ROWS, DM, DFF);

        float* lnout = (l == NLAYERS - 1) ? (float*)d_out : xb;
        ln_kernel<<<ROWS, 128>>>(h2, g2 + l*DM, be2 + l*DM, lnout);
        hin = xb;
    }
}

// round 6
// speedup vs baseline: 4.1266x; 1.4913x over previous
#include <cuda_runtime.h>
#include <cuda_fp16.h>
#include <cstdint>
#include <cstddef>

// Problem constants
#define DM      512
#define DFF     2048
#define NB      8
#define SEQ     1024
#define NHEAD   8
#define EHEAD   64
#define ROWS    (NB*SEQ)     // 8192
#define NLAYERS 4
#define LN_EPS  1e-5f

// ---------------- scratch (device globals; no allocations allowed) --------
__device__ __half g_qh [ROWS*DM];   // Q (pre-scaled by 1/8), fp16
__device__ __half g_kh [ROWS*DM];   // K, fp16
__device__ __half g_vth[DM*ROWS];   // V^T [col][token], fp16
__device__ float  g_o [ROWS*DM];
__device__ float  g_h [ROWS*DM];
__device__ float  g_h1[ROWS*DM];
__device__ float  g_h2[ROWS*DM];
__device__ float  g_x [ROWS*DM];
__device__ float  g_ff[ROWS*DFF];

// ---------------- helpers ---------------------------------------------------
__device__ __forceinline__ uint32_t f2h2(float a, float b) {
    __half2 h = __floats2half2_rn(a, b);
    return *(uint32_t*)&h;
}
__device__ __forceinline__ void ldsm4(uint32_t* r, uint32_t addr) {
    asm volatile("ldmatrix.sync.aligned.m8n8.x4.shared.b16 {%0,%1,%2,%3}, [%4];\n"
                 : "=r"(r[0]), "=r"(r[1]), "=r"(r[2]), "=r"(r[3]) : "r"(addr));
}
__device__ __forceinline__ void ldsm4t(uint32_t* r, uint32_t addr) {
    asm volatile("ldmatrix.sync.aligned.m8n8.x4.trans.shared.b16 {%0,%1,%2,%3}, [%4];\n"
                 : "=r"(r[0]), "=r"(r[1]), "=r"(r[2]), "=r"(r[3]) : "r"(addr));
}
__device__ __forceinline__ void mma_f16(float* d, const uint32_t* a,
                                        uint32_t b0, uint32_t b1) {
    asm volatile(
        "mma.sync.aligned.m16n8k16.row.col.f32.f16.f16.f32 "
        "{%0,%1,%2,%3},{%4,%5,%6,%7},{%8,%9},{%0,%1,%2,%3};\n"
        : "+f"(d[0]), "+f"(d[1]), "+f"(d[2]), "+f"(d[3])
        : "r"(a[0]), "r"(a[1]), "r"(a[2]), "r"(a[3]), "r"(b0), "r"(b1));
}
__device__ __forceinline__ uint32_t smem_u32(const void* p) {
    return (uint32_t)__cvta_generic_to_shared(p);
}
__device__ __forceinline__ void cpa16(uint32_t dst, const void* src) {
    asm volatile("cp.async.ca.shared.global [%0], [%1], 16;\n"
                 :: "r"(dst), "l"(src) : "memory");
}
__device__ __forceinline__ void cpa_commit() {
    asm volatile("cp.async.commit_group;\n" ::: "memory");
}
template<int N>
__device__ __forceinline__ void cpa_wait() {
    asm volatile("cp.async.wait_group %0;\n" :: "n"(N) : "memory");
}

// ---------------------------------------------------------------------------
// FP16 tensor-core GEMM:  C = A[M,K] @ B[K,N] + bias
//  EPI 0: bias->f32  1: bias+relu->f32  2: bias+residual->f32
//  EPI 4: bias, *cscale -> half        5: bias -> half, transposed (Ct[N][ROWS])
// BM=BN=128, BK=32, 256 thr = 8 warps (4m x 2n), warp tile 32x64, m16n8k16.
// A smem [m][k] pitch 40 halfs; B smem [k][n] pitch 136 halfs (ldsm.x4.trans).
// ---------------------------------------------------------------------------
#define GPA 40
#define GPB 136
#define ABUF (128*GPA)   // halfs per A buffer
#define BBUF (32*GPB)    // halfs per B buffer

template<int EPI>
__global__ __launch_bounds__(256, 2)
void gemm_f16(const float* __restrict__ A, const float* __restrict__ B,
              const float* __restrict__ bias, const float* __restrict__ res,
              float* __restrict__ C, int M, int N, int K, float cscale)
{
    __shared__ alignas(16) __half As[2][ABUF];
    __shared__ alignas(16) __half Bs[2][BBUF];

    const int tid = threadIdx.x;
    const int lane = tid & 31, wid = tid >> 5;
    const int wm = wid & 3, wn = wid >> 2;
    const int bx = blockIdx.x, by = blockIdx.y;

    // global load mapping
    const int arow = tid >> 1, aks = (tid & 1) * 16;   // A: 128 rows x 32 k
    const int brow = tid >> 3, bns = (tid & 7) * 16;   // B: 32 k-rows x 128 n
    const float* Ag = A + (size_t)(by*128 + arow)*K + aks;
    const float* Bg = B + (size_t)brow*N + bx*128 + bns;

    // ldsm addresses (buf 0)
    const uint32_t sAu = smem_u32(&As[0][0]);
    const uint32_t sBu = smem_u32(&Bs[0][0]);
    uint32_t aAd[2], bAd[4];
#pragma unroll
    for (int mi = 0; mi < 2; mi++)
        aAd[mi] = sAu + (((wm*32 + mi*16 + (lane & 15))*GPA + (lane >> 4)*8) << 1);
#pragma unroll
    for (int nt = 0; nt < 4; nt++)
        bAd[nt] = sBu + ((((lane & 7) + ((lane >> 3) & 1)*8)*GPB
                          + wn*64 + nt*16 + (lane >> 4)*8) << 1);

    float acc[2][8][4];
#pragma unroll
    for (int mi = 0; mi < 2; mi++)
#pragma unroll
        for (int ni = 0; ni < 8; ni++)
#pragma unroll
            for (int c = 0; c < 4; c++) acc[mi][ni][c] = 0.f;

    const int KT = K >> 5;

    // prologue: fill buffer 0
    {
        uint32_t ah[8], bh[8];
#pragma unroll
        for (int j = 0; j < 4; j++) {
            float4 t = *(const float4*)(Ag + j*4);
            ah[2*j]   = f2h2(t.x, t.y);
            ah[2*j+1] = f2h2(t.z, t.w);
            float4 u = *(const float4*)(Bg + j*4);
            bh[2*j]   = f2h2(u.x, u.y);
            bh[2*j+1] = f2h2(u.z, u.w);
        }
        *(uint4*)&As[0][arow*GPA + aks]     = *(uint4*)&ah[0];
        *(uint4*)&As[0][arow*GPA + aks + 8] = *(uint4*)&ah[4];
        *(uint4*)&Bs[0][brow*GPB + bns]     = *(uint4*)&bh[0];
        *(uint4*)&Bs[0][brow*GPB + bns + 8] = *(uint4*)&bh[4];
    }
    __syncthreads();

    int buf = 0;
    for (int kt = 0; kt < KT; kt++) {
        const bool next = (kt + 1 < KT);
        uint32_t ah[8], bh[8];
        if (next) {
#pragma unroll
            for (int j = 0; j < 4; j++) {
                float4 t = *(const float4*)(Ag + (kt+1)*32 + j*4);
                ah[2*j]   = f2h2(t.x, t.y);
                ah[2*j+1] = f2h2(t.z, t.w);
                float4 u = *(const float4*)(Bg + (size_t)(kt+1)*32*N + j*4);
                bh[2*j]   = f2h2(u.x, u.y);
                bh[2*j+1] = f2h2(u.z, u.w);
            }
        }

        const uint32_t boA = buf ? (uint32_t)(ABUF*2) : 0u;
        const uint32_t boB = buf ? (uint32_t)(BBUF*2) : 0u;
#pragma unroll
        for (int kh = 0; kh < 2; kh++) {
            uint32_t af[2][4], bf[4][4];
            ldsm4(af[0], aAd[0] + boA + kh*32);
            ldsm4(af[1], aAd[1] + boA + kh*32);
#pragma unroll
            for (int nt = 0; nt < 4; nt++)
                ldsm4t(bf[nt], bAd[nt] + boB + kh*16*GPB*2);
#pragma unroll
            for (int nt = 0; nt < 4; nt++) {
#pragma unroll
                for (int mi = 0; mi < 2; mi++) {
                    mma_f16(acc[mi][2*nt],   af[mi], bf[nt][0], bf[nt][1]);
                    mma_f16(acc[mi][2*nt+1], af[mi], bf[nt][2], bf[nt][3]);
                }
            }
        }

        if (next) {
            const int nb = buf ^ 1;
            *(uint4*)&As[nb][arow*GPA + aks]     = *(uint4*)&ah[0];
            *(uint4*)&As[nb][arow*GPA + aks + 8] = *(uint4*)&ah[4];
            *(uint4*)&Bs[nb][brow*GPB + bns]     = *(uint4*)&bh[0];
            *(uint4*)&Bs[nb][brow*GPB + bns + 8] = *(uint4*)&bh[4];
            __syncthreads();
            buf = nb;
        }
    }

    // ---- epilogue ----
    const int r0 = (by*128) + wm*32 + (lane >> 2);
#pragma unroll
    for (int mi = 0; mi < 2; mi++) {
        const int gr = r0 + mi*16;
#pragma unroll
        for (int ni = 0; ni < 8; ni++) {
            const int gc = (bx*128) + wn*64 + (ni >> 1)*16 + (ni & 1)*8
                         + ((lane & 3) << 1);
            const float2 bia = *(const float2*)(bias + gc);
            float2 v0 = make_float2(acc[mi][ni][0] + bia.x, acc[mi][ni][1] + bia.y);
            float2 v1 = make_float2(acc[mi][ni][2] + bia.x, acc[mi][ni][3] + bia.y);
            if (EPI == 1) {
                v0.x = fmaxf(v0.x, 0.f); v0.y = fmaxf(v0.y, 0.f);
                v1.x = fmaxf(v1.x, 0.f); v1.y = fmaxf(v1.y, 0.f);
            }
            if (EPI == 2) {
                const float2 r_0 = *(const float2*)(res + (size_t)gr*N + gc);
                const float2 r_1 = *(const float2*)(res + (size_t)(gr+8)*N + gc);
                v0.x += r_0.x; v0.y += r_0.y;
                v1.x += r_1.x; v1.y += r_1.y;
            }
            if (EPI == 4) {
                __half* Ch = (__half*)C;
                __half2 h0 = __floats2half2_rn(v0.x*cscale, v0.y*cscale);
                __half2 h1 = __floats2half2_rn(v1.x*cscale, v1.y*cscale);
                *(__half2*)(Ch + (size_t)gr*N + gc)     = h0;
                *(__half2*)(Ch + (size_t)(gr+8)*N + gc) = h1;
            } else if (EPI == 5) {
                __half* Ch = (__half*)C;
                Ch[(size_t)gc*ROWS + gr]         = __float2half_rn(v0.x);
                Ch[(size_t)(gc+1)*ROWS + gr]     = __float2half_rn(v0.y);
                Ch[(size_t)gc*ROWS + gr + 8]     = __float2half_rn(v1.x);
                Ch[(size_t)(gc+1)*ROWS + gr + 8] = __float2half_rn(v1.y);
            } else {
                *(float2*)(C + (size_t)gr*N + gc)     = v0;
                *(float2*)(C + (size_t)(gr+8)*N + gc) = v1;
            }
        }
    }
}

// ---------------------------------------------------------------------------
// FP16 tensor-core flash attention (fp32 softmax/accum).
// Block = 128 q rows of one (batch, head); 8 warps, warp = 16 q rows.
// K-tile = 128 keys double-buffered via cp.async. Inputs are fp16:
//   Qh (pre-scaled 1/8) [ROWS][DM], Kh [ROWS][DM], Vth [DM][ROWS].
// smem halfs: sA(Q then P) 128x136 | sK[2] 128x72 | sVt[2] 64x136
// ---------------------------------------------------------------------------
#define AT_PA 136
#define AT_PK 72
#define AT_AH (128*AT_PA)            // 17408 halfs
#define AT_KH (128*AT_PK)            // 9216 halfs per K buffer
#define AT_VH (64*AT_PA)             // 8704 halfs per V buffer
#define AT_OFF_K AT_AH
#define AT_OFF_V (AT_OFF_K + 2*AT_KH)
#define AT_SMEM_BYTES ((AT_OFF_V + 2*AT_VH)*2)   // 106496 B

__global__ __launch_bounds__(256, 1)
void attn_f16(const __half* __restrict__ Qh, const __half* __restrict__ Kh,
              const __half* __restrict__ Vth, float* __restrict__ O)
{
    extern __shared__ __half smh[];
    __half* sA = smh;

    const int n = blockIdx.z, h = blockIdx.y;
    const int tid = threadIdx.x, lane = tid & 31, w = tid >> 5;
    const size_t base  = ((size_t)n*SEQ)*DM + h*EHEAD;      // Q/K row base
    const size_t vbase = ((size_t)h*EHEAD)*ROWS + (size_t)n*SEQ;
    const int q0 = blockIdx.x * 128;

    const uint32_t sAu = smem_u32(sA);
    const uint32_t sKu = smem_u32(smh + AT_OFF_K);
    const uint32_t sVu = smem_u32(smh + AT_OFF_V);

    // ---- async-load Q tile (group 0) ----
#pragma unroll
    for (int j = 0; j < 4; j++) {
        int idx = j*256 + tid;                  // 0..1023
        int r = idx >> 3, c8 = (idx & 7) << 3;  // 128 rows x 64 halfs
        cpa16(sAu + (uint32_t)((r*AT_PA + c8) << 1),
              Qh + base + (size_t)(q0 + r)*DM + c8);
    }
    cpa_commit();
    // ---- async-load K+V tile 0 (group 1) ----
#pragma unroll
    for (int j = 0; j < 4; j++) {
        int idx = j*256 + tid;
        int r = idx >> 3, c8 = (idx & 7) << 3;
        cpa16(sKu + (uint32_t)((r*AT_PK + c8) << 1),
              Kh + base + (size_t)r*DM + c8);
    }
#pragma unroll
    for (int j = 0; j < 4; j++) {
        int idx = j*256 + tid;
        int r = idx >> 4, c8 = (idx & 15) << 3;  // 64 rows x 128 halfs
        cpa16(sVu + (uint32_t)((r*AT_PA + c8) << 1),
              Vth + vbase + (size_t)r*ROWS + c8);
    }
    cpa_commit();

    cpa_wait<1>();       // Q ready
    __syncthreads();

    // ---- hoist Q fragments ----
    const uint32_t aBase = sAu + (((w*16 + (lane & 15))*AT_PA + (lane >> 4)*8) << 1);
    uint32_t aQ[4][4];
#pragma unroll
    for (int ks = 0; ks < 4; ks++) ldsm4(aQ[ks], aBase + ks*32);

    uint32_t bK[8], bV[4];
#pragma unroll
    for (int p = 0; p < 8; p++)
        bK[p] = sKu + (((p*16 + (lane & 7) + ((lane >> 3) & 1)*8)*AT_PK
                        + (lane >> 4)*8) << 1);
#pragma unroll
    for (int p = 0; p < 4; p++)
        bV[p] = sVu + (((p*16 + (lane & 7) + ((lane >> 3) & 1)*8)*AT_PA
                        + (lane >> 4)*8) << 1);

    float accO[8][4];
#pragma unroll
    for (int ni = 0; ni < 8; ni++)
#pragma unroll
        for (int c = 0; c < 4; c++) accO[ni][c] = 0.f;
    float m0 = -1e30f, m1 = -1e30f, l0 = 0.f, l1 = 0.f;

    const int rA = w*16 + (lane >> 2);
    __half* pr0 = &sA[rA*AT_PA + 2*(lane & 3)];
    __half* pr1 = pr0 + 8*AT_PA;

    for (int kt = 0; kt < SEQ/128; kt++) {
        const int buf = kt & 1;
        if (kt + 1 < SEQ/128) {
            const int nb = buf ^ 1;
            const uint32_t ko = (uint32_t)(nb * AT_KH) << 1;
            const uint32_t vo = (uint32_t)(nb * AT_VH) << 1;
#pragma unroll
            for (int j = 0; j < 4; j++) {
                int idx = j*256 + tid;
                int r = idx >> 3, c8 = (idx & 7) << 3;
                cpa16(sKu + ko + (uint32_t)((r*AT_PK + c8) << 1),
                      Kh + base + (size_t)((kt+1)*128 + r)*DM + c8);
            }
#pragma unroll
            for (int j = 0; j < 4; j++) {
                int idx = j*256 + tid;
                int r = idx >> 4, c8 = (idx & 15) << 3;
                cpa16(sVu + vo + (uint32_t)((r*AT_PA + c8) << 1),
                      Vth + vbase + (size_t)r*ROWS + (kt+1)*128 + c8);
            }
            cpa_commit();
            cpa_wait<1>();
        } else {
            cpa_wait<0>();
        }
        __syncthreads();

        const uint32_t ko = (uint32_t)(buf * AT_KH) << 1;
        const uint32_t vo = (uint32_t)(buf * AT_VH) << 1;

        // ---- S = Q K^T  (64 mma) ----
        float accS[16][4];
#pragma unroll
        for (int t = 0; t < 16; t++)
#pragma unroll
            for (int c = 0; c < 4; c++) accS[t][c] = 0.f;
#pragma unroll
        for (int ks = 0; ks < 4; ks++) {
#pragma unroll
            for (int p = 0; p < 8; p++) {
                uint32_t bf[4];
                ldsm4(bf, bK[p] + ko + ks*32);
                mma_f16(accS[2*p],   aQ[ks], bf[0], bf[2]);
                mma_f16(accS[2*p+1], aQ[ks], bf[1], bf[3]);
            }
        }

        // ---- online softmax (fp32) ----
        float rmax0 = -1e30f, rmax1 = -1e30f;
#pragma unroll
        for (int t = 0; t < 16; t++) {
            rmax0 = fmaxf(rmax0, fmaxf(accS[t][0], accS[t][1]));
            rmax1 = fmaxf(rmax1, fmaxf(accS[t][2], accS[t][3]));
        }
        rmax0 = fmaxf(rmax0, __shfl_xor_sync(0xffffffffu, rmax0, 1));
        rmax0 = fmaxf(rmax0, __shfl_xor_sync(0xffffffffu, rmax0, 2));
        rmax1 = fmaxf(rmax1, __shfl_xor_sync(0xffffffffu, rmax1, 1));
        rmax1 = fmaxf(rmax1, __shfl_xor_sync(0xffffffffu, rmax1, 2));
        const float mn0 = fmaxf(m0, rmax0), mn1 = fmaxf(m1, rmax1);
        const float cr0 = __expf(m0 - mn0), cr1 = __expf(m1 - mn1);
        m0 = mn0; m1 = mn1;
        l0 *= cr0; l1 *= cr1;
#pragma unroll
        for (int ni = 0; ni < 8; ni++) {
            accO[ni][0] *= cr0; accO[ni][1] *= cr0;
            accO[ni][2] *= cr1; accO[ni][3] *= cr1;
        }
#pragma unroll
        for (int t = 0; t < 16; t++) {
            float p0 = __expf(accS[t][0] - m0), p1 = __expf(accS[t][1] - m0);
            float p2 = __expf(accS[t][2] - m1), p3 = __expf(accS[t][3] - m1);
            l0 += p0 + p1; l1 += p2 + p3;
            *(__half2*)(pr0 + t*8) = __floats2half2_rn(p0, p1);
            *(__half2*)(pr1 + t*8) = __floats2half2_rn(p2, p3);
        }
        __syncwarp();

        // ---- O += P V  (64 mma; B from V^T rows) ----
#pragma unroll
        for (int ks = 0; ks < 8; ks++) {
            uint32_t aP[4];
            ldsm4(aP, aBase + ks*32);
#pragma unroll
            for (int p = 0; p < 4; p++) {
                uint32_t bf[4];
                ldsm4(bf, bV[p] + vo + ks*32);
                mma_f16(accO[2*p],   aP, bf[0], bf[2]);
                mma_f16(accO[2*p+1], aP, bf[1], bf[3]);
            }
        }
        __syncthreads();
    }

    // ---- epilogue ----
    l0 += __shfl_xor_sync(0xffffffffu, l0, 1);
    l0 += __shfl_xor_sync(0xffffffffu, l0, 2);
    l1 += __shfl_xor_sync(0xffffffffu, l1, 1);
    l1 += __shfl_xor_sync(0xffffffffu, l1, 2);
    const float inv0 = 1.f / l0, inv1 = 1.f / l1;
    const int gr0 = q0 + w*16 + (lane >> 2);
    const int cc = 2*(lane & 3);
#pragma unroll
    for (int ni = 0; ni < 8; ni++) {
        float2 v0 = make_float2(accO[ni][0]*inv0, accO[ni][1]*inv0);
        float2 v1 = make_float2(accO[ni][2]*inv1, accO[ni][3]*inv1);
        *(float2*)(O + base + (size_t)gr0*DM + ni*8 + cc)     = v0;
        *(float2*)(O + base + (size_t)(gr0+8)*DM + ni*8 + cc) = v1;
    }
}

// ---------------------------------------------------------------------------
// LayerNorm over last dim (512). One block (128 threads) per row.
// ---------------------------------------------------------------------------
__global__ __launch_bounds__(128)
void ln_kernel(const float* __restrict__ in, const float* __restrict__ gamma,
               const float* __restrict__ beta, float* __restrict__ out)
{
    const int row = blockIdx.x, tid = threadIdx.x;
    const float4 v = ((const float4*)(in + (size_t)row*DM))[tid];
    float s  = v.x + v.y + v.z + v.w;
    float sq = v.x*v.x + v.y*v.y + v.z*v.z + v.w*v.w;
#pragma unroll
    for (int o = 16; o; o >>= 1) {
        s  += __shfl_down_sync(0xffffffffu, s,  o);
        sq += __shfl_down_sync(0xffffffffu, sq, o);
    }
    __shared__ float ss[4], sqs[4];
    const int w = tid >> 5, lane = tid & 31;
    if (lane == 0) { ss[w] = s; sqs[w] = sq; }
    __syncthreads();
    s  = ss[0] + ss[1] + ss[2] + ss[3];
    sq = sqs[0] + sqs[1] + sqs[2] + sqs[3];

    const float mean = s * (1.f / DM);
    const float var  = sq * (1.f / DM) - mean * mean;
    const float inv  = rsqrtf(var + LN_EPS);

    const float4 g4 = ((const float4*)gamma)[tid];
    const float4 b4 = ((const float4*)beta)[tid];
    float4 o4;
    o4.x = (v.x - mean)*inv*g4.x + b4.x;
    o4.y = (v.y - mean)*inv*g4.y + b4.y;
    o4.z = (v.z - mean)*inv*g4.z + b4.z;
    o4.w = (v.w - mean)*inv*g4.w + b4.w;
    ((float4*)(out + (size_t)row*DM))[tid] = o4;
}

// ---------------------------------------------------------------------------
extern "C" void kernel_launch(void* const* d_in, const int* in_sizes, int n_in,
                              void* d_out, int out_size)
{
    const float* x   = (const float*)d_in[0];
    const float* Wq  = (const float*)d_in[1];
    const float* bq  = (const float*)d_in[2];
    const float* Wk  = (const float*)d_in[3];
    const float* bk  = (const float*)d_in[4];
    const float* Wv  = (const float*)d_in[5];
    const float* bv  = (const float*)d_in[6];
    const float* Wo  = (const float*)d_in[7];
    const float* bo  = (const float*)d_in[8];
    const float* W1  = (const float*)d_in[9];
    const float* b1  = (const float*)d_in[10];
    const float* W2  = (const float*)d_in[11];
    const float* b2  = (const float*)d_in[12];
    const float* g1  = (const float*)d_in[13];
    const float* be1 = (const float*)d_in[14];
    const float* g2  = (const float*)d_in[15];
    const float* be2 = (const float*)d_in[16];

    __half *qh, *kh, *vth;
    float *o, *hb, *h1, *h2, *xb, *ff;
    cudaGetSymbolAddress((void**)&qh,  g_qh);
    cudaGetSymbolAddress((void**)&kh,  g_kh);
    cudaGetSymbolAddress((void**)&vth, g_vth);
    cudaGetSymbolAddress((void**)&o,   g_o);
    cudaGetSymbolAddress((void**)&hb,  g_h);
    cudaGetSymbolAddress((void**)&h1,  g_h1);
    cudaGetSymbolAddress((void**)&h2,  g_h2);
    cudaGetSymbolAddress((void**)&xb,  g_x);
    cudaGetSymbolAddress((void**)&ff,  g_ff);

    cudaFuncSetAttribute(attn_f16, cudaFuncAttributeMaxDynamicSharedMemorySize,
                         AT_SMEM_BYTES);

    const dim3 gProj(DM / 128, ROWS / 128);    // (4, 64)
    const dim3 gFF1 (DFF / 128, ROWS / 128);   // (16, 64)
    const dim3 gAttn(SEQ / 128, NHEAD, NB);    // (8, 8, 8)

    const float* hin = x;
    for (int l = 0; l < NLAYERS; l++) {
        const float* wq = Wq + (size_t)l*DM*DM;
        const float* wk = Wk + (size_t)l*DM*DM;
        const float* wv = Wv + (size_t)l*DM*DM;
        const float* wo = Wo + (size_t)l*DM*DM;
        const float* w1 = W1 + (size_t)l*DM*DFF;
        const float* w2 = W2 + (size_t)l*DFF*DM;

        gemm_f16<4><<<gProj, 256>>>(hin, wq, bq + l*DM, nullptr, (float*)qh,
                                    ROWS, DM, DM, 0.125f);
        gemm_f16<4><<<gProj, 256>>>(hin, wk, bk + l*DM, nullptr, (float*)kh,
                                    ROWS, DM, DM, 1.0f);
        gemm_f16<5><<<gProj, 256>>>(hin, wv, bv + l*DM, nullptr, (float*)vth,
                                    ROWS, DM, DM, 1.0f);

        attn_f16<<<gAttn, 256, AT_SMEM_BYTES>>>(qh, kh, vth, o);

        gemm_f16<2><<<gProj, 256>>>(o, wo, bo + l*DM, hin, hb, ROWS, DM, DM, 1.0f);
        ln_kernel<<<ROWS, 128>>>(hb, g1 + l*DM, be1 + l*DM, h1);

        gemm_f16<1><<<gFF1, 256>>>(h1, w1, b1 + l*DFF, nullptr, ff, ROWS, DFF, DM, 1.0f);
        gemm_f16<2><<<gProj, 256>>>(ff, w2, b2 + l*DM, h1, h2, ROWS, DM, DFF, 1.0f);

        float* lnout = (l == NLAYERS - 1) ? (float*)d_out : xb;
        ln_kernel<<<ROWS, 128>>>(h2, g2 + l*DM, be2 + l*DM, lnout);
        hin = xb;
    }
}

// round 8
// speedup vs baseline: 6.3063x; 1.5282x over previous
#include <cuda_runtime.h>
#include <cuda_fp16.h>
#include <cstdint>
#include <cstddef>

// Problem constants
#define DM      512
#define DFF     2048
#define NB      8
#define SEQ     1024
#define NHEAD   8
#define EHEAD   64
#define ROWS    (NB*SEQ)     // 8192
#define NLAYERS 4
#define LN_EPS  1e-5f

// ---------------- scratch (device globals; no allocations allowed) --------
__device__ __half g_qh [ROWS*DM];    // Q (pre-scaled 1/8)
__device__ __half g_kh [ROWS*DM];
__device__ __half g_vth[DM*ROWS];    // V^T [col][token]
__device__ __half g_oh [ROWS*DM];    // attention out
__device__ __half g_xh [ROWS*DM];    // fp16 copy of layer input
__device__ __half g_h1h[ROWS*DM];    // fp16 copy of post-LN1
__device__ __half g_ffh[ROWS*DFF];   // ReLU(FFN1) in fp16
__device__ float  g_h  [ROWS*DM];
__device__ float  g_h1 [ROWS*DM];
__device__ float  g_h2 [ROWS*DM];
__device__ float  g_x  [ROWS*DM];
// fp16 weights (converted once per launch)
__device__ __half g_wq[NLAYERS*DM*DM];
__device__ __half g_wk[NLAYERS*DM*DM];
__device__ __half g_wv[NLAYERS*DM*DM];
__device__ __half g_wo[NLAYERS*DM*DM];
__device__ __half g_w1[NLAYERS*DM*DFF];
__device__ __half g_w2[NLAYERS*DFF*DM];

// ---------------- helpers ---------------------------------------------------
__device__ __forceinline__ uint32_t f2h2(float a, float b) {
    __half2 h = __floats2half2_rn(a, b);
    return *(uint32_t*)&h;
}
__device__ __forceinline__ void ldsm4(uint32_t* r, uint32_t addr) {
    asm volatile("ldmatrix.sync.aligned.m8n8.x4.shared.b16 {%0,%1,%2,%3}, [%4];\n"
                 : "=r"(r[0]), "=r"(r[1]), "=r"(r[2]), "=r"(r[3]) : "r"(addr));
}
__device__ __forceinline__ void ldsm4t(uint32_t* r, uint32_t addr) {
    asm volatile("ldmatrix.sync.aligned.m8n8.x4.trans.shared.b16 {%0,%1,%2,%3}, [%4];\n"
                 : "=r"(r[0]), "=r"(r[1]), "=r"(r[2]), "=r"(r[3]) : "r"(addr));
}
__device__ __forceinline__ void mma_f16(float* d, const uint32_t* a,
                                        uint32_t b0, uint32_t b1) {
    asm volatile(
        "mma.sync.aligned.m16n8k16.row.col.f32.f16.f16.f32 "
        "{%0,%1,%2,%3},{%4,%5,%6,%7},{%8,%9},{%0,%1,%2,%3};\n"
        : "+f"(d[0]), "+f"(d[1]), "+f"(d[2]), "+f"(d[3])
        : "r"(a[0]), "r"(a[1]), "r"(a[2]), "r"(a[3]), "r"(b0), "r"(b1));
}
__device__ __forceinline__ uint32_t smem_u32(const void* p) {
    return (uint32_t)__cvta_generic_to_shared(p);
}
__device__ __forceinline__ void cpa16(uint32_t dst, const void* src) {
    asm volatile("cp.async.ca.shared.global [%0], [%1], 16;\n"
                 :: "r"(dst), "l"(src) : "memory");
}
__device__ __forceinline__ void cpa_commit() {
    asm volatile("cp.async.commit_group;\n" ::: "memory");
}
template<int N>
__device__ __forceinline__ void cpa_wait() {
    asm volatile("cp.async.wait_group %0;\n" :: "n"(N) : "memory");
}

// ---------------- fp32 -> fp16 bulk convert ---------------------------------
__global__ __launch_bounds__(256)
void f2h_kernel(const float4* __restrict__ src, uint2* __restrict__ dst, int n4)
{
    int i = blockIdx.x*blockDim.x + threadIdx.x;
    if (i < n4) {
        float4 v = src[i];
        uint2 o;
        o.x = f2h2(v.x, v.y);
        o.y = f2h2(v.z, v.w);
        dst[i] = o;
    }
}

// ---------------------------------------------------------------------------
// Pure-FP16 tensor-core GEMM: C = A[M,K] @ B[K,N] + bias, A,B fp16 in gmem.
//  EPI 1: half out, bias+relu       EPI 2: f32 out, bias+residual
//  EPI 4: half out, bias, *cscale   EPI 5: half out transposed Ct[N][ROWS]
// BM=BN=128, BK=32, 256 thr (8 warps, 4m x 2n, warp tile 32x64), m16n8k16.
// cp.async double pipeline; A smem pitch 40 halfs, B pitch 136 halfs.
// ---------------------------------------------------------------------------
#define GPA 40
#define GPB 136
#define ABUF (128*GPA)
#define BBUF (32*GPB)

template<int EPI>
__global__ __launch_bounds__(256, 2)
void gemm_h(const __half* __restrict__ A, const __half* __restrict__ B,
            const float* __restrict__ bias, const float* __restrict__ res,
            void* __restrict__ Cv, int M, int N, int K, float cscale)
{
    __shared__ alignas(16) __half As[2][ABUF];
    __shared__ alignas(16) __half Bs[2][BBUF];

    const int tid = threadIdx.x;
    const int lane = tid & 31, wid = tid >> 5;
    const int wm = wid & 3, wn = wid >> 2;
    const int bx = blockIdx.x, by = blockIdx.y;

    // cp.async chunk mapping (16B = 8 halfs per chunk)
    // A tile: 128 rows x 32 halfs = 512 chunks; thread does chunks tid, tid+256
    const int ar0 = tid >> 2,            ak0 = (tid & 3) << 3;
    const int ar1 = (tid + 256) >> 2,    ak1 = ((tid + 256) & 3) << 3;
    // B tile: 32 rows x 128 halfs = 512 chunks; thread does chunks tid, tid+256
    const int bk0 = tid >> 4,            bn0 = (tid & 15) << 3;
    const int bk1 = bk0 + 16;            // chunk tid+256: same column, +16 rows

    const __half* Ag = A + (size_t)(by*128)*K;
    const __half* Bg = B + (size_t)bx*128;

    const uint32_t sAu = smem_u32(&As[0][0]);
    const uint32_t sBu = smem_u32(&Bs[0][0]);
    const uint32_t dA0 = (uint32_t)((ar0*GPA + ak0) << 1);
    const uint32_t dA1 = (uint32_t)((ar1*GPA + ak1) << 1);
    const uint32_t dB0 = (uint32_t)((bk0*GPB + bn0) << 1);
    const uint32_t dB1 = (uint32_t)((bk1*GPB + bn0) << 1);

    // ldsm addresses (buf 0)
    uint32_t aAd[2], bAd[4];
#pragma unroll
    for (int mi = 0; mi < 2; mi++)
        aAd[mi] = sAu + (((wm*32 + mi*16 + (lane & 15))*GPA + (lane >> 4)*8) << 1);
#pragma unroll
    for (int nt = 0; nt < 4; nt++)
        bAd[nt] = sBu + ((((lane & 7) + ((lane >> 3) & 1)*8)*GPB
                          + wn*64 + nt*16 + (lane >> 4)*8) << 1);

    float acc[2][8][4];
#pragma unroll
    for (int mi = 0; mi < 2; mi++)
#pragma unroll
        for (int ni = 0; ni < 8; ni++)
#pragma unroll
            for (int c = 0; c < 4; c++) acc[mi][ni][c] = 0.f;

    const int KT = K >> 5;

    // prologue: issue tiles 0 and 1
    {
        cpa16(sAu + dA0, Ag + (size_t)ar0*K + ak0);
        cpa16(sAu + dA1, Ag + (size_t)ar1*K + ak1);
        cpa16(sBu + dB0, Bg + (size_t)bk0*N + bn0);
        cpa16(sBu + dB1, Bg + (size_t)bk1*N + bn0);
        cpa_commit();
    }
    {
        const uint32_t boA = ABUF*2, boB = BBUF*2;
        cpa16(sAu + boA + dA0, Ag + (size_t)ar0*K + 32 + ak0);
        cpa16(sAu + boA + dA1, Ag + (size_t)ar1*K + 32 + ak1);
        cpa16(sBu + boB + dB0, Bg + (size_t)(32 + bk0)*N + bn0);
        cpa16(sBu + boB + dB1, Bg + (size_t)(32 + bk1)*N + bn0);
        cpa_commit();
    }

    for (int kt = 0; kt < KT; kt++) {
        const int buf = kt & 1;
        if (kt + 1 < KT) cpa_wait<1>(); else cpa_wait<0>();
        __syncthreads();

        const uint32_t boA = buf ? (uint32_t)(ABUF*2) : 0u;
        const uint32_t boB = buf ? (uint32_t)(BBUF*2) : 0u;
#pragma unroll
        for (int kh = 0; kh < 2; kh++) {
            uint32_t af[2][4], bf[4][4];
            ldsm4(af[0], aAd[0] + boA + kh*32);
            ldsm4(af[1], aAd[1] + boA + kh*32);
#pragma unroll
            for (int nt = 0; nt < 4; nt++)
                ldsm4t(bf[nt], bAd[nt] + boB + kh*16*GPB*2);
#pragma unroll
            for (int nt = 0; nt < 4; nt++) {
#pragma unroll
                for (int mi = 0; mi < 2; mi++) {
                    mma_f16(acc[mi][2*nt],   af[mi], bf[nt][0], bf[nt][1]);
                    mma_f16(acc[mi][2*nt+1], af[mi], bf[nt][2], bf[nt][3]);
                }
            }
        }
        __syncthreads();

        if (kt + 2 < KT) {
            const int k0 = (kt + 2) * 32;
            cpa16(sAu + boA + dA0, Ag + (size_t)ar0*K + k0 + ak0);
            cpa16(sAu + boA + dA1, Ag + (size_t)ar1*K + k0 + ak1);
            cpa16(sBu + boB + dB0, Bg + (size_t)(k0 + bk0)*N + bn0);
            cpa16(sBu + boB + dB1, Bg + (size_t)(k0 + bk1)*N + bn0);
            cpa_commit();
        }
    }

    // ---- epilogue ----
    const int r0 = (by*128) + wm*32 + (lane >> 2);
#pragma unroll
    for (int mi = 0; mi < 2; mi++) {
        const int gr = r0 + mi*16;
#pragma unroll
        for (int ni = 0; ni < 8; ni++) {
            const int gc = (bx*128) + wn*64 + (ni >> 1)*16 + (ni & 1)*8
                         + ((lane & 3) << 1);
            const float2 bia = *(const float2*)(bias + gc);
            float2 v0 = make_float2(acc[mi][ni][0] + bia.x, acc[mi][ni][1] + bia.y);
            float2 v1 = make_float2(acc[mi][ni][2] + bia.x, acc[mi][ni][3] + bia.y);
            if (EPI == 1) {
                v0.x = fmaxf(v0.x, 0.f); v0.y = fmaxf(v0.y, 0.f);
                v1.x = fmaxf(v1.x, 0.f); v1.y = fmaxf(v1.y, 0.f);
                __half* Ch = (__half*)Cv;
                *(__half2*)(Ch + (size_t)gr*N + gc)     = __floats2half2_rn(v0.x, v0.y);
                *(__half2*)(Ch + (size_t)(gr+8)*N + gc) = __floats2half2_rn(v1.x, v1.y);
            } else if (EPI == 2) {
                const float2 r_0 = *(const float2*)(res + (size_t)gr*N + gc);
                const float2 r_1 = *(const float2*)(res + (size_t)(gr+8)*N + gc);
                v0.x += r_0.x; v0.y += r_0.y;
                v1.x += r_1.x; v1.y += r_1.y;
                float* Cf = (float*)Cv;
                *(float2*)(Cf + (size_t)gr*N + gc)     = v0;
                *(float2*)(Cf + (size_t)(gr+8)*N + gc) = v1;
            } else if (EPI == 4) {
                __half* Ch = (__half*)Cv;
                *(__half2*)(Ch + (size_t)gr*N + gc) =
                    __floats2half2_rn(v0.x*cscale, v0.y*cscale);
                *(__half2*)(Ch + (size_t)(gr+8)*N + gc) =
                    __floats2half2_rn(v1.x*cscale, v1.y*cscale);
            } else {  // EPI == 5, transposed half store
                __half* Ch = (__half*)Cv;
                Ch[(size_t)gc*ROWS + gr]         = __float2half_rn(v0.x);
                Ch[(size_t)(gc+1)*ROWS + gr]     = __float2half_rn(v0.y);
                Ch[(size_t)gc*ROWS + gr + 8]     = __float2half_rn(v1.x);
                Ch[(size_t)(gc+1)*ROWS + gr + 8] = __float2half_rn(v1.y);
            }
        }
    }
}

// ---------------------------------------------------------------------------
// FP16 tensor-core flash attention (fp32 softmax/accum). Output fp16.
// ---------------------------------------------------------------------------
#define AT_PA 136
#define AT_PK 72
#define AT_AH (128*AT_PA)
#define AT_KH (128*AT_PK)
#define AT_VH (64*AT_PA)
#define AT_OFF_K AT_AH
#define AT_OFF_V (AT_OFF_K + 2*AT_KH)
#define AT_SMEM_BYTES ((AT_OFF_V + 2*AT_VH)*2)

__global__ __launch_bounds__(256, 1)
void attn_f16(const __half* __restrict__ Qh, const __half* __restrict__ Kh,
              const __half* __restrict__ Vth, __half* __restrict__ Oh)
{
    extern __shared__ __half smh[];
    __half* sA = smh;

    const int n = blockIdx.z, h = blockIdx.y;
    const int tid = threadIdx.x, lane = tid & 31, w = tid >> 5;
    const size_t base  = ((size_t)n*SEQ)*DM + h*EHEAD;
    const size_t vbase = ((size_t)h*EHEAD)*ROWS + (size_t)n*SEQ;
    const int q0 = blockIdx.x * 128;

    const uint32_t sAu = smem_u32(sA);
    const uint32_t sKu = smem_u32(smh + AT_OFF_K);
    const uint32_t sVu = smem_u32(smh + AT_OFF_V);

#pragma unroll
    for (int j = 0; j < 4; j++) {
        int idx = j*256 + tid;
        int r = idx >> 3, c8 = (idx & 7) << 3;
        cpa16(sAu + (uint32_t)((r*AT_PA + c8) << 1),
              Qh + base + (size_t)(q0 + r)*DM + c8);
    }
    cpa_commit();
#pragma unroll
    for (int j = 0; j < 4; j++) {
        int idx = j*256 + tid;
        int r = idx >> 3, c8 = (idx & 7) << 3;
        cpa16(sKu + (uint32_t)((r*AT_PK + c8) << 1),
              Kh + base + (size_t)r*DM + c8);
    }
#pragma unroll
    for (int j = 0; j < 4; j++) {
        int idx = j*256 + tid;
        int r = idx >> 4, c8 = (idx & 15) << 3;
        cpa16(sVu + (uint32_t)((r*AT_PA + c8) << 1),
              Vth + vbase + (size_t)r*ROWS + c8);
    }
    cpa_commit();

    cpa_wait<1>();
    __syncthreads();

    const uint32_t aBase = sAu + (((w*16 + (lane & 15))*AT_PA + (lane >> 4)*8) << 1);
    uint32_t aQ[4][4];
#pragma unroll
    for (int ks = 0; ks < 4; ks++) ldsm4(aQ[ks], aBase + ks*32);

    uint32_t bK[8], bV[4];
#pragma unroll
    for (int p = 0; p < 8; p++)
        bK[p] = sKu + (((p*16 + (lane & 7) + ((lane >> 3) & 1)*8)*AT_PK
                        + (lane >> 4)*8) << 1);
#pragma unroll
    for (int p = 0; p < 4; p++)
        bV[p] = sVu + (((p*16 + (lane & 7) + ((lane >> 3) & 1)*8)*AT_PA
                        + (lane >> 4)*8) << 1);

    float accO[8][4];
#pragma unroll
    for (int ni = 0; ni < 8; ni++)
#pragma unroll
        for (int c = 0; c < 4; c++) accO[ni][c] = 0.f;
    float m0 = -1e30f, m1 = -1e30f, l0 = 0.f, l1 = 0.f;

    const int rA = w*16 + (lane >> 2);
    __half* pr0 = &sA[rA*AT_PA + 2*(lane & 3)];
    __half* pr1 = pr0 + 8*AT_PA;

    for (int kt = 0; kt < SEQ/128; kt++) {
        const int buf = kt & 1;
        if (kt + 1 < SEQ/128) {
            const int nb = buf ^ 1;
            const uint32_t ko = (uint32_t)(nb * AT_KH) << 1;
            const uint32_t vo = (uint32_t)(nb * AT_VH) << 1;
#pragma unroll
            for (int j = 0; j < 4; j++) {
                int idx = j*256 + tid;
                int r = idx >> 3, c8 = (idx & 7) << 3;
                cpa16(sKu + ko + (uint32_t)((r*AT_PK + c8) << 1),
                      Kh + base + (size_t)((kt+1)*128 + r)*DM + c8);
            }
#pragma unroll
            for (int j = 0; j < 4; j++) {
                int idx = j*256 + tid;
                int r = idx >> 4, c8 = (idx & 15) << 3;
                cpa16(sVu + vo + (uint32_t)((r*AT_PA + c8) << 1),
                      Vth + vbase + (size_t)r*ROWS + (kt+1)*128 + c8);
            }
            cpa_commit();
            cpa_wait<1>();
        } else {
            cpa_wait<0>();
        }
        __syncthreads();

        const uint32_t ko = (uint32_t)(buf * AT_KH) << 1;
        const uint32_t vo = (uint32_t)(buf * AT_VH) << 1;

        float accS[16][4];
#pragma unroll
        for (int t = 0; t < 16; t++)
#pragma unroll
            for (int c = 0; c < 4; c++) accS[t][c] = 0.f;
#pragma unroll
        for (int ks = 0; ks < 4; ks++) {
#pragma unroll
            for (int p = 0; p < 8; p++) {
                uint32_t bf[4];
                ldsm4(bf, bK[p] + ko + ks*32);
                mma_f16(accS[2*p],   aQ[ks], bf[0], bf[2]);
                mma_f16(accS[2*p+1], aQ[ks], bf[1], bf[3]);
            }
        }

        float rmax0 = -1e30f, rmax1 = -1e30f;
#pragma unroll
        for (int t = 0; t < 16; t++) {
            rmax0 = fmaxf(rmax0, fmaxf(accS[t][0], accS[t][1]));
            rmax1 = fmaxf(rmax1, fmaxf(accS[t][2], accS[t][3]));
        }
        rmax0 = fmaxf(rmax0, __shfl_xor_sync(0xffffffffu, rmax0, 1));
        rmax0 = fmaxf(rmax0, __shfl_xor_sync(0xffffffffu, rmax0, 2));
        rmax1 = fmaxf(rmax1, __shfl_xor_sync(0xffffffffu, rmax1, 1));
        rmax1 = fmaxf(rmax1, __shfl_xor_sync(0xffffffffu, rmax1, 2));
        const float mn0 = fmaxf(m0, rmax0), mn1 = fmaxf(m1, rmax1);
        const float cr0 = __expf(m0 - mn0), cr1 = __expf(m1 - mn1);
        m0 = mn0; m1 = mn1;
        l0 *= cr0; l1 *= cr1;
#pragma unroll
        for (int ni = 0; ni < 8; ni++) {
            accO[ni][0] *= cr0; accO[ni][1] *= cr0;
            accO[ni][2] *= cr1; accO[ni][3] *= cr1;
        }
#pragma unroll
        for (int t = 0; t < 16; t++) {
            float p0 = __expf(accS[t][0] - m0), p1 = __expf(accS[t][1] - m0);
            float p2 = __expf(accS[t][2] - m1), p3 = __expf(accS[t][3] - m1);
            l0 += p0 + p1; l1 += p2 + p3;
            *(__half2*)(pr0 + t*8) = __floats2half2_rn(p0, p1);
            *(__half2*)(pr1 + t*8) = __floats2half2_rn(p2, p3);
        }
        __syncwarp();

#pragma unroll
        for (int ks = 0; ks < 8; ks++) {
            uint32_t aP[4];
            ldsm4(aP, aBase + ks*32);
#pragma unroll
            for (int p = 0; p < 4; p++) {
                uint32_t bf[4];
                ldsm4(bf, bV[p] + vo + ks*32);
                mma_f16(accO[2*p],   aP, bf[0], bf[2]);
                mma_f16(accO[2*p+1], aP, bf[1], bf[3]);
            }
        }
        __syncthreads();
    }

    l0 += __shfl_xor_sync(0xffffffffu, l0, 1);
    l0 += __shfl_xor_sync(0xffffffffu, l0, 2);
    l1 += __shfl_xor_sync(0xffffffffu, l1, 1);
    l1 += __shfl_xor_sync(0xffffffffu, l1, 2);
    const float inv0 = 1.f / l0, inv1 = 1.f / l1;
    const int gr0 = q0 + w*16 + (lane >> 2);
    const int cc = 2*(lane & 3);
#pragma unroll
    for (int ni = 0; ni < 8; ni++) {
        *(__half2*)(Oh + base + (size_t)gr0*DM + ni*8 + cc) =
            __floats2half2_rn(accO[ni][0]*inv0, accO[ni][1]*inv0);
        *(__half2*)(Oh + base + (size_t)(gr0+8)*DM + ni*8 + cc) =
            __floats2half2_rn(accO[ni][2]*inv1, accO[ni][3]*inv1);
    }
}

// ---------------------------------------------------------------------------
// LayerNorm (512). One block/row. Writes fp32 out and optional fp16 copy.
// ---------------------------------------------------------------------------
__global__ __launch_bounds__(128)
void ln_kernel(const float* __restrict__ in, const float* __restrict__ gamma,
               const float* __restrict__ beta, float* __restrict__ out,
               __half* __restrict__ out16)
{
    const int row = blockIdx.x, tid = threadIdx.x;
    const float4 v = ((const float4*)(in + (size_t)row*DM))[tid];
    float s  = v.x + v.y + v.z + v.w;
    float sq = v.x*v.x + v.y*v.y + v.z*v.z + v.w*v.w;
#pragma unroll
    for (int o = 16; o; o >>= 1) {
        s  += __shfl_down_sync(0xffffffffu, s,  o);
        sq += __shfl_down_sync(0xffffffffu, sq, o);
    }
    __shared__ float ss[4], sqs[4];
    const int w = tid >> 5, lane = tid & 31;
    if (lane == 0) { ss[w] = s; sqs[w] = sq; }
    __syncthreads();
    s  = ss[0] + ss[1] + ss[2] + ss[3];
    sq = sqs[0] + sqs[1] + sqs[2] + sqs[3];

    const float mean = s * (1.f / DM);
    const float var  = sq * (1.f / DM) - mean * mean;
    const float inv  = rsqrtf(var + LN_EPS);

    const float4 g4 = ((const float4*)gamma)[tid];
    const float4 b4 = ((const float4*)beta)[tid];
    float4 o4;
    o4.x = (v.x - mean)*inv*g4.x + b4.x;
    o4.y = (v.y - mean)*inv*g4.y + b4.y;
    o4.z = (v.z - mean)*inv*g4.z + b4.z;
    o4.w = (v.w - mean)*inv*g4.w + b4.w;
    ((float4*)(out + (size_t)row*DM))[tid] = o4;
    if (out16) {
        uint2 h;
        h.x = f2h2(o4.x, o4.y);
        h.y = f2h2(o4.z, o4.w);
        ((uint2*)(out16 + (size_t)row*DM))[tid] = h;
    }
}

// ---------------------------------------------------------------------------
extern "C" void kernel_launch(void* const* d_in, const int* in_sizes, int n_in,
                              void* d_out, int out_size)
{
    const float* x   = (const float*)d_in[0];
    const float* Wq  = (const float*)d_in[1];
    const float* bq  = (const float*)d_in[2];
    const float* Wk  = (const float*)d_in[3];
    const float* bk  = (const float*)d_in[4];
    const float* Wv  = (const float*)d_in[5];
    const float* bv  = (const float*)d_in[6];
    const float* Wo  = (const float*)d_in[7];
    const float* bo  = (const float*)d_in[8];
    const float* W1  = (const float*)d_in[9];
    const float* b1  = (const float*)d_in[10];
    const float* W2  = (const float*)d_in[11];
    const float* b2  = (const float*)d_in[12];
    const float* g1  = (const float*)d_in[13];
    const float* be1 = (const float*)d_in[14];
    const float* g2  = (const float*)d_in[15];
    const float* be2 = (const float*)d_in[16];

    __half *qh, *kh, *vth, *oh, *xh, *h1h, *ffh;
    __half *wqh, *wkh, *wvh, *woh, *w1h, *w2h;
    float *hb, *h1, *h2, *xb;
    cudaGetSymbolAddress((void**)&qh,  g_qh);
    cudaGetSymbolAddress((void**)&kh,  g_kh);
    cudaGetSymbolAddress((void**)&vth, g_vth);
    cudaGetSymbolAddress((void**)&oh,  g_oh);
    cudaGetSymbolAddress((void**)&xh,  g_xh);
    cudaGetSymbolAddress((void**)&h1h, g_h1h);
    cudaGetSymbolAddress((void**)&ffh, g_ffh);
    cudaGetSymbolAddress((void**)&hb,  g_h);
    cudaGetSymbolAddress((void**)&h1,  g_h1);
    cudaGetSymbolAddress((void**)&h2,  g_h2);
    cudaGetSymbolAddress((void**)&xb,  g_x);
    cudaGetSymbolAddress((void**)&wqh, g_wq);
    cudaGetSymbolAddress((void**)&wkh, g_wk);
    cudaGetSymbolAddress((void**)&wvh, g_wv);
    cudaGetSymbolAddress((void**)&woh, g_wo);
    cudaGetSymbolAddress((void**)&w1h, g_w1);
    cudaGetSymbolAddress((void**)&w2h, g_w2);

    cudaFuncSetAttribute(attn_f16, cudaFuncAttributeMaxDynamicSharedMemorySize,
                         AT_SMEM_BYTES);

    // ---- one-time fp32 -> fp16 conversions (weights + layer-0 input) ----
    {
        const int nqkv = NLAYERS*DM*DM/4, nff = NLAYERS*DM*DFF/4,
                  nx = ROWS*DM/4;
        f2h_kernel<<<(nqkv+255)/256, 256>>>((const float4*)Wq, (uint2*)wqh, nqkv);
        f2h_kernel<<<(nqkv+255)/256, 256>>>((const float4*)Wk, (uint2*)wkh, nqkv);
        f2h_kernel<<<(nqkv+255)/256, 256>>>((const float4*)Wv, (uint2*)wvh, nqkv);
        f2h_kernel<<<(nqkv+255)/256, 256>>>((const float4*)Wo, (uint2*)woh, nqkv);
        f2h_kernel<<<(nff+255)/256, 256>>>((const float4*)W1, (uint2*)w1h, nff);
        f2h_kernel<<<(nff+255)/256, 256>>>((const float4*)W2, (uint2*)w2h, nff);
        f2h_kernel<<<(nx+255)/256, 256>>>((const float4*)x, (uint2*)xh, nx);
    }

    const dim3 gProj(DM / 128, ROWS / 128);    // (4, 64)
    const dim3 gFF1 (DFF / 128, ROWS / 128);   // (16, 64)
    const dim3 gAttn(SEQ / 128, NHEAD, NB);    // (8, 8, 8)

    const float* hin = x;
    for (int l = 0; l < NLAYERS; l++) {
        const __half* wq = wqh + (size_t)l*DM*DM;
        const __half* wk = wkh + (size_t)l*DM*DM;
        const __half* wv = wvh + (size_t)l*DM*DM;
        const __half* wo = woh + (size_t)l*DM*DM;
        const __half* w1 = w1h + (size_t)l*DM*DFF;
        const __half* w2 = w2h + (size_t)l*DFF*DM;

        gemm_h<4><<<gProj, 256>>>(xh, wq, bq + l*DM, nullptr, qh,
                                  ROWS, DM, DM, 0.125f);
        gemm_h<4><<<gProj, 256>>>(xh, wk, bk + l*DM, nullptr, kh,
                                  ROWS, DM, DM, 1.0f);
        gemm_h<5><<<gProj, 256>>>(xh, wv, bv + l*DM, nullptr, vth,
                                  ROWS, DM, DM, 1.0f);

        attn_f16<<<gAttn, 256, AT_SMEM_BYTES>>>(qh, kh, vth, oh);

        gemm_h<2><<<gProj, 256>>>(oh, wo, bo + l*DM, hin, hb, ROWS, DM, DM, 1.0f);
        ln_kernel<<<ROWS, 128>>>(hb, g1 + l*DM, be1 + l*DM, h1, h1h);

        gemm_h<1><<<gFF1, 256>>>(h1h, w1, b1 + l*DFF, nullptr, ffh,
                                 ROWS, DFF, DM, 1.0f);
        gemm_h<2><<<gProj, 256>>>(ffh, w2, b2 + l*DM, h1, h2, ROWS, DM, DFF, 1.0f);

        float* lnout = (l == NLAYERS - 1) ? (float*)d_out : xb;
        __half* lnout16 = (l == NLAYERS - 1) ? (__half*)nullptr : xh;
        ln_kernel<<<ROWS, 128>>>(h2, g2 + l*DM, be2 + l*DM, lnout, lnout16);
        hin = xb;
    }
}

// round 9
// speedup vs baseline: 6.4754x; 1.0268x over previous
#include <cuda_runtime.h>
#include <cuda_fp16.h>
#include <cstdint>
#include <cstddef>

// Problem constants
#define DM      512
#define DFF     2048
#define NB      8
#define SEQ     1024
#define NHEAD   8
#define EHEAD   64
#define ROWS    (NB*SEQ)     // 8192
#define NLAYERS 4
#define LN_EPS  1e-5f

// ---------------- scratch (device globals; no allocations allowed) --------
__device__ __half g_qh [ROWS*DM];    // Q (pre-scaled 1/8)
__device__ __half g_kh [ROWS*DM];
__device__ __half g_vth[DM*ROWS];    // V^T [col][token]
__device__ __half g_oh [ROWS*DM];    // attention out
__device__ __half g_xh [ROWS*DM];    // fp16 copy of layer input
__device__ __half g_h1h[ROWS*DM];    // fp16 copy of post-LN1
__device__ __half g_ffh[ROWS*DFF];   // ReLU(FFN1) in fp16
__device__ float  g_h  [ROWS*DM];
__device__ float  g_h1 [ROWS*DM];
__device__ float  g_h2 [ROWS*DM];
__device__ float  g_x  [ROWS*DM];
// fp16 weights (converted once per launch)
__device__ __half g_wq[NLAYERS*DM*DM];
__device__ __half g_wk[NLAYERS*DM*DM];
__device__ __half g_wv[NLAYERS*DM*DM];
__device__ __half g_wo[NLAYERS*DM*DM];
__device__ __half g_w1[NLAYERS*DM*DFF];
__device__ __half g_w2[NLAYERS*DFF*DM];

// ---------------- helpers ---------------------------------------------------
__device__ __forceinline__ uint32_t f2h2(float a, float b) {
    __half2 h = __floats2half2_rn(a, b);
    return *(uint32_t*)&h;
}
__device__ __forceinline__ void ldsm4(uint32_t* r, uint32_t addr) {
    asm volatile("ldmatrix.sync.aligned.m8n8.x4.shared.b16 {%0,%1,%2,%3}, [%4];\n"
                 : "=r"(r[0]), "=r"(r[1]), "=r"(r[2]), "=r"(r[3]) : "r"(addr));
}
__device__ __forceinline__ void ldsm4t(uint32_t* r, uint32_t addr) {
    asm volatile("ldmatrix.sync.aligned.m8n8.x4.trans.shared.b16 {%0,%1,%2,%3}, [%4];\n"
                 : "=r"(r[0]), "=r"(r[1]), "=r"(r[2]), "=r"(r[3]) : "r"(addr));
}
__device__ __forceinline__ void mma_f16(float* d, const uint32_t* a,
                                        uint32_t b0, uint32_t b1) {
    asm volatile(
        "mma.sync.aligned.m16n8k16.row.col.f32.f16.f16.f32 "
        "{%0,%1,%2,%3},{%4,%5,%6,%7},{%8,%9},{%0,%1,%2,%3};\n"
        : "+f"(d[0]), "+f"(d[1]), "+f"(d[2]), "+f"(d[3])
        : "r"(a[0]), "r"(a[1]), "r"(a[2]), "r"(a[3]), "r"(b0), "r"(b1));
}
__device__ __forceinline__ uint32_t smem_u32(const void* p) {
    return (uint32_t)__cvta_generic_to_shared(p);
}
__device__ __forceinline__ void cpa16(uint32_t dst, const void* src) {
    asm volatile("cp.async.ca.shared.global [%0], [%1], 16;\n"
                 :: "r"(dst), "l"(src) : "memory");
}
__device__ __forceinline__ void cpa_commit() {
    asm volatile("cp.async.commit_group;\n" ::: "memory");
}
template<int N>
__device__ __forceinline__ void cpa_wait() {
    asm volatile("cp.async.wait_group %0;\n" :: "n"(N) : "memory");
}

// ---------------- fp32 -> fp16 bulk convert (all 7 arrays, one launch) -----
__global__ __launch_bounds__(256)
void f2h_all(const float4* s0, uint2* d0, int n0,
             const float4* s1, uint2* d1, int n1,
             const float4* s2, uint2* d2, int n2,
             const float4* s3, uint2* d3, int n3,
             const float4* s4, uint2* d4, int n4,
             const float4* s5, uint2* d5, int n5,
             const float4* s6, uint2* d6, int n6)
{
    const float4* s; uint2* d; int n;
    switch (blockIdx.y) {
        case 0: s = s0; d = d0; n = n0; break;
        case 1: s = s1; d = d1; n = n1; break;
        case 2: s = s2; d = d2; n = n2; break;
        case 3: s = s3; d = d3; n = n3; break;
        case 4: s = s4; d = d4; n = n4; break;
        case 5: s = s5; d = d5; n = n5; break;
        default: s = s6; d = d6; n = n6; break;
    }
    int i = blockIdx.x*blockDim.x + threadIdx.x;
    if (i < n) {
        float4 v = s[i];
        uint2 o;
        o.x = f2h2(v.x, v.y);
        o.y = f2h2(v.z, v.w);
        d[i] = o;
    }
}

// ---------------------------------------------------------------------------
// GEMM core macros (shared by gemm_h and gemm_qkv)
// BM=BN=128, BK=32, 256 thr (8 warps, 4m x 2n, warp tile 32x64), m16n8k16.
// ---------------------------------------------------------------------------
#define GPA 40
#define GPB 136
#define ABUF (128*GPA)
#define BBUF (32*GPB)

// mainloop shared by both GEMM kernels (A,B fp16 gmem; acc fp32)
#define GEMM_MAINLOOP(Aptr, Bptr, Kdim, Ndim)                                   \
    const int ar0 = tid >> 2,         ak0 = (tid & 3) << 3;                     \
    const int ar1 = (tid + 256) >> 2, ak1 = ((tid + 256) & 3) << 3;             \
    const int bk0 = tid >> 4,         bn0 = (tid & 15) << 3;                    \
    const int bk1 = bk0 + 16;                                                   \
    const uint32_t sAu = smem_u32(&As[0][0]);                                   \
    const uint32_t sBu = smem_u32(&Bs[0][0]);                                   \
    const uint32_t dA0 = (uint32_t)((ar0*GPA + ak0) << 1);                      \
    const uint32_t dA1 = (uint32_t)((ar1*GPA + ak1) << 1);                      \
    const uint32_t dB0 = (uint32_t)((bk0*GPB + bn0) << 1);                      \
    const uint32_t dB1 = (uint32_t)((bk1*GPB + bn0) << 1);                      \
    uint32_t aAd[2], bAd[4];                                                    \
    _Pragma("unroll")                                                           \
    for (int mi = 0; mi < 2; mi++)                                              \
        aAd[mi] = sAu + (((wm*32 + mi*16 + (lane & 15))*GPA + (lane >> 4)*8) << 1); \
    _Pragma("unroll")                                                           \
    for (int nt = 0; nt < 4; nt++)                                              \
        bAd[nt] = sBu + ((((lane & 7) + ((lane >> 3) & 1)*8)*GPB                \
                          + wn*64 + nt*16 + (lane >> 4)*8) << 1);               \
    float acc[2][8][4];                                                         \
    _Pragma("unroll")                                                           \
    for (int mi = 0; mi < 2; mi++)                                              \
        _Pragma("unroll")                                                       \
        for (int ni = 0; ni < 8; ni++)                                          \
            _Pragma("unroll")                                                   \
            for (int c = 0; c < 4; c++) acc[mi][ni][c] = 0.f;                   \
    const int KT = (Kdim) >> 5;                                                 \
    {                                                                           \
        cpa16(sAu + dA0, (Aptr) + (size_t)ar0*(Kdim) + ak0);                    \
        cpa16(sAu + dA1, (Aptr) + (size_t)ar1*(Kdim) + ak1);                    \
        cpa16(sBu + dB0, (Bptr) + (size_t)bk0*(Ndim) + bn0);                    \
        cpa16(sBu + dB1, (Bptr) + (size_t)bk1*(Ndim) + bn0);                    \
        cpa_commit();                                                           \
    }                                                                           \
    {                                                                           \
        const uint32_t pA = ABUF*2, pB = BBUF*2;                                \
        cpa16(sAu + pA + dA0, (Aptr) + (size_t)ar0*(Kdim) + 32 + ak0);          \
        cpa16(sAu + pA + dA1, (Aptr) + (size_t)ar1*(Kdim) + 32 + ak1);          \
        cpa16(sBu + pB + dB0, (Bptr) + (size_t)(32 + bk0)*(Ndim) + bn0);        \
        cpa16(sBu + pB + dB1, (Bptr) + (size_t)(32 + bk1)*(Ndim) + bn0);        \
        cpa_commit();                                                           \
    }                                                                           \
    for (int kt = 0; kt < KT; kt++) {                                           \
        const int buf = kt & 1;                                                 \
        if (kt + 1 < KT) cpa_wait<1>(); else cpa_wait<0>();                     \
        __syncthreads();                                                        \
        const uint32_t boA = buf ? (uint32_t)(ABUF*2) : 0u;                     \
        const uint32_t boB = buf ? (uint32_t)(BBUF*2) : 0u;                     \
        _Pragma("unroll")                                                       \
        for (int kh = 0; kh < 2; kh++) {                                        \
            uint32_t af[2][4], bf[4][4];                                        \
            ldsm4(af[0], aAd[0] + boA + kh*32);                                 \
            ldsm4(af[1], aAd[1] + boA + kh*32);                                 \
            _Pragma("unroll")                                                   \
            for (int nt = 0; nt < 4; nt++)                                      \
                ldsm4t(bf[nt], bAd[nt] + boB + kh*16*GPB*2);                    \
            _Pragma("unroll")                                                   \
            for (int nt = 0; nt < 4; nt++) {                                    \
                _Pragma("unroll")                                               \
                for (int mi = 0; mi < 2; mi++) {                                \
                    mma_f16(acc[mi][2*nt],   af[mi], bf[nt][0], bf[nt][1]);     \
                    mma_f16(acc[mi][2*nt+1], af[mi], bf[nt][2], bf[nt][3]);     \
                }                                                               \
            }                                                                   \
        }                                                                       \
        __syncthreads();                                                        \
        if (kt + 2 < KT) {                                                      \
            const int k0 = (kt + 2) * 32;                                       \
            cpa16(sAu + boA + dA0, (Aptr) + (size_t)ar0*(Kdim) + k0 + ak0);     \
            cpa16(sAu + boA + dA1, (Aptr) + (size_t)ar1*(Kdim) + k0 + ak1);     \
            cpa16(sBu + boB + dB0, (Bptr) + (size_t)(k0 + bk0)*(Ndim) + bn0);   \
            cpa16(sBu + boB + dB1, (Bptr) + (size_t)(k0 + bk1)*(Ndim) + bn0);   \
            cpa_commit();                                                       \
        }                                                                       \
    }

// ---------------------------------------------------------------------------
// General fp16 GEMM with fused epilogues.
//  EPI 1: half out, bias+relu   EPI 2: f32 out, bias+residual
// ---------------------------------------------------------------------------
template<int EPI>
__global__ __launch_bounds__(256, 2)
void gemm_h(const __half* __restrict__ A, const __half* __restrict__ B,
            const float* __restrict__ bias, const float* __restrict__ res,
            void* __restrict__ Cv, int M, int N, int K)
{
    __shared__ alignas(16) __half As[2][ABUF];
    __shared__ alignas(16) __half Bs[2][BBUF];

    const int tid = threadIdx.x;
    const int lane = tid & 31, wid = tid >> 5;
    const int wm = wid & 3, wn = wid >> 2;
    const int bx = blockIdx.x, by = blockIdx.y;

    const __half* Ag = A + (size_t)(by*128)*K;
    const __half* Bg = B + (size_t)bx*128;

    GEMM_MAINLOOP(Ag, Bg, K, N)

    const int r0 = (by*128) + wm*32 + (lane >> 2);
#pragma unroll
    for (int mi = 0; mi < 2; mi++) {
        const int gr = r0 + mi*16;
#pragma unroll
        for (int ni = 0; ni < 8; ni++) {
            const int gc = (bx*128) + wn*64 + (ni >> 1)*16 + (ni & 1)*8
                         + ((lane & 3) << 1);
            const float2 bia = *(const float2*)(bias + gc);
            float2 v0 = make_float2(acc[mi][ni][0] + bia.x, acc[mi][ni][1] + bia.y);
            float2 v1 = make_float2(acc[mi][ni][2] + bia.x, acc[mi][ni][3] + bia.y);
            if (EPI == 1) {
                v0.x = fmaxf(v0.x, 0.f); v0.y = fmaxf(v0.y, 0.f);
                v1.x = fmaxf(v1.x, 0.f); v1.y = fmaxf(v1.y, 0.f);
                __half* Ch = (__half*)Cv;
                *(__half2*)(Ch + (size_t)gr*N + gc)     = __floats2half2_rn(v0.x, v0.y);
                *(__half2*)(Ch + (size_t)(gr+8)*N + gc) = __floats2half2_rn(v1.x, v1.y);
            } else {  // EPI == 2
                const float2 r_0 = *(const float2*)(res + (size_t)gr*N + gc);
                const float2 r_1 = *(const float2*)(res + (size_t)(gr+8)*N + gc);
                v0.x += r_0.x; v0.y += r_0.y;
                v1.x += r_1.x; v1.y += r_1.y;
                float* Cf = (float*)Cv;
                *(float2*)(Cf + (size_t)gr*N + gc)     = v0;
                *(float2*)(Cf + (size_t)(gr+8)*N + gc) = v1;
            }
        }
    }
}

// ---------------------------------------------------------------------------
// Fused QKV projection: grid (12, 64). bx>>2 selects Q/K/V.
//  Q: half out, bias, *0.125      K: half out, bias      V: half out, C^T
// ---------------------------------------------------------------------------
__global__ __launch_bounds__(256, 2)
void gemm_qkv(const __half* __restrict__ A,
              const __half* __restrict__ Bq, const __half* __restrict__ Bk,
              const __half* __restrict__ Bv,
              const float* __restrict__ bq, const float* __restrict__ bk,
              const float* __restrict__ bv,
              __half* __restrict__ Oq, __half* __restrict__ Ok,
              __half* __restrict__ Ovt)
{
    __shared__ alignas(16) __half As[2][ABUF];
    __shared__ alignas(16) __half Bs[2][BBUF];

    const int tid = threadIdx.x;
    const int lane = tid & 31, wid = tid >> 5;
    const int wm = wid & 3, wn = wid >> 2;
    const int sel = blockIdx.x >> 2, bx = blockIdx.x & 3;
    const int by = blockIdx.y;
    const int N = DM, K = DM;

    const __half* B  = (sel == 0) ? Bq : (sel == 1) ? Bk : Bv;
    const float* bia_p = (sel == 0) ? bq : (sel == 1) ? bk : bv;

    const __half* Ag = A + (size_t)(by*128)*K;
    const __half* Bg = B + (size_t)bx*128;

    GEMM_MAINLOOP(Ag, Bg, K, N)

    const int r0 = (by*128) + wm*32 + (lane >> 2);
#pragma unroll
    for (int mi = 0; mi < 2; mi++) {
        const int gr = r0 + mi*16;
#pragma unroll
        for (int ni = 0; ni < 8; ni++) {
            const int gc = (bx*128) + wn*64 + (ni >> 1)*16 + (ni & 1)*8
                         + ((lane & 3) << 1);
            const float2 bia = *(const float2*)(bia_p + gc);
            float2 v0 = make_float2(acc[mi][ni][0] + bia.x, acc[mi][ni][1] + bia.y);
            float2 v1 = make_float2(acc[mi][ni][2] + bia.x, acc[mi][ni][3] + bia.y);
            if (sel == 0) {
                *(__half2*)(Oq + (size_t)gr*N + gc) =
                    __floats2half2_rn(v0.x*0.125f, v0.y*0.125f);
                *(__half2*)(Oq + (size_t)(gr+8)*N + gc) =
                    __floats2half2_rn(v1.x*0.125f, v1.y*0.125f);
            } else if (sel == 1) {
                *(__half2*)(Ok + (size_t)gr*N + gc)     = __floats2half2_rn(v0.x, v0.y);
                *(__half2*)(Ok + (size_t)(gr+8)*N + gc) = __floats2half2_rn(v1.x, v1.y);
            } else {
                Ovt[(size_t)gc*ROWS + gr]         = __float2half_rn(v0.x);
                Ovt[(size_t)(gc+1)*ROWS + gr]     = __float2half_rn(v0.y);
                Ovt[(size_t)gc*ROWS + gr + 8]     = __float2half_rn(v1.x);
                Ovt[(size_t)(gc+1)*ROWS + gr + 8] = __float2half_rn(v1.y);
            }
        }
    }
}

// ---------------------------------------------------------------------------
// FP16 flash attention, 64 q-rows / 128 threads / 4 warps per CTA,
// 2 CTAs per SM. K-tile 128 keys double-buffered; V from V^T.
// smem halfs: sA(Q then P) 64x136 | sK[2] 128x72 | sVt[2] 64x136
// ---------------------------------------------------------------------------
#define AT_PA 136
#define AT_PK 72
#define AT_AH (64*AT_PA)             // 8704 halfs
#define AT_KH (128*AT_PK)            // 9216 halfs per K buffer
#define AT_VH (64*AT_PA)             // 8704 halfs per V buffer
#define AT_OFF_K AT_AH
#define AT_OFF_V (AT_OFF_K + 2*AT_KH)
#define AT_SMEM_BYTES ((AT_OFF_V + 2*AT_VH)*2)   // 89088 B

__global__ __launch_bounds__(128, 2)
void attn_f16(const __half* __restrict__ Qh, const __half* __restrict__ Kh,
              const __half* __restrict__ Vth, __half* __restrict__ Oh)
{
    extern __shared__ __half smh[];
    __half* sA = smh;

    const int n = blockIdx.z, h = blockIdx.y;
    const int tid = threadIdx.x, lane = tid & 31, w = tid >> 5;
    const size_t base  = ((size_t)n*SEQ)*DM + h*EHEAD;
    const size_t vbase = ((size_t)h*EHEAD)*ROWS + (size_t)n*SEQ;
    const int q0 = blockIdx.x * 64;

    const uint32_t sAu = smem_u32(sA);
    const uint32_t sKu = smem_u32(smh + AT_OFF_K);
    const uint32_t sVu = smem_u32(smh + AT_OFF_V);

    // ---- async-load Q tile (64 rows x 64 halfs = 512 chunks) ----
#pragma unroll
    for (int j = 0; j < 4; j++) {
        int idx = j*128 + tid;
        int r = idx >> 3, c8 = (idx & 7) << 3;
        cpa16(sAu + (uint32_t)((r*AT_PA + c8) << 1),
              Qh + base + (size_t)(q0 + r)*DM + c8);
    }
    cpa_commit();
    // ---- async-load K (128x64) + V (64x128) tile 0 ----
#pragma unroll
    for (int j = 0; j < 8; j++) {
        int idx = j*128 + tid;
        int r = idx >> 3, c8 = (idx & 7) << 3;
        cpa16(sKu + (uint32_t)((r*AT_PK + c8) << 1),
              Kh + base + (size_t)r*DM + c8);
    }
#pragma unroll
    for (int j = 0; j < 8; j++) {
        int idx = j*128 + tid;
        int r = idx >> 4, c8 = (idx & 15) << 3;
        cpa16(sVu + (uint32_t)((r*AT_PA + c8) << 1),
              Vth + vbase + (size_t)r*ROWS + c8);
    }
    cpa_commit();

    cpa_wait<1>();
    __syncthreads();

    // ---- hoist Q fragments (warp w owns q rows w*16..w*16+15) ----
    const uint32_t aBase = sAu + (((w*16 + (lane & 15))*AT_PA + (lane >> 4)*8) << 1);
    uint32_t aQ[4][4];
#pragma unroll
    for (int ks = 0; ks < 4; ks++) ldsm4(aQ[ks], aBase + ks*32);

    uint32_t bK[8], bV[4];
#pragma unroll
    for (int p = 0; p < 8; p++)
        bK[p] = sKu + (((p*16 + (lane & 7) + ((lane >> 3) & 1)*8)*AT_PK
                        + (lane >> 4)*8) << 1);
#pragma unroll
    for (int p = 0; p < 4; p++)
        bV[p] = sVu + (((p*16 + (lane & 7) + ((lane >> 3) & 1)*8)*AT_PA
                        + (lane >> 4)*8) << 1);

    float accO[8][4];
#pragma unroll
    for (int ni = 0; ni < 8; ni++)
#pragma unroll
        for (int c = 0; c < 4; c++) accO[ni][c] = 0.f;
    float m0 = -1e30f, m1 = -1e30f, l0 = 0.f, l1 = 0.f;

    const int rA = w*16 + (lane >> 2);
    __half* pr0 = &sA[rA*AT_PA + 2*(lane & 3)];
    __half* pr1 = pr0 + 8*AT_PA;

    for (int kt = 0; kt < SEQ/128; kt++) {
        const int buf = kt & 1;
        if (kt + 1 < SEQ/128) {
            const int nb = buf ^ 1;
            const uint32_t ko = (uint32_t)(nb * AT_KH) << 1;
            const uint32_t vo = (uint32_t)(nb * AT_VH) << 1;
#pragma unroll
            for (int j = 0; j < 8; j++) {
                int idx = j*128 + tid;
                int r = idx >> 3, c8 = (idx & 7) << 3;
                cpa16(sKu + ko + (uint32_t)((r*AT_PK + c8) << 1),
                      Kh + base + (size_t)((kt+1)*128 + r)*DM + c8);
            }
#pragma unroll
            for (int j = 0; j < 8; j++) {
                int idx = j*128 + tid;
                int r = idx >> 4, c8 = (idx & 15) << 3;
                cpa16(sVu + vo + (uint32_t)((r*AT_PA + c8) << 1),
                      Vth + vbase + (size_t)r*ROWS + (kt+1)*128 + c8);
            }
            cpa_commit();
            cpa_wait<1>();
        } else {
            cpa_wait<0>();
        }
        __syncthreads();

        const uint32_t ko = (uint32_t)(buf * AT_KH) << 1;
        const uint32_t vo = (uint32_t)(buf * AT_VH) << 1;

        // ---- S = Q K^T ----
        float accS[16][4];
#pragma unroll
        for (int t = 0; t < 16; t++)
#pragma unroll
            for (int c = 0; c < 4; c++) accS[t][c] = 0.f;
#pragma unroll
        for (int ks = 0; ks < 4; ks++) {
#pragma unroll
            for (int p = 0; p < 8; p++) {
                uint32_t bf[4];
                ldsm4(bf, bK[p] + ko + ks*32);
                mma_f16(accS[2*p],   aQ[ks], bf[0], bf[2]);
                mma_f16(accS[2*p+1], aQ[ks], bf[1], bf[3]);
            }
        }

        // ---- online softmax (fp32) ----
        float rmax0 = -1e30f, rmax1 = -1e30f;
#pragma unroll
        for (int t = 0; t < 16; t++) {
            rmax0 = fmaxf(rmax0, fmaxf(accS[t][0], accS[t][1]));
            rmax1 = fmaxf(rmax1, fmaxf(accS[t][2], accS[t][3]));
        }
        rmax0 = fmaxf(rmax0, __shfl_xor_sync(0xffffffffu, rmax0, 1));
        rmax0 = fmaxf(rmax0, __shfl_xor_sync(0xffffffffu, rmax0, 2));
        rmax1 = fmaxf(rmax1, __shfl_xor_sync(0xffffffffu, rmax1, 1));
        rmax1 = fmaxf(rmax1, __shfl_xor_sync(0xffffffffu, rmax1, 2));
        const float mn0 = fmaxf(m0, rmax0), mn1 = fmaxf(m1, rmax1);
        const float cr0 = __expf(m0 - mn0), cr1 = __expf(m1 - mn1);
        m0 = mn0; m1 = mn1;
        l0 *= cr0; l1 *= cr1;
#pragma unroll
        for (int ni = 0; ni < 8; ni++) {
            accO[ni][0] *= cr0; accO[ni][1] *= cr0;
            accO[ni][2] *= cr1; accO[ni][3] *= cr1;
        }
#pragma unroll
        for (int t = 0; t < 16; t++) {
            float p0 = __expf(accS[t][0] - m0), p1 = __expf(accS[t][1] - m0);
            float p2 = __expf(accS[t][2] - m1), p3 = __expf(accS[t][3] - m1);
            l0 += p0 + p1; l1 += p2 + p3;
            *(__half2*)(pr0 + t*8) = __floats2half2_rn(p0, p1);
            *(__half2*)(pr1 + t*8) = __floats2half2_rn(p2, p3);
        }
        __syncwarp();

        // ---- O += P V ----
#pragma unroll
        for (int ks = 0; ks < 8; ks++) {
            uint32_t aP[4];
            ldsm4(aP, aBase + ks*32);
#pragma unroll
            for (int p = 0; p < 4; p++) {
                uint32_t bf[4];
                ldsm4(bf, bV[p] + vo + ks*32);
                mma_f16(accO[2*p],   aP, bf[0], bf[2]);
                mma_f16(accO[2*p+1], aP, bf[1], bf[3]);
            }
        }
        __syncthreads();
    }

    // ---- epilogue ----
    l0 += __shfl_xor_sync(0xffffffffu, l0, 1);
    l0 += __shfl_xor_sync(0xffffffffu, l0, 2);
    l1 += __shfl_xor_sync(0xffffffffu, l1, 1);
    l1 += __shfl_xor_sync(0xffffffffu, l1, 2);
    const float inv0 = 1.f / l0, inv1 = 1.f / l1;
    const int gr0 = q0 + w*16 + (lane >> 2);
    const int cc = 2*(lane & 3);
#pragma unroll
    for (int ni = 0; ni < 8; ni++) {
        *(__half2*)(Oh + base + (size_t)gr0*DM + ni*8 + cc) =
            __floats2half2_rn(accO[ni][0]*inv0, accO[ni][1]*inv0);
        *(__half2*)(Oh + base + (size_t)(gr0+8)*DM + ni*8 + cc) =
            __floats2half2_rn(accO[ni][2]*inv1, accO[ni][3]*inv1);
    }
}

// ---------------------------------------------------------------------------
// LayerNorm (512). One block/row. Writes fp32 out and optional fp16 copy.
// ---------------------------------------------------------------------------
__global__ __launch_bounds__(128)
void ln_kernel(const float* __restrict__ in, const float* __restrict__ gamma,
               const float* __restrict__ beta, float* __restrict__ out,
               __half* __restrict__ out16)
{
    const int row = blockIdx.x, tid = threadIdx.x;
    const float4 v = ((const float4*)(in + (size_t)row*DM))[tid];
    float s  = v.x + v.y + v.z + v.w;
    float sq = v.x*v.x + v.y*v.y + v.z*v.z + v.w*v.w;
#pragma unroll
    for (int o = 16; o; o >>= 1) {
        s  += __shfl_down_sync(0xffffffffu, s,  o);
        sq += __shfl_down_sync(0xffffffffu, sq, o);
    }
    __shared__ float ss[4], sqs[4];
    const int w = tid >> 5, lane = tid & 31;
    if (lane == 0) { ss[w] = s; sqs[w] = sq; }
    __syncthreads();
    s  = ss[0] + ss[1] + ss[2] + ss[3];
    sq = sqs[0] + sqs[1] + sqs[2] + sqs[3];

    const float mean = s * (1.f / DM);
    const float var  = sq * (1.f / DM) - mean * mean;
    const float inv  = rsqrtf(var + LN_EPS);

    const float4 g4 = ((const float4*)gamma)[tid];
    const float4 b4 = ((const float4*)beta)[tid];
    float4 o4;
    o4.x = (v.x - mean)*inv*g4.x + b4.x;
    o4.y = (v.y - mean)*inv*g4.y + b4.y;
    o4.z = (v.z - mean)*inv*g4.z + b4.z;
    o4.w = (v.w - mean)*inv*g4.w + b4.w;
    ((float4*)(out + (size_t)row*DM))[tid] = o4;
    if (out16) {
        uint2 h;
        h.x = f2h2(o4.x, o4.y);
        h.y = f2h2(o4.z, o4.w);
        ((uint2*)(out16 + (size_t)row*DM))[tid] = h;
    }
}

// ---------------------------------------------------------------------------
extern "C" void kernel_launch(void* const* d_in, const int* in_sizes, int n_in,
                              void* d_out, int out_size)
{
    const float* x   = (const float*)d_in[0];
    const float* Wq  = (const float*)d_in[1];
    const float* bq  = (const float*)d_in[2];
    const float* Wk  = (const float*)d_in[3];
    const float* bk  = (const float*)d_in[4];
    const float* Wv  = (const float*)d_in[5];
    const float* bv  = (const float*)d_in[6];
    const float* Wo  = (const float*)d_in[7];
    const float* bo  = (const float*)d_in[8];
    const float* W1  = (const float*)d_in[9];
    const float* b1  = (const float*)d_in[10];
    const float* W2  = (const float*)d_in[11];
    const float* b2  = (const float*)d_in[12];
    const float* g1  = (const float*)d_in[13];
    const float* be1 = (const float*)d_in[14];
    const float* g2  = (const float*)d_in[15];
    const float* be2 = (const float*)d_in[16];

    __half *qh, *kh, *vth, *oh, *xh, *h1h, *ffh;
    __half *wqh, *wkh, *wvh, *woh, *w1h, *w2h;
    float *hb, *h1, *h2, *xb;
    cudaGetSymbolAddress((void**)&qh,  g_qh);
    cudaGetSymbolAddress((void**)&kh,  g_kh);
    cudaGetSymbolAddress((void**)&vth, g_vth);
    cudaGetSymbolAddress((void**)&oh,  g_oh);
    cudaGetSymbolAddress((void**)&xh,  g_xh);
    cudaGetSymbolAddress((void**)&h1h, g_h1h);
    cudaGetSymbolAddress((void**)&ffh, g_ffh);
    cudaGetSymbolAddress((void**)&hb,  g_h);
    cudaGetSymbolAddress((void**)&h1,  g_h1);
    cudaGetSymbolAddress((void**)&h2,  g_h2);
    cudaGetSymbolAddress((void**)&xb,  g_x);
    cudaGetSymbolAddress((void**)&wqh, g_wq);
    cudaGetSymbolAddress((void**)&wkh, g_wk);
    cudaGetSymbolAddress((void**)&wvh, g_wv);
    cudaGetSymbolAddress((void**)&woh, g_wo);
    cudaGetSymbolAddress((void**)&w1h, g_w1);
    cudaGetSymbolAddress((void**)&w2h, g_w2);

    cudaFuncSetAttribute(attn_f16, cudaFuncAttributeMaxDynamicSharedMemorySize,
                         AT_SMEM_BYTES);

    // ---- one launch: fp32 -> fp16 for 6 weight arrays + layer-0 input ----
    {
        const int nqkv = NLAYERS*DM*DM/4;       // 262144 chunks
        const int nff  = NLAYERS*DM*DFF/4;      // 1048576 chunks
        const int nx   = ROWS*DM/4;             // 1048576 chunks
        const int maxb = (nff + 255) / 256;     // 4096
        dim3 g(maxb, 7);
        f2h_all<<<g, 256>>>((const float4*)Wq, (uint2*)wqh, nqkv,
                            (const float4*)Wk, (uint2*)wkh, nqkv,
                            (const float4*)Wv, (uint2*)wvh, nqkv,
                            (const float4*)Wo, (uint2*)woh, nqkv,
                            (const float4*)W1, (uint2*)w1h, nff,
                            (const float4*)W2, (uint2*)w2h, nff,
                            (const float4*)x,  (uint2*)xh,  nx);
    }

    const dim3 gQKV(12, ROWS / 128);           // (12, 64) fused QKV
    const dim3 gProj(DM / 128, ROWS / 128);    // (4, 64)
    const dim3 gFF1 (DFF / 128, ROWS / 128);   // (16, 64)
    const dim3 gAttn(SEQ / 64, NHEAD, NB);     // (16, 8, 8)

    const float* hin = x;
    for (int l = 0; l < NLAYERS; l++) {
        const __half* wq = wqh + (size_t)l*DM*DM;
        const __half* wk = wkh + (size_t)l*DM*DM;
        const __half* wv = wvh + (size_t)l*DM*DM;
        const __half* wo = woh + (size_t)l*DM*DM;
        const __half* w1 = w1h + (size_t)l*DM*DFF;
        const __half* w2 = w2h + (size_t)l*DFF*DM;

        gemm_qkv<<<gQKV, 256>>>(xh, wq, wk, wv,
                                bq + l*DM, bk + l*DM, bv + l*DM,
                                qh, kh, vth);

        attn_f16<<<gAttn, 128, AT_SMEM_BYTES>>>(qh, kh, vth, oh);

        gemm_h<2><<<gProj, 256>>>(oh, wo, bo + l*DM, hin, hb, ROWS, DM, DM);
        ln_kernel<<<ROWS, 128>>>(hb, g1 + l*DM, be1 + l*DM, h1, h1h);

        gemm_h<1><<<gFF1, 256>>>(h1h, w1, b1 + l*DFF, nullptr, ffh,
                                 ROWS, DFF, DM);
        gemm_h<2><<<gProj, 256>>>(ffh, w2, b2 + l*DM, h1, h2, ROWS, DM, DFF);

        float* lnout = (l == NLAYERS - 1) ? (float*)d_out : xb;
        __half* lnout16 = (l == NLAYERS - 1) ? (__half*)nullptr : xh;
        ln_kernel<<<ROWS, 128>>>(h2, g2 + l*DM, be2 + l*DM, lnout, lnout16);
        hin = xb;
    }
}

// round 10
// speedup vs baseline: 6.5720x; 1.0149x over previous
#include <cuda_runtime.h>
#include <cuda_fp16.h>
#include <cstdint>
#include <cstddef>

// Problem constants
#define DM      512
#define DFF     2048
#define NB      8
#define SEQ     1024
#define NHEAD   8
#define EHEAD   64
#define ROWS    (NB*SEQ)     // 8192
#define NLAYERS 4
#define LN_EPS  1e-5f

// ---------------- scratch (device globals; no allocations allowed) --------
__device__ __half g_qh [ROWS*DM];    // Q (pre-scaled 1/8)
__device__ __half g_kh [ROWS*DM];
__device__ __half g_vth[DM*ROWS];    // V^T [col][token]
__device__ __half g_oh [ROWS*DM];    // attention out
__device__ __half g_xh [ROWS*DM];    // fp16 copy of layer input
__device__ __half g_h1h[ROWS*DM];    // fp16 copy of post-LN1
__device__ __half g_ffh[ROWS*DFF];   // ReLU(FFN1) in fp16
__device__ float  g_h  [ROWS*DM];
__device__ float  g_h1 [ROWS*DM];
__device__ float  g_h2 [ROWS*DM];
__device__ float  g_x  [ROWS*DM];
// fp16 weights (converted once per launch)
__device__ __half g_wq[NLAYERS*DM*DM];
__device__ __half g_wk[NLAYERS*DM*DM];
__device__ __half g_wv[NLAYERS*DM*DM];
__device__ __half g_wo[NLAYERS*DM*DM];
__device__ __half g_w1[NLAYERS*DM*DFF];
__device__ __half g_w2[NLAYERS*DFF*DM];

// ---------------- helpers ---------------------------------------------------
__device__ __forceinline__ uint32_t f2h2(float a, float b) {
    __half2 h = __floats2half2_rn(a, b);
    return *(uint32_t*)&h;
}
__device__ __forceinline__ void ldsm4(uint32_t* r, uint32_t addr) {
    asm volatile("ldmatrix.sync.aligned.m8n8.x4.shared.b16 {%0,%1,%2,%3}, [%4];\n"
                 : "=r"(r[0]), "=r"(r[1]), "=r"(r[2]), "=r"(r[3]) : "r"(addr));
}
__device__ __forceinline__ void ldsm4t(uint32_t* r, uint32_t addr) {
    asm volatile("ldmatrix.sync.aligned.m8n8.x4.trans.shared.b16 {%0,%1,%2,%3}, [%4];\n"
                 : "=r"(r[0]), "=r"(r[1]), "=r"(r[2]), "=r"(r[3]) : "r"(addr));
}
__device__ __forceinline__ void mma_f16(float* d, const uint32_t* a,
                                        uint32_t b0, uint32_t b1) {
    asm volatile(
        "mma.sync.aligned.m16n8k16.row.col.f32.f16.f16.f32 "
        "{%0,%1,%2,%3},{%4,%5,%6,%7},{%8,%9},{%0,%1,%2,%3};\n"
        : "+f"(d[0]), "+f"(d[1]), "+f"(d[2]), "+f"(d[3])
        : "r"(a[0]), "r"(a[1]), "r"(a[2]), "r"(a[3]), "r"(b0), "r"(b1));
}
__device__ __forceinline__ uint32_t smem_u32(const void* p) {
    return (uint32_t)__cvta_generic_to_shared(p);
}
__device__ __forceinline__ void cpa16(uint32_t dst, const void* src) {
    asm volatile("cp.async.ca.shared.global [%0], [%1], 16;\n"
                 :: "r"(dst), "l"(src) : "memory");
}
__device__ __forceinline__ void cpa_commit() {
    asm volatile("cp.async.commit_group;\n" ::: "memory");
}
template<int N>
__device__ __forceinline__ void cpa_wait() {
    asm volatile("cp.async.wait_group %0;\n" :: "n"(N) : "memory");
}

// ---------------- fp32 -> fp16 bulk convert (all 7 arrays, one launch) -----
__global__ __launch_bounds__(256)
void f2h_all(const float4* s0, uint2* d0, int n0,
             const float4* s1, uint2* d1, int n1,
             const float4* s2, uint2* d2, int n2,
             const float4* s3, uint2* d3, int n3,
             const float4* s4, uint2* d4, int n4,
             const float4* s5, uint2* d5, int n5,
             const float4* s6, uint2* d6, int n6)
{
    const float4* s; uint2* d; int n;
    switch (blockIdx.y) {
        case 0: s = s0; d = d0; n = n0; break;
        case 1: s = s1; d = d1; n = n1; break;
        case 2: s = s2; d = d2; n = n2; break;
        case 3: s = s3; d = d3; n = n3; break;
        case 4: s = s4; d = d4; n = n4; break;
        case 5: s = s5; d = d5; n = n5; break;
        default: s = s6; d = d6; n = n6; break;
    }
    int i = blockIdx.x*blockDim.x + threadIdx.x;
    if (i < n) {
        float4 v = s[i];
        uint2 o;
        o.x = f2h2(v.x, v.y);
        o.y = f2h2(v.z, v.w);
        d[i] = o;
    }
}

// ---------------------------------------------------------------------------
// GEMM core: BM=BN=128, BK=32, 256 thr (8 warps, 4m x 2n, warp tile 32x64),
// m16n8k16, 4-stage cp.async ring in DYNAMIC smem, ONE __syncthreads/k-tile.
// ---------------------------------------------------------------------------
#define GPA 40
#define GPB 136
#define ABUF (128*GPA)            // halfs per A stage (5120)
#define BBUF (32*GPB)             // halfs per B stage (4352)
#define GSTAGES 4
#define GSMEM_BYTES (GSTAGES*(ABUF+BBUF)*2)   // 75776 B

// issue one k-tile's cp.async into stage st (A rows, B rows), group committed
#define GEMM_ISSUE(Aptr, Bptr, Kdim, Ndim, st, k0)                              \
    {                                                                           \
        const uint32_t oA = (uint32_t)((st)*ABUF*2);                            \
        const uint32_t oB = (uint32_t)((st)*BBUF*2);                            \
        cpa16(sAu + oA + dA0, (Aptr) + (size_t)ar0*(Kdim) + (k0) + ak0);        \
        cpa16(sAu + oA + dA1, (Aptr) + (size_t)ar1*(Kdim) + (k0) + ak1);        \
        cpa16(sBu + oB + dB0, (Bptr) + (size_t)((k0) + bk0)*(Ndim) + bn0);      \
        cpa16(sBu + oB + dB1, (Bptr) + (size_t)((k0) + bk1)*(Ndim) + bn0);      \
    }

#define GEMM_MAINLOOP(Aptr, Bptr, Kdim, Ndim)                                   \
    __half* smA = dsm;                                                          \
    __half* smB = dsm + GSTAGES*ABUF;                                           \
    const int ar0 = tid >> 2,         ak0 = (tid & 3) << 3;                     \
    const int ar1 = (tid + 256) >> 2, ak1 = ((tid + 256) & 3) << 3;             \
    const int bk0 = tid >> 4,         bn0 = (tid & 15) << 3;                    \
    const int bk1 = bk0 + 16;                                                   \
    const uint32_t sAu = smem_u32(smA);                                         \
    const uint32_t sBu = smem_u32(smB);                                         \
    const uint32_t dA0 = (uint32_t)((ar0*GPA + ak0) << 1);                      \
    const uint32_t dA1 = (uint32_t)((ar1*GPA + ak1) << 1);                      \
    const uint32_t dB0 = (uint32_t)((bk0*GPB + bn0) << 1);                      \
    const uint32_t dB1 = (uint32_t)((bk1*GPB + bn0) << 1);                      \
    uint32_t aAd[2], bAd[4];                                                    \
    _Pragma("unroll")                                                           \
    for (int mi = 0; mi < 2; mi++)                                              \
        aAd[mi] = sAu + (((wm*32 + mi*16 + (lane & 15))*GPA + (lane >> 4)*8) << 1); \
    _Pragma("unroll")                                                           \
    for (int nt = 0; nt < 4; nt++)                                              \
        bAd[nt] = sBu + ((((lane & 7) + ((lane >> 3) & 1)*8)*GPB                \
                          + wn*64 + nt*16 + (lane >> 4)*8) << 1);               \
    float acc[2][8][4];                                                         \
    _Pragma("unroll")                                                           \
    for (int mi = 0; mi < 2; mi++)                                              \
        _Pragma("unroll")                                                       \
        for (int ni = 0; ni < 8; ni++)                                          \
            _Pragma("unroll")                                                   \
            for (int c = 0; c < 4; c++) acc[mi][ni][c] = 0.f;                   \
    const int KT = (Kdim) >> 5;                                                 \
    GEMM_ISSUE(Aptr, Bptr, Kdim, Ndim, 0, 0)  cpa_commit();                     \
    GEMM_ISSUE(Aptr, Bptr, Kdim, Ndim, 1, 32) cpa_commit();                     \
    GEMM_ISSUE(Aptr, Bptr, Kdim, Ndim, 2, 64) cpa_commit();                     \
    for (int kt = 0; kt < KT; kt++) {                                           \
        const int st = kt & (GSTAGES - 1);                                      \
        cpa_wait<GSTAGES - 2>();                                                \
        __syncthreads();                                                        \
        if (kt + 3 < KT) {                                                      \
            const int ns = (kt + 3) & (GSTAGES - 1);                            \
            GEMM_ISSUE(Aptr, Bptr, Kdim, Ndim, ns, (kt + 3)*32)                 \
        }                                                                       \
        cpa_commit();                                                           \
        const uint32_t boA = (uint32_t)(st*ABUF*2);                             \
        const uint32_t boB = (uint32_t)(st*BBUF*2);                             \
        _Pragma("unroll")                                                       \
        for (int kh = 0; kh < 2; kh++) {                                        \
            uint32_t af[2][4], bf[4][4];                                        \
            ldsm4(af[0], aAd[0] + boA + kh*32);                                 \
            ldsm4(af[1], aAd[1] + boA + kh*32);                                 \
            _Pragma("unroll")                                                   \
            for (int nt = 0; nt < 4; nt++)                                      \
                ldsm4t(bf[nt], bAd[nt] + boB + kh*16*GPB*2);                    \
            _Pragma("unroll")                                                   \
            for (int nt = 0; nt < 4; nt++) {                                    \
                _Pragma("unroll")                                               \
                for (int mi = 0; mi < 2; mi++) {                                \
                    mma_f16(acc[mi][2*nt],   af[mi], bf[nt][0], bf[nt][1]);     \
                    mma_f16(acc[mi][2*nt+1], af[mi], bf[nt][2], bf[nt][3]);     \
                }                                                               \
            }                                                                   \
        }                                                                       \
    }

// ---------------------------------------------------------------------------
// General fp16 GEMM with fused epilogues.
//  EPI 1: half out, bias+relu   EPI 2: f32 out, bias+residual
// ---------------------------------------------------------------------------
template<int EPI>
__global__ __launch_bounds__(256, 2)
void gemm_h(const __half* __restrict__ A, const __half* __restrict__ B,
            const float* __restrict__ bias, const float* __restrict__ res,
            void* __restrict__ Cv, int M, int N, int K)
{
    extern __shared__ __half dsm[];

    const int tid = threadIdx.x;
    const int lane = tid & 31, wid = tid >> 5;
    const int wm = wid & 3, wn = wid >> 2;
    const int bx = blockIdx.x, by = blockIdx.y;

    const __half* Ag = A + (size_t)(by*128)*K;
    const __half* Bg = B + (size_t)bx*128;

    GEMM_MAINLOOP(Ag, Bg, K, N)

    const int r0 = (by*128) + wm*32 + (lane >> 2);
#pragma unroll
    for (int mi = 0; mi < 2; mi++) {
        const int gr = r0 + mi*16;
#pragma unroll
        for (int ni = 0; ni < 8; ni++) {
            const int gc = (bx*128) + wn*64 + (ni >> 1)*16 + (ni & 1)*8
                         + ((lane & 3) << 1);
            const float2 bia = *(const float2*)(bias + gc);
            float2 v0 = make_float2(acc[mi][ni][0] + bia.x, acc[mi][ni][1] + bia.y);
            float2 v1 = make_float2(acc[mi][ni][2] + bia.x, acc[mi][ni][3] + bia.y);
            if (EPI == 1) {
                v0.x = fmaxf(v0.x, 0.f); v0.y = fmaxf(v0.y, 0.f);
                v1.x = fmaxf(v1.x, 0.f); v1.y = fmaxf(v1.y, 0.f);
                __half* Ch = (__half*)Cv;
                *(__half2*)(Ch + (size_t)gr*N + gc)     = __floats2half2_rn(v0.x, v0.y);
                *(__half2*)(Ch + (size_t)(gr+8)*N + gc) = __floats2half2_rn(v1.x, v1.y);
            } else {  // EPI == 2
                const float2 r_0 = *(const float2*)(res + (size_t)gr*N + gc);
                const float2 r_1 = *(const float2*)(res + (size_t)(gr+8)*N + gc);
                v0.x += r_0.x; v0.y += r_0.y;
                v1.x += r_1.x; v1.y += r_1.y;
                float* Cf = (float*)Cv;
                *(float2*)(Cf + (size_t)gr*N + gc)     = v0;
                *(float2*)(Cf + (size_t)(gr+8)*N + gc) = v1;
            }
        }
    }
}

// ---------------------------------------------------------------------------
// Fused QKV projection: grid (12, 64). bx>>2 selects Q/K/V.
// ---------------------------------------------------------------------------
__global__ __launch_bounds__(256, 2)
void gemm_qkv(const __half* __restrict__ A,
              const __half* __restrict__ Bq, const __half* __restrict__ Bk,
              const __half* __restrict__ Bv,
              const float* __restrict__ bq, const float* __restrict__ bk,
              const float* __restrict__ bv,
              __half* __restrict__ Oq, __half* __restrict__ Ok,
              __half* __restrict__ Ovt)
{
    extern __shared__ __half dsm[];

    const int tid = threadIdx.x;
    const int lane = tid & 31, wid = tid >> 5;
    const int wm = wid & 3, wn = wid >> 2;
    const int sel = blockIdx.x >> 2, bx = blockIdx.x & 3;
    const int by = blockIdx.y;
    const int N = DM, K = DM;

    const __half* B  = (sel == 0) ? Bq : (sel == 1) ? Bk : Bv;
    const float* bia_p = (sel == 0) ? bq : (sel == 1) ? bk : bv;

    const __half* Ag = A + (size_t)(by*128)*K;
    const __half* Bg = B + (size_t)bx*128;

    GEMM_MAINLOOP(Ag, Bg, K, N)

    const int r0 = (by*128) + wm*32 + (lane >> 2);
#pragma unroll
    for (int mi = 0; mi < 2; mi++) {
        const int gr = r0 + mi*16;
#pragma unroll
        for (int ni = 0; ni < 8; ni++) {
            const int gc = (bx*128) + wn*64 + (ni >> 1)*16 + (ni & 1)*8
                         + ((lane & 3) << 1);
            const float2 bia = *(const float2*)(bia_p + gc);
            float2 v0 = make_float2(acc[mi][ni][0] + bia.x, acc[mi][ni][1] + bia.y);
            float2 v1 = make_float2(acc[mi][ni][2] + bia.x, acc[mi][ni][3] + bia.y);
            if (sel == 0) {
                *(__half2*)(Oq + (size_t)gr*N + gc) =
                    __floats2half2_rn(v0.x*0.125f, v0.y*0.125f);
                *(__half2*)(Oq + (size_t)(gr+8)*N + gc) =
                    __floats2half2_rn(v1.x*0.125f, v1.y*0.125f);
            } else if (sel == 1) {
                *(__half2*)(Ok + (size_t)gr*N + gc)     = __floats2half2_rn(v0.x, v0.y);
                *(__half2*)(Ok + (size_t)(gr+8)*N + gc) = __floats2half2_rn(v1.x, v1.y);
            } else {
                Ovt[(size_t)gc*ROWS + gr]         = __float2half_rn(v0.x);
                Ovt[(size_t)(gc+1)*ROWS + gr]     = __float2half_rn(v0.y);
                Ovt[(size_t)gc*ROWS + gr + 8]     = __float2half_rn(v1.x);
                Ovt[(size_t)(gc+1)*ROWS + gr + 8] = __float2half_rn(v1.y);
            }
        }
    }
}

// ---------------------------------------------------------------------------
// FP16 flash attention, 64 q-rows / 128 threads / 4 warps per CTA,
// 2 CTAs per SM. K-tile 128 keys double-buffered; V from V^T.
// ---------------------------------------------------------------------------
#define AT_PA 136
#define AT_PK 72
#define AT_AH (64*AT_PA)
#define AT_KH (128*AT_PK)
#define AT_VH (64*AT_PA)
#define AT_OFF_K AT_AH
#define AT_OFF_V (AT_OFF_K + 2*AT_KH)
#define AT_SMEM_BYTES ((AT_OFF_V + 2*AT_VH)*2)   // 89088 B

__global__ __launch_bounds__(128, 2)
void attn_f16(const __half* __restrict__ Qh, const __half* __restrict__ Kh,
              const __half* __restrict__ Vth, __half* __restrict__ Oh)
{
    extern __shared__ __half smh[];
    __half* sA = smh;

    const int n = blockIdx.z, h = blockIdx.y;
    const int tid = threadIdx.x, lane = tid & 31, w = tid >> 5;
    const size_t base  = ((size_t)n*SEQ)*DM + h*EHEAD;
    const size_t vbase = ((size_t)h*EHEAD)*ROWS + (size_t)n*SEQ;
    const int q0 = blockIdx.x * 64;

    const uint32_t sAu = smem_u32(sA);
    const uint32_t sKu = smem_u32(smh + AT_OFF_K);
    const uint32_t sVu = smem_u32(smh + AT_OFF_V);

#pragma unroll
    for (int j = 0; j < 4; j++) {
        int idx = j*128 + tid;
        int r = idx >> 3, c8 = (idx & 7) << 3;
        cpa16(sAu + (uint32_t)((r*AT_PA + c8) << 1),
              Qh + base + (size_t)(q0 + r)*DM + c8);
    }
    cpa_commit();
#pragma unroll
    for (int j = 0; j < 8; j++) {
        int idx = j*128 + tid;
        int r = idx >> 3, c8 = (idx & 7) << 3;
        cpa16(sKu + (uint32_t)((r*AT_PK + c8) << 1),
              Kh + base + (size_t)r*DM + c8);
    }
#pragma unroll
    for (int j = 0; j < 8; j++) {
        int idx = j*128 + tid;
        int r = idx >> 4, c8 = (idx & 15) << 3;
        cpa16(sVu + (uint32_t)((r*AT_PA + c8) << 1),
              Vth + vbase + (size_t)r*ROWS + c8);
    }
    cpa_commit();

    cpa_wait<1>();
    __syncthreads();

    const uint32_t aBase = sAu + (((w*16 + (lane & 15))*AT_PA + (lane >> 4)*8) << 1);
    uint32_t aQ[4][4];
#pragma unroll
    for (int ks = 0; ks < 4; ks++) ldsm4(aQ[ks], aBase + ks*32);

    uint32_t bK[8], bV[4];
#pragma unroll
    for (int p = 0; p < 8; p++)
        bK[p] = sKu + (((p*16 + (lane & 7) + ((lane >> 3) & 1)*8)*AT_PK
                        + (lane >> 4)*8) << 1);
#pragma unroll
    for (int p = 0; p < 4; p++)
        bV[p] = sVu + (((p*16 + (lane & 7) + ((lane >> 3) & 1)*8)*AT_PA
                        + (lane >> 4)*8) << 1);

    float accO[8][4];
#pragma unroll
    for (int ni = 0; ni < 8; ni++)
#pragma unroll
        for (int c = 0; c < 4; c++) accO[ni][c] = 0.f;
    float m0 = -1e30f, m1 = -1e30f, l0 = 0.f, l1 = 0.f;

    const int rA = w*16 + (lane >> 2);
    __half* pr0 = &sA[rA*AT_PA + 2*(lane & 3)];
    __half* pr1 = pr0 + 8*AT_PA;

    for (int kt = 0; kt < SEQ/128; kt++) {
        const int buf = kt & 1;
        if (kt + 1 < SEQ/128) {
            const int nb = buf ^ 1;
            const uint32_t ko = (uint32_t)(nb * AT_KH) << 1;
            const uint32_t vo = (uint32_t)(nb * AT_VH) << 1;
#pragma unroll
            for (int j = 0; j < 8; j++) {
                int idx = j*128 + tid;
                int r = idx >> 3, c8 = (idx & 7) << 3;
                cpa16(sKu + ko + (uint32_t)((r*AT_PK + c8) << 1),
                      Kh + base + (size_t)((kt+1)*128 + r)*DM + c8);
            }
#pragma unroll
            for (int j = 0; j < 8; j++) {
                int idx = j*128 + tid;
                int r = idx >> 4, c8 = (idx & 15) << 3;
                cpa16(sVu + vo + (uint32_t)((r*AT_PA + c8) << 1),
                      Vth + vbase + (size_t)r*ROWS + (kt+1)*128 + c8);
            }
            cpa_commit();
            cpa_wait<1>();
        } else {
            cpa_wait<0>();
        }
        __syncthreads();

        const uint32_t ko = (uint32_t)(buf * AT_KH) << 1;
        const uint32_t vo = (uint32_t)(buf * AT_VH) << 1;

        float accS[16][4];
#pragma unroll
        for (int t = 0; t < 16; t++)
#pragma unroll
            for (int c = 0; c < 4; c++) accS[t][c] = 0.f;
#pragma unroll
        for (int ks = 0; ks < 4; ks++) {
#pragma unroll
            for (int p = 0; p < 8; p++) {
                uint32_t bf[4];
                ldsm4(bf, bK[p] + ko + ks*32);
                mma_f16(accS[2*p],   aQ[ks], bf[0], bf[2]);
                mma_f16(accS[2*p+1], aQ[ks], bf[1], bf[3]);
            }
        }

        float rmax0 = -1e30f, rmax1 = -1e30f;
#pragma unroll
        for (int t = 0; t < 16; t++) {
            rmax0 = fmaxf(rmax0, fmaxf(accS[t][0], accS[t][1]));
            rmax1 = fmaxf(rmax1, fmaxf(accS[t][2], accS[t][3]));
        }
        rmax0 = fmaxf(rmax0, __shfl_xor_sync(0xffffffffu, rmax0, 1));
        rmax0 = fmaxf(rmax0, __shfl_xor_sync(0xffffffffu, rmax0, 2));
        rmax1 = fmaxf(rmax1, __shfl_xor_sync(0xffffffffu, rmax1, 1));
        rmax1 = fmaxf(rmax1, __shfl_xor_sync(0xffffffffu, rmax1, 2));
        const float mn0 = fmaxf(m0, rmax0), mn1 = fmaxf(m1, rmax1);
        const float cr0 = __expf(m0 - mn0), cr1 = __expf(m1 - mn1);
        m0 = mn0; m1 = mn1;
        l0 *= cr0; l1 *= cr1;
#pragma unroll
        for (int ni = 0; ni < 8; ni++) {
            accO[ni][0] *= cr0; accO[ni][1] *= cr0;
            accO[ni][2] *= cr1; accO[ni][3] *= cr1;
        }
#pragma unroll
        for (int t = 0; t < 16; t++) {
            float p0 = __expf(accS[t][0] - m0), p1 = __expf(accS[t][1] - m0);
            float p2 = __expf(accS[t][2] - m1), p3 = __expf(accS[t][3] - m1);
            l0 += p0 + p1; l1 += p2 + p3;
            *(__half2*)(pr0 + t*8) = __floats2half2_rn(p0, p1);
            *(__half2*)(pr1 + t*8) = __floats2half2_rn(p2, p3);
        }
        __syncwarp();

#pragma unroll
        for (int ks = 0; ks < 8; ks++) {
            uint32_t aP[4];
            ldsm4(aP, aBase + ks*32);
#pragma unroll
            for (int p = 0; p < 4; p++) {
                uint32_t bf[4];
                ldsm4(bf, bV[p] + vo + ks*32);
                mma_f16(accO[2*p],   aP, bf[0], bf[2]);
                mma_f16(accO[2*p+1], aP, bf[1], bf[3]);
            }
        }
        __syncthreads();
    }

    l0 += __shfl_xor_sync(0xffffffffu, l0, 1);
    l0 += __shfl_xor_sync(0xffffffffu, l0, 2);
    l1 += __shfl_xor_sync(0xffffffffu, l1, 1);
    l1 += __shfl_xor_sync(0xffffffffu, l1, 2);
    const float inv0 = 1.f / l0, inv1 = 1.f / l1;
    const int gr0 = q0 + w*16 + (lane >> 2);
    const int cc = 2*(lane & 3);
#pragma unroll
    for (int ni = 0; ni < 8; ni++) {
        *(__half2*)(Oh + base + (size_t)gr0*DM + ni*8 + cc) =
            __floats2half2_rn(accO[ni][0]*inv0, accO[ni][1]*inv0);
        *(__half2*)(Oh + base + (size_t)(gr0+8)*DM + ni*8 + cc) =
            __floats2half2_rn(accO[ni][2]*inv1, accO[ni][3]*inv1);
    }
}

// ---------------------------------------------------------------------------
// LayerNorm (512). One block/row. Writes fp32 out and optional fp16 copy.
// ---------------------------------------------------------------------------
__global__ __launch_bounds__(128)
void ln_kernel(const float* __restrict__ in, const float* __restrict__ gamma,
               const float* __restrict__ beta, float* __restrict__ out,
               __half* __restrict__ out16)
{
    const int row = blockIdx.x, tid = threadIdx.x;
    const float4 v = ((const float4*)(in + (size_t)row*DM))[tid];
    float s  = v.x + v.y + v.z + v.w;
    float sq = v.x*v.x + v.y*v.y + v.z*v.z + v.w*v.w;
#pragma unroll
    for (int o = 16; o; o >>= 1) {
        s  += __shfl_down_sync(0xffffffffu, s,  o);
        sq += __shfl_down_sync(0xffffffffu, sq, o);
    }
    __shared__ float ss[4], sqs[4];
    const int w = tid >> 5, lane = tid & 31;
    if (lane == 0) { ss[w] = s; sqs[w] = sq; }
    __syncthreads();
    s  = ss[0] + ss[1] + ss[2] + ss[3];
    sq = sqs[0] + sqs[1] + sqs[2] + sqs[3];

    const float mean = s * (1.f / DM);
    const float var  = sq * (1.f / DM) - mean * mean;
    const float inv  = rsqrtf(var + LN_EPS);

    const float4 g4 = ((const float4*)gamma)[tid];
    const float4 b4 = ((const float4*)beta)[tid];
    float4 o4;
    o4.x = (v.x - mean)*inv*g4.x + b4.x;
    o4.y = (v.y - mean)*inv*g4.y + b4.y;
    o4.z = (v.z - mean)*inv*g4.z + b4.z;
    o4.w = (v.w - mean)*inv*g4.w + b4.w;
    ((float4*)(out + (size_t)row*DM))[tid] = o4;
    if (out16) {
        uint2 h;
        h.x = f2h2(o4.x, o4.y);
        h.y = f2h2(o4.z, o4.w);
        ((uint2*)(out16 + (size_t)row*DM))[tid] = h;
    }
}

// ---------------------------------------------------------------------------
extern "C" void kernel_launch(void* const* d_in, const int* in_sizes, int n_in,
                              void* d_out, int out_size)
{
    const float* x   = (const float*)d_in[0];
    const float* Wq  = (const float*)d_in[1];
    const float* bq  = (const float*)d_in[2];
    const float* Wk  = (const float*)d_in[3];
    const float* bk  = (const float*)d_in[4];
    const float* Wv  = (const float*)d_in[5];
    const float* bv  = (const float*)d_in[6];
    const float* Wo  = (const float*)d_in[7];
    const float* bo  = (const float*)d_in[8];
    const float* W1  = (const float*)d_in[9];
    const float* b1  = (const float*)d_in[10];
    const float* W2  = (const float*)d_in[11];
    const float* b2  = (const float*)d_in[12];
    const float* g1  = (const float*)d_in[13];
    const float* be1 = (const float*)d_in[14];
    const float* g2  = (const float*)d_in[15];
    const float* be2 = (const float*)d_in[16];

    __half *qh, *kh, *vth, *oh, *xh, *h1h, *ffh;
    __half *wqh, *wkh, *wvh, *woh, *w1h, *w2h;
    float *hb, *h1, *h2, *xb;
    cudaGetSymbolAddress((void**)&qh,  g_qh);
    cudaGetSymbolAddress((void**)&kh,  g_kh);
    cudaGetSymbolAddress((void**)&vth, g_vth);
    cudaGetSymbolAddress((void**)&oh,  g_oh);
    cudaGetSymbolAddress((void**)&xh,  g_xh);
    cudaGetSymbolAddress((void**)&h1h, g_h1h);
    cudaGetSymbolAddress((void**)&ffh, g_ffh);
    cudaGetSymbolAddress((void**)&hb,  g_h);
    cudaGetSymbolAddress((void**)&h1,  g_h1);
    cudaGetSymbolAddress((void**)&h2,  g_h2);
    cudaGetSymbolAddress((void**)&xb,  g_x);
    cudaGetSymbolAddress((void**)&wqh, g_wq);
    cudaGetSymbolAddress((void**)&wkh, g_wk);
    cudaGetSymbolAddress((void**)&wvh, g_wv);
    cudaGetSymbolAddress((void**)&woh, g_wo);
    cudaGetSymbolAddress((void**)&w1h, g_w1);
    cudaGetSymbolAddress((void**)&w2h, g_w2);

    cudaFuncSetAttribute(attn_f16, cudaFuncAttributeMaxDynamicSharedMemorySize,
                         AT_SMEM_BYTES);
    cudaFuncSetAttribute(gemm_h<1>, cudaFuncAttributeMaxDynamicSharedMemorySize,
                         GSMEM_BYTES);
    cudaFuncSetAttribute(gemm_h<2>, cudaFuncAttributeMaxDynamicSharedMemorySize,
                         GSMEM_BYTES);
    cudaFuncSetAttribute(gemm_qkv, cudaFuncAttributeMaxDynamicSharedMemorySize,
                         GSMEM_BYTES);

    // ---- one launch: fp32 -> fp16 for 6 weight arrays + layer-0 input ----
    {
        const int nqkv = NLAYERS*DM*DM/4;
        const int nff  = NLAYERS*DM*DFF/4;
        const int nx   = ROWS*DM/4;
        const int maxb = (nff + 255) / 256;
        dim3 g(maxb, 7);
        f2h_all<<<g, 256>>>((const float4*)Wq, (uint2*)wqh, nqkv,
                            (const float4*)Wk, (uint2*)wkh, nqkv,
                            (const float4*)Wv, (uint2*)wvh, nqkv,
                            (const float4*)Wo, (uint2*)woh, nqkv,
                            (const float4*)W1, (uint2*)w1h, nff,
                            (const float4*)W2, (uint2*)w2h, nff,
                            (const float4*)x,  (uint2*)xh,  nx);
    }

    const dim3 gQKV(12, ROWS / 128);           // (12, 64) fused QKV
    const dim3 gProj(DM / 128, ROWS / 128);    // (4, 64)
    const dim3 gFF1 (DFF / 128, ROWS / 128);   // (16, 64)
    const dim3 gAttn(SEQ / 64, NHEAD, NB);     // (16, 8, 8)

    const float* hin = x;
    for (int l = 0; l < NLAYERS; l++) {
        const __half* wq = wqh + (size_t)l*DM*DM;
        const __half* wk = wkh + (size_t)l*DM*DM;
        const __half* wv = wvh + (size_t)l*DM*DM;
        const __half* wo = woh + (size_t)l*DM*DM;
        const __half* w1 = w1h + (size_t)l*DM*DFF;
        const __half* w2 = w2h + (size_t)l*DFF*DM;

        gemm_qkv<<<gQKV, 256, GSMEM_BYTES>>>(xh, wq, wk, wv,
                                             bq + l*DM, bk + l*DM, bv + l*DM,
                                             qh, kh, vth);

        attn_f16<<<gAttn, 128, AT_SMEM_BYTES>>>(qh, kh, vth, oh);

        gemm_h<2><<<gProj, 256, GSMEM_BYTES>>>(oh, wo, bo + l*DM, hin, hb,
                                               ROWS, DM, DM);
        ln_kernel<<<ROWS, 128>>>(hb, g1 + l*DM, be1 + l*DM, h1, h1h);

        gemm_h<1><<<gFF1, 256, GSMEM_BYTES>>>(h1h, w1, b1 + l*DFF, nullptr, ffh,
                                              ROWS, DFF, DM);
        gemm_h<2><<<gProj, 256, GSMEM_BYTES>>>(ffh, w2, b2 + l*DM, h1, h2,
                                               ROWS, DM, DFF);

        float* lnout = (l == NLAYERS - 1) ? (float*)d_out : xb;
        __half* lnout16 = (l == NLAYERS - 1) ? (__half*)nullptr : xh;
        ln_kernel<<<ROWS, 128>>>(h2, g2 + l*DM, be2 + l*DM, lnout, lnout16);
        hin = xb;
    }
}